// round 4
// baseline (speedup 1.0000x reference)
#include <cuda_runtime.h>

#define NB 2
#define NNODE 40962
#define NEDGE 327680
#define ND 256
#define ED 64
#define HD 512
#define NL 16
#define K1E 576   /* ED + 2*ND */
#define K1N 320   /* ND + ED   */

// Scratch: allocations are forbidden; __device__ globals are the sanctioned path.
__device__ float g_e[(size_t)NB * NEDGE * ED];    // ~168 MB edge features
__device__ float g_agg[(size_t)NB * NNODE * ED];  // ~21 MB scatter accumulator

typedef unsigned long long ull;

__device__ __forceinline__ void ffma2(ull& d, ull a, ull b) {
    asm("fma.rn.f32x2 %0, %1, %2, %0;" : "+l"(d) : "l"(a), "l"(b));
}
__device__ __forceinline__ ull pk(float x, float y) {
    ull r; asm("mov.b64 %0, {%1, %2};" : "=l"(r) : "f"(x), "f"(y)); return r;
}
__device__ __forceinline__ float2 up(ull v) {
    float2 f; asm("mov.b64 {%0, %1}, %2;" : "=f"(f.x), "=f"(f.y) : "l"(v)); return f;
}
__device__ __forceinline__ float silu_f(float v) {
    return __fdividef(v, 1.0f + __expf(-v));
}

__global__ void zero_agg_kernel() {
    size_t n = (size_t)NB * NNODE * ED;
    for (size_t i = (size_t)blockIdx.x * blockDim.x + threadIdx.x; i < n;
         i += (size_t)gridDim.x * blockDim.x)
        g_agg[i] = 0.0f;
}

// shared-memory layouts (element counts, fp32)
#define E_M   (64 * 580)   /* input tile [64][576] padded */
#define E_W   (64 * 132)   /* W1 slab 64x128 / h chunk    */
#define E_P   (128 * 68)   /* W2 chunk 128x64 / p tile    */
#define EDGE_SMEM ((E_M + E_W + E_P + 128) * 4 + 512)
#define N_IN  (64 * 324)   /* input tile [64][320] padded */
#define N_W   (64 * 132)
#define N_P   (64 * 260)   /* W2 slab 64x256 / p tile     */
#define NODE_SMEM ((N_IN + N_W + N_P + 128) * 4)

// ============================ EDGE KERNEL =============================
__global__ void __launch_bounds__(256, 1)
edge_kernel(const float* __restrict__ x, const int* __restrict__ eidx,
            const float* __restrict__ We1, const float* __restrict__ be1,
            const float* __restrict__ We2, const float* __restrict__ be2,
            const float* __restrict__ geW, const float* __restrict__ bleW, int l)
{
    extern __shared__ float sm[];
    float* sm_m  = sm;                 // [64][580]
    float* sm_w  = sm_m + E_M;         // [64][132]
    float* sm_p  = sm_w + E_W;         // [128][68]
    float* sm_mu = sm_p + E_P;         // [64]
    float* sm_rs = sm_mu + 64;         // [64]
    int*   sm_dst = (int*)(sm_rs + 64);// [64]

    const int tid = threadIdx.x;
    const int tx = tid & 15, ty = tid >> 4;
    const int b = blockIdx.y;
    const int e0 = blockIdx.x * 64;

    __shared__ int s_src[64];
    if (tid < 64) {
        s_src[tid]  = eidx[e0 + tid];
        sm_dst[tid] = eidx[NEDGE + e0 + tid];
    }
    __syncthreads();

    const float4* x4 = (const float4*)(x + (size_t)b * NNODE * ND);
    const float4* e4 = (const float4*)(g_e + (size_t)b * NEDGE * ED);

    // gather: per row 144 float4 = [e:16 | x_src:64 | x_dst:64]
    for (int i = tid; i < 64 * 144; i += 256) {
        int r = i / 144, q = i - r * 144;
        float4 v;
        if (q < 16)      v = e4[(size_t)(e0 + r) * 16 + q];
        else if (q < 80) v = x4[(size_t)s_src[r] * 64 + (q - 16)];
        else             v = x4[(size_t)sm_dst[r] * 64 + (q - 80)];
        *(float4*)(sm_m + r * 580 + q * 4) = v;
    }

    const float* W1 = We1 + (size_t)l * K1E * HD;
    const float* B1 = be1 + l * HD;
    const float* W2 = We2 + (size_t)l * HD * ED;
    const float* B2 = be2 + l * ED;

    ull oa[4][2];   // 64x64 out: rows ty*4+i, cols tx*4+{0,1},{2,3}
    #pragma unroll
    for (int i = 0; i < 4; i++) { oa[i][0] = 0ull; oa[i][1] = 0ull; }

    for (int nc = 0; nc < 4; nc++) {          // hidden chunks of 128
        ull ha[4][4];                          // rows ty*4+i, cols tx*8+2j
        #pragma unroll
        for (int i = 0; i < 4; i++)
            #pragma unroll
            for (int j = 0; j < 4; j++) ha[i][j] = 0ull;

        for (int k0 = 0; k0 < K1E; k0 += 64) {   // GEMM1 K slabs
            __syncthreads();
            for (int i = tid; i < 2048; i += 256) {   // W1 slab 64x128
                int kk = i >> 5, c = i & 31;
                ((float4*)(sm_w + kk * 132))[c] =
                    ((const float4*)(W1 + (size_t)(k0 + kk) * HD + nc * 128))[c];
            }
            __syncthreads();
            #pragma unroll 4
            for (int k4 = 0; k4 < 16; k4++) {
                float4 av[4];
                #pragma unroll
                for (int i = 0; i < 4; i++)
                    av[i] = *(const float4*)(sm_m + (ty * 4 + i) * 580 + k0 + k4 * 4);
                #pragma unroll
                for (int u = 0; u < 4; u++) {
                    int kk = k4 * 4 + u;
                    ulonglong2 b0 = *(const ulonglong2*)(sm_w + kk * 132 + tx * 8);
                    ulonglong2 b1 = *(const ulonglong2*)(sm_w + kk * 132 + tx * 8 + 4);
                    #pragma unroll
                    for (int i = 0; i < 4; i++) {
                        float a = (u == 0) ? av[i].x : (u == 1) ? av[i].y
                                : (u == 2) ? av[i].z : av[i].w;
                        ull ap = pk(a, a);
                        ffma2(ha[i][0], ap, b0.x); ffma2(ha[i][1], ap, b0.y);
                        ffma2(ha[i][2], ap, b1.x); ffma2(ha[i][3], ap, b1.y);
                    }
                }
            }
        }
        __syncthreads();

        // silu + bias -> sm_w (h chunk 64x128)
        #pragma unroll
        for (int i = 0; i < 4; i++)
            #pragma unroll
            for (int j = 0; j < 4; j++) {
                float2 v = up(ha[i][j]);
                int c = nc * 128 + tx * 8 + j * 2;
                sm_w[(ty * 4 + i) * 132 + tx * 8 + j * 2]     = silu_f(v.x + B1[c]);
                sm_w[(ty * 4 + i) * 132 + tx * 8 + j * 2 + 1] = silu_f(v.y + B1[c + 1]);
            }
        for (int i = tid; i < 2048; i += 256) {     // W2 chunk 128x64
            int kk = i >> 4, c = i & 15;
            ((float4*)(sm_p + kk * 68))[c] =
                ((const float4*)(W2 + (size_t)(nc * 128 + kk) * ED))[c];
        }
        __syncthreads();
        #pragma unroll 4
        for (int k4 = 0; k4 < 32; k4++) {
            float4 av[4];
            #pragma unroll
            for (int i = 0; i < 4; i++)
                av[i] = *(const float4*)(sm_w + (ty * 4 + i) * 132 + k4 * 4);
            #pragma unroll
            for (int u = 0; u < 4; u++) {
                int kk = k4 * 4 + u;
                ulonglong2 bb = *(const ulonglong2*)(sm_p + kk * 68 + tx * 4);
                #pragma unroll
                for (int i = 0; i < 4; i++) {
                    float a = (u == 0) ? av[i].x : (u == 1) ? av[i].y
                            : (u == 2) ? av[i].z : av[i].w;
                    ull ap = pk(a, a);
                    ffma2(oa[i][0], ap, bb.x); ffma2(oa[i][1], ap, bb.y);
                }
            }
        }
        __syncthreads();
    }

    // epilogue: bias -> smem, LN(64), residual, store + scatter
    #pragma unroll
    for (int i = 0; i < 4; i++)
        #pragma unroll
        for (int j = 0; j < 2; j++) {
            float2 v = up(oa[i][j]);
            int c = tx * 4 + j * 2;
            sm_p[(ty * 4 + i) * 68 + c]     = v.x + B2[c];
            sm_p[(ty * 4 + i) * 68 + c + 1] = v.y + B2[c + 1];
        }
    __syncthreads();
    {
        int r = tid >> 2, sub = tid & 3;
        float s = 0.f, s2 = 0.f;
        #pragma unroll
        for (int cc = 0; cc < 16; cc++) {
            float v = sm_p[r * 68 + sub * 16 + cc];
            s += v; s2 += v * v;
        }
        s  += __shfl_xor_sync(0xffffffffu, s, 1);
        s  += __shfl_xor_sync(0xffffffffu, s, 2);
        s2 += __shfl_xor_sync(0xffffffffu, s2, 1);
        s2 += __shfl_xor_sync(0xffffffffu, s2, 2);
        if (sub == 0) {
            float mu = s * (1.0f / 64.0f);
            sm_mu[r] = mu;
            sm_rs[r] = rsqrtf(s2 * (1.0f / 64.0f) - mu * mu + 1e-5f);
        }
    }
    __syncthreads();
    {
        int c = tid & 63, rg = tid >> 6;
        float gv = geW[l * ED + c], bv = bleW[l * ED + c];
        float* eo = g_e + (size_t)b * NEDGE * ED;
        float* ag = g_agg + (size_t)b * NNODE * ED;
        #pragma unroll 4
        for (int rr = 0; rr < 16; rr++) {
            int r = rg * 16 + rr;
            float v = sm_p[r * 68 + c];
            float en = sm_m[r * 580 + c] + (v - sm_mu[r]) * sm_rs[r] * gv + bv;
            eo[(size_t)(e0 + r) * ED + c] = en;
            atomicAdd(ag + (size_t)sm_dst[r] * ED + c, en);
        }
    }
}

// ============================ NODE KERNEL =============================
__global__ void __launch_bounds__(256, 1)
node_kernel(float* __restrict__ x,
            const float* __restrict__ Wn1, const float* __restrict__ bn1,
            const float* __restrict__ Wn2, const float* __restrict__ bn2,
            const float* __restrict__ gnW, const float* __restrict__ blnW, int l)
{
    extern __shared__ float sm[];
    float* sm_in = sm;                 // [64][324]
    float* sm_w  = sm_in + N_IN;       // [64][132]
    float* sm_p  = sm_w + N_W;         // [64][260]
    float* sm_mu = sm_p + N_P;         // [64]
    float* sm_rs = sm_mu + 64;         // [64]

    const int tid = threadIdx.x;
    const int tx = tid & 15, ty = tid >> 4;
    const int b = blockIdx.y;
    const int n0 = blockIdx.x * 64;

    const float4* x4 = (const float4*)(x + (size_t)b * NNODE * ND);
    const float4* a4 = (const float4*)(g_agg + (size_t)b * NNODE * ED);

    // gather: per row 80 float4 = [x:64 | agg:16]
    for (int i = tid; i < 64 * 80; i += 256) {
        int r = i / 80, q = i - r * 80;
        int node = min(n0 + r, NNODE - 1);
        float4 v = (q < 64) ? x4[(size_t)node * 64 + q]
                            : a4[(size_t)node * 16 + (q - 64)];
        *(float4*)(sm_in + r * 324 + q * 4) = v;
    }

    const float* W1 = Wn1 + (size_t)l * K1N * HD;
    const float* B1 = bn1 + l * HD;
    const float* W2 = Wn2 + (size_t)l * HD * ND;
    const float* B2 = bn2 + l * ND;

    ull oa[4][8];   // 64x256 out: rows ty*4+i, cols tx*16+2j
    #pragma unroll
    for (int i = 0; i < 4; i++)
        #pragma unroll
        for (int j = 0; j < 8; j++) oa[i][j] = 0ull;

    for (int nc = 0; nc < 4; nc++) {
        ull ha[4][4];
        #pragma unroll
        for (int i = 0; i < 4; i++)
            #pragma unroll
            for (int j = 0; j < 4; j++) ha[i][j] = 0ull;

        for (int k0 = 0; k0 < K1N; k0 += 64) {
            __syncthreads();
            for (int i = tid; i < 2048; i += 256) {
                int kk = i >> 5, c = i & 31;
                ((float4*)(sm_w + kk * 132))[c] =
                    ((const float4*)(W1 + (size_t)(k0 + kk) * HD + nc * 128))[c];
            }
            __syncthreads();
            #pragma unroll 4
            for (int k4 = 0; k4 < 16; k4++) {
                float4 av[4];
                #pragma unroll
                for (int i = 0; i < 4; i++)
                    av[i] = *(const float4*)(sm_in + (ty * 4 + i) * 324 + k0 + k4 * 4);
                #pragma unroll
                for (int u = 0; u < 4; u++) {
                    int kk = k4 * 4 + u;
                    ulonglong2 b0 = *(const ulonglong2*)(sm_w + kk * 132 + tx * 8);
                    ulonglong2 b1 = *(const ulonglong2*)(sm_w + kk * 132 + tx * 8 + 4);
                    #pragma unroll
                    for (int i = 0; i < 4; i++) {
                        float a = (u == 0) ? av[i].x : (u == 1) ? av[i].y
                                : (u == 2) ? av[i].z : av[i].w;
                        ull ap = pk(a, a);
                        ffma2(ha[i][0], ap, b0.x); ffma2(ha[i][1], ap, b0.y);
                        ffma2(ha[i][2], ap, b1.x); ffma2(ha[i][3], ap, b1.y);
                    }
                }
            }
        }
        __syncthreads();

        #pragma unroll
        for (int i = 0; i < 4; i++)
            #pragma unroll
            for (int j = 0; j < 4; j++) {
                float2 v = up(ha[i][j]);
                int c = nc * 128 + tx * 8 + j * 2;
                sm_w[(ty * 4 + i) * 132 + tx * 8 + j * 2]     = silu_f(v.x + B1[c]);
                sm_w[(ty * 4 + i) * 132 + tx * 8 + j * 2 + 1] = silu_f(v.y + B1[c + 1]);
            }

        for (int s = 0; s < 2; s++) {    // GEMM2 k-slabs of 64
            for (int i = tid; i < 4096; i += 256) {   // W2 slab 64x256
                int kk = i >> 6, c = i & 63;
                ((float4*)(sm_p + kk * 260))[c] =
                    ((const float4*)(W2 + (size_t)(nc * 128 + s * 64 + kk) * ND))[c];
            }
            __syncthreads();
            #pragma unroll 2
            for (int k4 = 0; k4 < 16; k4++) {
                float4 av[4];
                #pragma unroll
                for (int i = 0; i < 4; i++)
                    av[i] = *(const float4*)(sm_w + (ty * 4 + i) * 132 + s * 64 + k4 * 4);
                #pragma unroll
                for (int u = 0; u < 4; u++) {
                    int kk = k4 * 4 + u;
                    const ulonglong2* bp = (const ulonglong2*)(sm_p + kk * 260 + tx * 16);
                    ulonglong2 q0 = bp[0], q1 = bp[1], q2 = bp[2], q3 = bp[3];
                    #pragma unroll
                    for (int i = 0; i < 4; i++) {
                        float a = (u == 0) ? av[i].x : (u == 1) ? av[i].y
                                : (u == 2) ? av[i].z : av[i].w;
                        ull ap = pk(a, a);
                        ffma2(oa[i][0], ap, q0.x); ffma2(oa[i][1], ap, q0.y);
                        ffma2(oa[i][2], ap, q1.x); ffma2(oa[i][3], ap, q1.y);
                        ffma2(oa[i][4], ap, q2.x); ffma2(oa[i][5], ap, q2.y);
                        ffma2(oa[i][6], ap, q3.x); ffma2(oa[i][7], ap, q3.y);
                    }
                }
            }
            __syncthreads();
        }
    }

    // epilogue: bias -> smem, LN(256), residual, store
    #pragma unroll
    for (int i = 0; i < 4; i++)
        #pragma unroll
        for (int j = 0; j < 8; j++) {
            float2 v = up(oa[i][j]);
            int c = tx * 16 + j * 2;
            sm_p[(ty * 4 + i) * 260 + c]     = v.x + B2[c];
            sm_p[(ty * 4 + i) * 260 + c + 1] = v.y + B2[c + 1];
        }
    __syncthreads();
    {
        int r = tid >> 2, sub = tid & 3;
        float s = 0.f, s2 = 0.f;
        #pragma unroll 8
        for (int cc = 0; cc < 64; cc++) {
            float v = sm_p[r * 260 + sub * 64 + cc];
            s += v; s2 += v * v;
        }
        s  += __shfl_xor_sync(0xffffffffu, s, 1);
        s  += __shfl_xor_sync(0xffffffffu, s, 2);
        s2 += __shfl_xor_sync(0xffffffffu, s2, 1);
        s2 += __shfl_xor_sync(0xffffffffu, s2, 2);
        if (sub == 0) {
            float mu = s * (1.0f / 256.0f);
            sm_mu[r] = mu;
            sm_rs[r] = rsqrtf(s2 * (1.0f / 256.0f) - mu * mu + 1e-5f);
        }
    }
    __syncthreads();
    {
        int c = tid;   // 0..255 = all output cols
        float gv = gnW[l * ND + c], bv = blnW[l * ND + c];
        float* xo = x + (size_t)b * NNODE * ND;
        for (int rr = 0; rr < 64; rr++) {
            if (n0 + rr < NNODE) {
                float v = sm_p[rr * 260 + c];
                xo[(size_t)(n0 + rr) * ND + c] =
                    sm_in[rr * 324 + c] + (v - sm_mu[rr]) * sm_rs[rr] * gv + bv;
            }
        }
    }
}

// ============================== LAUNCH ===============================
extern "C" void kernel_launch(void* const* d_in, const int* in_sizes, int n_in,
                              void* d_out, int out_size) {
    const float* nf  = (const float*)d_in[0];   // node_features (B,N,ND)
    const float* ef  = (const float*)d_in[1];   // edge_features (E,ED)
    const float* We1 = (const float*)d_in[2];
    const float* be1 = (const float*)d_in[3];
    const float* We2 = (const float*)d_in[4];
    const float* be2 = (const float*)d_in[5];
    const float* geW = (const float*)d_in[6];
    const float* ble = (const float*)d_in[7];
    const float* Wn1 = (const float*)d_in[8];
    const float* bn1 = (const float*)d_in[9];
    const float* Wn2 = (const float*)d_in[10];
    const float* bn2 = (const float*)d_in[11];
    const float* gnW = (const float*)d_in[12];
    const float* bln = (const float*)d_in[13];
    const int*  eidx = (const int*)d_in[14];    // edge_index (2,E)
    float* x = (float*)d_out;

    cudaFuncSetAttribute(edge_kernel, cudaFuncAttributeMaxDynamicSharedMemorySize, EDGE_SMEM);
    cudaFuncSetAttribute(node_kernel, cudaFuncAttributeMaxDynamicSharedMemorySize, NODE_SMEM);

    // x := node_features (updated in place; final layer write IS the output)
    cudaMemcpyAsync(x, nf, sizeof(float) * (size_t)NB * NNODE * ND,
                    cudaMemcpyDeviceToDevice, 0);
    // e := edge_features, replicated per batch
    size_t ebytes = sizeof(float) * (size_t)NEDGE * ED;
    cudaMemcpyToSymbolAsync(g_e, ef, ebytes, 0, cudaMemcpyDeviceToDevice, 0);
    cudaMemcpyToSymbolAsync(g_e, ef, ebytes, ebytes, cudaMemcpyDeviceToDevice, 0);

    dim3 eg(NEDGE / 64, NB);
    dim3 ng((NNODE + 63) / 64, NB);
    for (int l = 0; l < NL; l++) {
        zero_agg_kernel<<<512, 256>>>();
        edge_kernel<<<eg, 256, EDGE_SMEM>>>(x, eidx, We1, be1, We2, be2, geW, ble, l);
        node_kernel<<<ng, 256, NODE_SMEM>>>(x, Wn1, bn1, Wn2, bn2, gnW, bln, l);
    }
}

// round 6
// speedup vs baseline: 2.2575x; 2.2575x over previous
#include <cuda_runtime.h>
#include <cuda_bf16.h>
#include <cstdint>

#define NB 2
#define NNODE 40962
#define NEDGE 327680
#define ND 256
#define ED 64
#define HD 512
#define NL 16
#define K1E 576   /* ED + 2*ND */
#define K1N 320   /* ND + ED   */

typedef unsigned long long ull;
typedef unsigned int u32;
typedef unsigned short u16;

// ----------------------------- scratch ------------------------------
__device__ float g_e[(size_t)NB * NEDGE * ED];     // edge features
__device__ float g_agg[(size_t)NB * NNODE * ED];   // scatter accumulator
// split-bf16 transposed edge weights: W1T[l][n(512)][k(576)], W2T[l][n(64)][k(512)]
__device__ u16 gW1T_hi[(size_t)NL * HD * K1E];
__device__ u16 gW1T_lo[(size_t)NL * HD * K1E];
__device__ u16 gW2T_hi[(size_t)NL * ED * HD];
__device__ u16 gW2T_lo[(size_t)NL * ED * HD];

// --------------------------- helpers --------------------------------
__device__ __forceinline__ u16 bf_hi(float v) {
    return __bfloat16_as_ushort(__float2bfloat16_rn(v));
}
__device__ __forceinline__ float bf_f(u16 h) {
    return __bfloat162float(__ushort_as_bfloat16(h));
}
__device__ __forceinline__ float silu_f(float v) {
    return __fdividef(v, 1.0f + __expf(-v));
}
// classic HMMA: m16n8k16 row.col f32 <- bf16 x bf16
__device__ __forceinline__ void mma16816(float* d, const u32* a, u32 b0, u32 b1) {
    asm volatile(
        "mma.sync.aligned.m16n8k16.row.col.f32.bf16.bf16.f32 "
        "{%0,%1,%2,%3}, {%4,%5,%6,%7}, {%8,%9}, {%0,%1,%2,%3};"
        : "+f"(d[0]), "+f"(d[1]), "+f"(d[2]), "+f"(d[3])
        : "r"(a[0]), "r"(a[1]), "r"(a[2]), "r"(a[3]), "r"(b0), "r"(b1));
}

typedef unsigned long long ullt;
__device__ __forceinline__ void ffma2(ullt& d, ullt a, ullt b) {
    asm("fma.rn.f32x2 %0, %1, %2, %0;" : "+l"(d) : "l"(a), "l"(b));
}
__device__ __forceinline__ ullt pk(float x, float y) {
    ullt r; asm("mov.b64 %0, {%1, %2};" : "=l"(r) : "f"(x), "f"(y)); return r;
}
__device__ __forceinline__ float2 up(ullt v) {
    float2 f; asm("mov.b64 {%0, %1}, %2;" : "=f"(f.x), "=f"(f.y) : "l"(v)); return f;
}

// --------------------------- prep kernels ---------------------------
__global__ void prep_w1(const float* __restrict__ We1) {
    size_t tot = (size_t)NL * K1E * HD;
    for (size_t i = (size_t)blockIdx.x * blockDim.x + threadIdx.x; i < tot;
         i += (size_t)gridDim.x * blockDim.x) {
        size_t l = i / ((size_t)K1E * HD);
        size_t rem = i - l * (size_t)K1E * HD;
        size_t k = rem / HD, n = rem - k * HD;
        float w = We1[i];
        u16 hi = bf_hi(w);
        u16 lo = bf_hi(w - bf_f(hi));
        size_t o = (l * HD + n) * K1E + k;
        gW1T_hi[o] = hi; gW1T_lo[o] = lo;
    }
}
__global__ void prep_w2(const float* __restrict__ We2) {
    size_t tot = (size_t)NL * HD * ED;
    for (size_t i = (size_t)blockIdx.x * blockDim.x + threadIdx.x; i < tot;
         i += (size_t)gridDim.x * blockDim.x) {
        size_t l = i / ((size_t)HD * ED);
        size_t rem = i - l * (size_t)HD * ED;
        size_t k = rem / ED, n = rem - k * ED;
        float w = We2[i];
        u16 hi = bf_hi(w);
        u16 lo = bf_hi(w - bf_f(hi));
        size_t o = (l * ED + n) * HD + k;
        gW2T_hi[o] = hi; gW2T_lo[o] = lo;
    }
}

__global__ void zero_agg_kernel() {
    size_t n = (size_t)NB * NNODE * ED;
    for (size_t i = (size_t)blockIdx.x * blockDim.x + threadIdx.x; i < n;
         i += (size_t)gridDim.x * blockDim.x)
        g_agg[i] = 0.0f;
}

// ===================== EDGE KERNEL (mma.sync bf16 split) ==============
// 64 edges/block, 256 threads (8 warps: 4 m-groups x 2 n-groups).
// A[64][576] bf16 hi/lo persistent in smem; per 128-hidden chunk:
// GEMM1 (reg accum 16x64/warp) with 64-k B slabs prefetched; silu -> h smem;
// GEMM2 (reg accum 16x32/warp, held across chunks); LN + residual + scatter.
#define SA 584    /* A row stride (576+8): 1168B = 292w, mod32 = 4 -> conflict-free */
#define SB 72     /* B slab row stride (64+8): 144B = 36w, mod32 = 4 */
#define SH 136    /* h / W2 row stride (128+8): 272B = 68w, mod32 = 4 */
#define OFF_A  0
#define OFF_B  149504                  /* 2 * 64*584*2  */
#define OFF_W2 186368                  /* OFF_B + 2 * 128*72*2 */
#define EDGE_DSMEM 221184              /* OFF_W2 + 2 * 64*136*2 */

__global__ void __launch_bounds__(256, 1)
edge_kernel_mma(const float* __restrict__ x, const int* __restrict__ eidx,
                const float* __restrict__ be1, const float* __restrict__ be2,
                const float* __restrict__ geW, const float* __restrict__ bleW, int l)
{
    extern __shared__ char dyn[];
    u16* sAh = (u16*)(dyn + OFF_A);
    u16* sAl = sAh + 64 * SA;
    u16* sBh = (u16*)(dyn + OFF_B);
    u16* sBl = sBh + 128 * SB;
    u16* sW2h = (u16*)(dyn + OFF_W2);
    u16* sW2l = sW2h + 64 * SH;
    u16* sHh = sBh;                   // overlay: h chunk reuses B region
    u16* sHl = sHh + 64 * SH;
    float* sm_p = (float*)(dyn + OFF_A);   // overlay: p tile reuses A region

    __shared__ int s_src[64], s_dst[64];
    __shared__ float s_b1[512], s_b2[64], s_g[64], s_bb[64];
    __shared__ float s_mu[64], s_rs[64];

    const int tid = threadIdx.x;
    const int lane = tid & 31;
    const int w = tid >> 5;
    const int g = lane >> 2;          // 0..7
    const int t = lane & 3;           // 0..3
    const int m0 = (w & 3) * 16;      // warp m-group
    const int ngrp = w >> 2;          // warp n-group (0/1)
    const int b = blockIdx.y;
    const int e0 = blockIdx.x * 64;

    if (tid < 64) {
        s_src[tid] = eidx[e0 + tid];
        s_dst[tid] = eidx[NEDGE + e0 + tid];
    }
    for (int i = tid; i < 512; i += 256) s_b1[i] = be1[l * HD + i];
    if (tid < 64) {
        s_b2[tid] = be2[l * ED + tid];
        s_g[tid]  = geW[l * ED + tid];
        s_bb[tid] = bleW[l * ED + tid];
    }
    __syncthreads();

    const float* xb = x + (size_t)b * NNODE * ND;
    const float* eb = g_e + (size_t)b * NEDGE * ED;

    // ---- gather + split-convert A[64][576] -> bf16 hi/lo smem ----
    for (int i = tid; i < 64 * 144; i += 256) {
        int r = i / 144, q4 = i - r * 144;
        int k = q4 * 4;
        float4 v;
        if (k < 64)       v = *(const float4*)(eb + (size_t)(e0 + r) * ED + k);
        else if (k < 320) v = *(const float4*)(xb + (size_t)s_src[r] * ND + (k - 64));
        else              v = *(const float4*)(xb + (size_t)s_dst[r] * ND + (k - 320));
        u16 h0 = bf_hi(v.x), h1 = bf_hi(v.y), h2 = bf_hi(v.z), h3 = bf_hi(v.w);
        u16 l0 = bf_hi(v.x - bf_f(h0)), l1 = bf_hi(v.y - bf_f(h1));
        u16 l2 = bf_hi(v.z - bf_f(h2)), l3 = bf_hi(v.w - bf_f(h3));
        size_t o = (size_t)r * SA + k;
        *(ull*)(sAh + o) = (ull)h0 | ((ull)h1 << 16) | ((ull)h2 << 32) | ((ull)h3 << 48);
        *(ull*)(sAl + o) = (ull)l0 | ((ull)l1 << 16) | ((ull)l2 << 32) | ((ull)l3 << 48);
    }
    __syncthreads();

    const u16* W1h = gW1T_hi + (size_t)l * HD * K1E;
    const u16* W1l = gW1T_lo + (size_t)l * HD * K1E;
    const u16* W2h = gW2T_hi + (size_t)l * ED * HD;
    const u16* W2l = gW2T_lo + (size_t)l * ED * HD;

    float acc2[4][4];                 // GEMM2 out 16x32/warp, across all chunks
    #pragma unroll
    for (int j = 0; j < 4; j++)
        #pragma unroll
        for (int q = 0; q < 4; q++) acc2[j][q] = 0.0f;

    for (int nc = 0; nc < 4; nc++) {
        float acc1[8][4];             // GEMM1 chunk out 16x64/warp
        #pragma unroll
        for (int j = 0; j < 8; j++)
            #pragma unroll
            for (int q = 0; q < 4; q++) acc1[j][q] = 0.0f;

        // B slab prefetch (kc=0): 128n x 64k hi/lo, 4+4 uint4 per thread
        uint4 ph[4], pl[4];
        #pragma unroll
        for (int j = 0; j < 4; j++) {
            int lin = j * 256 + tid;
            int n = lin >> 3, q = lin & 7;
            size_t go = (size_t)(nc * 128 + n) * K1E + q * 8;
            ph[j] = *(const uint4*)(W1h + go);
            pl[j] = *(const uint4*)(W1l + go);
        }

        for (int kc = 0; kc < 9; kc++) {
            // store prefetched slab
            #pragma unroll
            for (int j = 0; j < 4; j++) {
                int lin = j * 256 + tid;
                int n = lin >> 3, q = lin & 7;
                *(uint4*)(sBh + n * SB + q * 8) = ph[j];
                *(uint4*)(sBl + n * SB + q * 8) = pl[j];
            }
            __syncthreads();
            if (kc < 8) {             // overlap next slab's LDG with mma
                #pragma unroll
                for (int j = 0; j < 4; j++) {
                    int lin = j * 256 + tid;
                    int n = lin >> 3, q = lin & 7;
                    size_t go = (size_t)(nc * 128 + n) * K1E + (kc + 1) * 64 + q * 8;
                    ph[j] = *(const uint4*)(W1h + go);
                    pl[j] = *(const uint4*)(W1l + go);
                }
            }
            #pragma unroll
            for (int ks = 0; ks < 4; ks++) {
                int kA = kc * 64 + ks * 16;
                u32 ah[4], al[4];
                ah[0] = *(const u32*)(sAh + (m0 + g) * SA + kA + 2 * t);
                ah[1] = *(const u32*)(sAh + (m0 + g + 8) * SA + kA + 2 * t);
                ah[2] = *(const u32*)(sAh + (m0 + g) * SA + kA + 2 * t + 8);
                ah[3] = *(const u32*)(sAh + (m0 + g + 8) * SA + kA + 2 * t + 8);
                al[0] = *(const u32*)(sAl + (m0 + g) * SA + kA + 2 * t);
                al[1] = *(const u32*)(sAl + (m0 + g + 8) * SA + kA + 2 * t);
                al[2] = *(const u32*)(sAl + (m0 + g) * SA + kA + 2 * t + 8);
                al[3] = *(const u32*)(sAl + (m0 + g + 8) * SA + kA + 2 * t + 8);
                int kB = ks * 16;
                #pragma unroll
                for (int j = 0; j < 8; j++) {
                    int n = ngrp * 64 + j * 8 + g;
                    u32 bh0 = *(const u32*)(sBh + n * SB + kB + 2 * t);
                    u32 bh1 = *(const u32*)(sBh + n * SB + kB + 2 * t + 8);
                    u32 bl0 = *(const u32*)(sBl + n * SB + kB + 2 * t);
                    u32 bl1 = *(const u32*)(sBl + n * SB + kB + 2 * t + 8);
                    mma16816(acc1[j], ah, bh0, bh1);   // hi*hi
                    mma16816(acc1[j], ah, bl0, bl1);   // hi*lo
                    mma16816(acc1[j], al, bh0, bh1);   // lo*hi
                }
            }
            __syncthreads();
        }

        // ---- silu + bias -> h (bf16 hi/lo) into B region ----
        #pragma unroll
        for (int j = 0; j < 8; j++) {
            int col = ngrp * 64 + j * 8 + 2 * t;
            int bc = nc * 128 + col;
            float v0 = silu_f(acc1[j][0] + s_b1[bc]);
            float v1 = silu_f(acc1[j][1] + s_b1[bc + 1]);
            float v2 = silu_f(acc1[j][2] + s_b1[bc]);
            float v3 = silu_f(acc1[j][3] + s_b1[bc + 1]);
            u16 h0 = bf_hi(v0), h1 = bf_hi(v1);
            u16 h2 = bf_hi(v2), h3 = bf_hi(v3);
            *(u32*)(sHh + (m0 + g) * SH + col)     = (u32)h0 | ((u32)h1 << 16);
            *(u32*)(sHh + (m0 + g + 8) * SH + col) = (u32)h2 | ((u32)h3 << 16);
            u16 q0 = bf_hi(v0 - bf_f(h0)), q1 = bf_hi(v1 - bf_f(h1));
            u16 q2 = bf_hi(v2 - bf_f(h2)), q3 = bf_hi(v3 - bf_f(h3));
            *(u32*)(sHl + (m0 + g) * SH + col)     = (u32)q0 | ((u32)q1 << 16);
            *(u32*)(sHl + (m0 + g + 8) * SH + col) = (u32)q2 | ((u32)q3 << 16);
        }
        // ---- load W2 chunk [64n][128k] hi/lo ----
        #pragma unroll
        for (int j = 0; j < 4; j++) {
            int lin = j * 256 + tid;
            int n = lin >> 4, q = lin & 15;
            size_t go = (size_t)n * HD + nc * 128 + q * 8;
            *(uint4*)(sW2h + n * SH + q * 8) = *(const uint4*)(W2h + go);
            *(uint4*)(sW2l + n * SH + q * 8) = *(const uint4*)(W2l + go);
        }
        __syncthreads();

        // ---- GEMM2: acc2 += h_chunk @ W2_chunk ----
        #pragma unroll
        for (int ks = 0; ks < 8; ks++) {
            int k0 = ks * 16;
            u32 ah[4], al[4];
            ah[0] = *(const u32*)(sHh + (m0 + g) * SH + k0 + 2 * t);
            ah[1] = *(const u32*)(sHh + (m0 + g + 8) * SH + k0 + 2 * t);
            ah[2] = *(const u32*)(sHh + (m0 + g) * SH + k0 + 2 * t + 8);
            ah[3] = *(const u32*)(sHh + (m0 + g + 8) * SH + k0 + 2 * t + 8);
            al[0] = *(const u32*)(sHl + (m0 + g) * SH + k0 + 2 * t);
            al[1] = *(const u32*)(sHl + (m0 + g + 8) * SH + k0 + 2 * t);
            al[2] = *(const u32*)(sHl + (m0 + g) * SH + k0 + 2 * t + 8);
            al[3] = *(const u32*)(sHl + (m0 + g + 8) * SH + k0 + 2 * t + 8);
            #pragma unroll
            for (int j = 0; j < 4; j++) {
                int n = ngrp * 32 + j * 8 + g;
                u32 bh0 = *(const u32*)(sW2h + n * SH + k0 + 2 * t);
                u32 bh1 = *(const u32*)(sW2h + n * SH + k0 + 2 * t + 8);
                u32 bl0 = *(const u32*)(sW2l + n * SH + k0 + 2 * t);
                u32 bl1 = *(const u32*)(sW2l + n * SH + k0 + 2 * t + 8);
                mma16816(acc2[j], ah, bh0, bh1);
                mma16816(acc2[j], ah, bl0, bl1);
                mma16816(acc2[j], al, bh0, bh1);
            }
        }
        __syncthreads();   // h region free before next nc's B store
    }

    // ---- epilogue: bias -> p (overlay A region), LN(64), residual, scatter
    #pragma unroll
    for (int j = 0; j < 4; j++) {
        int col = ngrp * 32 + j * 8 + 2 * t;
        sm_p[(m0 + g) * 68 + col]         = acc2[j][0] + s_b2[col];
        sm_p[(m0 + g) * 68 + col + 1]     = acc2[j][1] + s_b2[col + 1];
        sm_p[(m0 + g + 8) * 68 + col]     = acc2[j][2] + s_b2[col];
        sm_p[(m0 + g + 8) * 68 + col + 1] = acc2[j][3] + s_b2[col + 1];
    }
    __syncthreads();
    {
        int r = tid >> 2, sub = tid & 3;
        float s = 0.f, s2 = 0.f;
        #pragma unroll
        for (int cc = 0; cc < 16; cc++) {
            float v = sm_p[r * 68 + sub * 16 + cc];
            s += v; s2 += v * v;
        }
        s  += __shfl_xor_sync(0xffffffffu, s, 1);
        s  += __shfl_xor_sync(0xffffffffu, s, 2);
        s2 += __shfl_xor_sync(0xffffffffu, s2, 1);
        s2 += __shfl_xor_sync(0xffffffffu, s2, 2);
        if (sub == 0) {
            float mu = s * (1.0f / 64.0f);
            s_mu[r] = mu;
            s_rs[r] = rsqrtf(s2 * (1.0f / 64.0f) - mu * mu + 1e-5f);
        }
    }
    __syncthreads();
    {
        int c = tid & 63, grp = tid >> 6;
        float gv = s_g[c], bv = s_bb[c];
        float* eo = g_e + (size_t)b * NEDGE * ED;
        float* ag = g_agg + (size_t)b * NNODE * ED;
        #pragma unroll 4
        for (int rr = 0; rr < 16; rr++) {
            int r = grp * 16 + rr;
            float p = sm_p[r * 68 + c];
            float en = eo[(size_t)(e0 + r) * ED + c]
                     + (p - s_mu[r]) * s_rs[r] * gv + bv;
            eo[(size_t)(e0 + r) * ED + c] = en;
            atomicAdd(ag + (size_t)s_dst[r] * ED + c, en);
        }
    }
}

// ===================== NODE KERNEL (FFMA2, validated R4) =============
#define N_IN  (64 * 324)
#define N_W   (64 * 132)
#define N_P   (64 * 260)
#define NODE_SMEM ((N_IN + N_W + N_P + 128) * 4)

__global__ void __launch_bounds__(256, 1)
node_kernel(float* __restrict__ x,
            const float* __restrict__ Wn1, const float* __restrict__ bn1,
            const float* __restrict__ Wn2, const float* __restrict__ bn2,
            const float* __restrict__ gnW, const float* __restrict__ blnW, int l)
{
    extern __shared__ float sm[];
    float* sm_in = sm;
    float* sm_w  = sm_in + N_IN;
    float* sm_p  = sm_w + N_W;
    float* sm_mu = sm_p + N_P;
    float* sm_rs = sm_mu + 64;

    const int tid = threadIdx.x;
    const int tx = tid & 15, ty = tid >> 4;
    const int b = blockIdx.y;
    const int n0 = blockIdx.x * 64;

    const float4* x4 = (const float4*)(x + (size_t)b * NNODE * ND);
    const float4* a4 = (const float4*)(g_agg + (size_t)b * NNODE * ED);

    for (int i = tid; i < 64 * 80; i += 256) {
        int r = i / 80, q = i - r * 80;
        int node = min(n0 + r, NNODE - 1);
        float4 v = (q < 64) ? x4[(size_t)node * 64 + q]
                            : a4[(size_t)node * 16 + (q - 64)];
        *(float4*)(sm_in + r * 324 + q * 4) = v;
    }

    const float* W1 = Wn1 + (size_t)l * K1N * HD;
    const float* B1 = bn1 + l * HD;
    const float* W2 = Wn2 + (size_t)l * HD * ND;
    const float* B2 = bn2 + l * ND;

    ullt oa[4][8];
    #pragma unroll
    for (int i = 0; i < 4; i++)
        #pragma unroll
        for (int j = 0; j < 8; j++) oa[i][j] = 0ull;

    for (int nc = 0; nc < 4; nc++) {
        ullt ha[4][4];
        #pragma unroll
        for (int i = 0; i < 4; i++)
            #pragma unroll
            for (int j = 0; j < 4; j++) ha[i][j] = 0ull;

        for (int k0 = 0; k0 < K1N; k0 += 64) {
            __syncthreads();
            for (int i = tid; i < 2048; i += 256) {
                int kk = i >> 5, c = i & 31;
                ((float4*)(sm_w + kk * 132))[c] =
                    ((const float4*)(W1 + (size_t)(k0 + kk) * HD + nc * 128))[c];
            }
            __syncthreads();
            #pragma unroll 4
            for (int k4 = 0; k4 < 16; k4++) {
                float4 av[4];
                #pragma unroll
                for (int i = 0; i < 4; i++)
                    av[i] = *(const float4*)(sm_in + (ty * 4 + i) * 324 + k0 + k4 * 4);
                #pragma unroll
                for (int u = 0; u < 4; u++) {
                    int kk = k4 * 4 + u;
                    ulonglong2 b0 = *(const ulonglong2*)(sm_w + kk * 132 + tx * 8);
                    ulonglong2 b1 = *(const ulonglong2*)(sm_w + kk * 132 + tx * 8 + 4);
                    #pragma unroll
                    for (int i = 0; i < 4; i++) {
                        float a = (u == 0) ? av[i].x : (u == 1) ? av[i].y
                                : (u == 2) ? av[i].z : av[i].w;
                        ullt ap = pk(a, a);
                        ffma2(ha[i][0], ap, b0.x); ffma2(ha[i][1], ap, b0.y);
                        ffma2(ha[i][2], ap, b1.x); ffma2(ha[i][3], ap, b1.y);
                    }
                }
            }
        }
        __syncthreads();

        #pragma unroll
        for (int i = 0; i < 4; i++)
            #pragma unroll
            for (int j = 0; j < 4; j++) {
                float2 v = up(ha[i][j]);
                int c = nc * 128 + tx * 8 + j * 2;
                float s0 = v.x + B1[c], s1 = v.y + B1[c + 1];
                sm_w[(ty * 4 + i) * 132 + tx * 8 + j * 2]     = silu_f(s0);
                sm_w[(ty * 4 + i) * 132 + tx * 8 + j * 2 + 1] = silu_f(s1);
            }

        for (int s = 0; s < 2; s++) {
            for (int i = tid; i < 4096; i += 256) {
                int kk = i >> 6, c = i & 63;
                ((float4*)(sm_p + kk * 260))[c] =
                    ((const float4*)(W2 + (size_t)(nc * 128 + s * 64 + kk) * ND))[c];
            }
            __syncthreads();
            #pragma unroll 2
            for (int k4 = 0; k4 < 16; k4++) {
                float4 av[4];
                #pragma unroll
                for (int i = 0; i < 4; i++)
                    av[i] = *(const float4*)(sm_w + (ty * 4 + i) * 132 + s * 64 + k4 * 4);
                #pragma unroll
                for (int u = 0; u < 4; u++) {
                    int kk = k4 * 4 + u;
                    const ulonglong2* bp = (const ulonglong2*)(sm_p + kk * 260 + tx * 16);
                    ulonglong2 q0 = bp[0], q1 = bp[1], q2 = bp[2], q3 = bp[3];
                    #pragma unroll
                    for (int i = 0; i < 4; i++) {
                        float a = (u == 0) ? av[i].x : (u == 1) ? av[i].y
                                : (u == 2) ? av[i].z : av[i].w;
                        ullt ap = pk(a, a);
                        ffma2(oa[i][0], ap, q0.x); ffma2(oa[i][1], ap, q0.y);
                        ffma2(oa[i][2], ap, q1.x); ffma2(oa[i][3], ap, q1.y);
                        ffma2(oa[i][4], ap, q2.x); ffma2(oa[i][5], ap, q2.y);
                        ffma2(oa[i][6], ap, q3.x); ffma2(oa[i][7], ap, q3.y);
                    }
                }
            }
            __syncthreads();
        }
    }

    #pragma unroll
    for (int i = 0; i < 4; i++)
        #pragma unroll
        for (int j = 0; j < 8; j++) {
            float2 v = up(oa[i][j]);
            int c = tx * 16 + j * 2;
            sm_p[(ty * 4 + i) * 260 + c]     = v.x + B2[c];
            sm_p[(ty * 4 + i) * 260 + c + 1] = v.y + B2[c + 1];
        }
    __syncthreads();
    {
        int r = tid >> 2, sub = tid & 3;
        float s = 0.f, s2 = 0.f;
        #pragma unroll 8
        for (int cc = 0; cc < 64; cc++) {
            float v = sm_p[r * 260 + sub * 64 + cc];
            s += v; s2 += v * v;
        }
        s  += __shfl_xor_sync(0xffffffffu, s, 1);
        s  += __shfl_xor_sync(0xffffffffu, s, 2);
        s2 += __shfl_xor_sync(0xffffffffu, s2, 1);
        s2 += __shfl_xor_sync(0xffffffffu, s2, 2);
        if (sub == 0) {
            float mu = s * (1.0f / 256.0f);
            sm_mu[r] = mu;
            sm_rs[r] = rsqrtf(s2 * (1.0f / 256.0f) - mu * mu + 1e-5f);
        }
    }
    __syncthreads();
    {
        int c = tid;
        float gv = gnW[l * ND + c], bv = blnW[l * ND + c];
        float* xo = x + (size_t)b * NNODE * ND;
        for (int rr = 0; rr < 64; rr++) {
            if (n0 + rr < NNODE) {
                float v = sm_p[rr * 260 + c];
                xo[(size_t)(n0 + rr) * ND + c] =
                    sm_in[rr * 324 + c] + (v - sm_mu[rr]) * sm_rs[rr] * gv + bv;
            }
        }
    }
}

// ============================== LAUNCH ===============================
extern "C" void kernel_launch(void* const* d_in, const int* in_sizes, int n_in,
                              void* d_out, int out_size) {
    const float* nf  = (const float*)d_in[0];
    const float* ef  = (const float*)d_in[1];
    const float* We1 = (const float*)d_in[2];
    const float* be1 = (const float*)d_in[3];
    const float* We2 = (const float*)d_in[4];
    const float* be2 = (const float*)d_in[5];
    const float* geW = (const float*)d_in[6];
    const float* ble = (const float*)d_in[7];
    const float* Wn1 = (const float*)d_in[8];
    const float* bn1 = (const float*)d_in[9];
    const float* Wn2 = (const float*)d_in[10];
    const float* bn2 = (const float*)d_in[11];
    const float* gnW = (const float*)d_in[12];
    const float* bln = (const float*)d_in[13];
    const int*  eidx = (const int*)d_in[14];
    float* x = (float*)d_out;

    cudaFuncSetAttribute(edge_kernel_mma, cudaFuncAttributeMaxDynamicSharedMemorySize, EDGE_DSMEM);
    cudaFuncSetAttribute(node_kernel, cudaFuncAttributeMaxDynamicSharedMemorySize, NODE_SMEM);

    prep_w1<<<2048, 256>>>(We1);
    prep_w2<<<512, 256>>>(We2);

    cudaMemcpyAsync(x, nf, sizeof(float) * (size_t)NB * NNODE * ND,
                    cudaMemcpyDeviceToDevice, 0);
    size_t ebytes = sizeof(float) * (size_t)NEDGE * ED;
    cudaMemcpyToSymbolAsync(g_e, ef, ebytes, 0, cudaMemcpyDeviceToDevice, 0);
    cudaMemcpyToSymbolAsync(g_e, ef, ebytes, ebytes, cudaMemcpyDeviceToDevice, 0);

    dim3 eg(NEDGE / 64, NB);
    dim3 ng((NNODE + 63) / 64, NB);
    for (int l = 0; l < NL; l++) {
        zero_agg_kernel<<<512, 256>>>();
        edge_kernel_mma<<<eg, 256, EDGE_DSMEM>>>(x, eidx, be1, be2, geW, ble, l);
        node_kernel<<<ng, 256, NODE_SMEM>>>(x, Wn1, bn1, Wn2, bn2, gnW, bln, l);
    }
}

// round 8
// speedup vs baseline: 3.0165x; 1.3362x over previous
#include <cuda_runtime.h>
#include <cuda_bf16.h>
#include <cstdint>

#define NB 2
#define NNODE 40962
#define NEDGE 327680
#define ND 256
#define ED 64
#define HD 512
#define NL 16
#define K1E 576   /* ED + 2*ND */
#define K1N 320   /* ND + ED   */

typedef unsigned long long ull;
typedef unsigned int u32;
typedef unsigned short u16;

// ----------------------------- scratch ------------------------------
__device__ float g_e[(size_t)NB * NEDGE * ED];
__device__ float g_agg[(size_t)NB * NNODE * ED];
// split-bf16 transposed weights (edge + node)
__device__ u16 gW1T_hi[(size_t)NL * HD * K1E];
__device__ u16 gW1T_lo[(size_t)NL * HD * K1E];
__device__ u16 gW2T_hi[(size_t)NL * ED * HD];
__device__ u16 gW2T_lo[(size_t)NL * ED * HD];
__device__ u16 gWn1T_hi[(size_t)NL * HD * K1N];
__device__ u16 gWn1T_lo[(size_t)NL * HD * K1N];
__device__ u16 gWn2T_hi[(size_t)NL * ND * HD];
__device__ u16 gWn2T_lo[(size_t)NL * ND * HD];

// --------------------------- helpers --------------------------------
__device__ __forceinline__ u16 bf_hi(float v) {
    return __bfloat16_as_ushort(__float2bfloat16_rn(v));
}
__device__ __forceinline__ float bf_f(u16 h) {
    return __bfloat162float(__ushort_as_bfloat16(h));
}
__device__ __forceinline__ float silu_f(float v) {
    return __fdividef(v, 1.0f + __expf(-v));
}
__device__ __forceinline__ u32 smem_u32(const void* p) {
    u32 a; asm("{ .reg .u64 t; cvta.to.shared.u64 t, %1; cvt.u32.u64 %0, t; }"
               : "=r"(a) : "l"(p));
    return a;
}
__device__ __forceinline__ void mma16816(float* d, const u32* a, u32 b0, u32 b1) {
    asm volatile(
        "mma.sync.aligned.m16n8k16.row.col.f32.bf16.bf16.f32 "
        "{%0,%1,%2,%3}, {%4,%5,%6,%7}, {%8,%9}, {%0,%1,%2,%3};"
        : "+f"(d[0]), "+f"(d[1]), "+f"(d[2]), "+f"(d[3])
        : "r"(a[0]), "r"(a[1]), "r"(a[2]), "r"(a[3]), "r"(b0), "r"(b1));
}
__device__ __forceinline__ void ldm_x4(u32* r, u32 a) {
    asm volatile("ldmatrix.sync.aligned.m8n8.x4.shared.b16 {%0,%1,%2,%3}, [%4];"
        : "=r"(r[0]), "=r"(r[1]), "=r"(r[2]), "=r"(r[3]) : "r"(a));
}
__device__ __forceinline__ void ldm_x2(u32& r0, u32& r1, u32 a) {
    asm volatile("ldmatrix.sync.aligned.m8n8.x2.shared.b16 {%0,%1}, [%2];"
        : "=r"(r0), "=r"(r1) : "r"(a));
}

// --------------------------- prep kernels ---------------------------
__global__ void prep_w1(const float* __restrict__ W) {
    size_t tot = (size_t)NL * K1E * HD;
    for (size_t i = (size_t)blockIdx.x * blockDim.x + threadIdx.x; i < tot;
         i += (size_t)gridDim.x * blockDim.x) {
        size_t l = i / ((size_t)K1E * HD);
        size_t rem = i - l * (size_t)K1E * HD;
        size_t k = rem / HD, n = rem - k * HD;
        float w = W[i];
        u16 hi = bf_hi(w), lo = bf_hi(w - bf_f(hi));
        size_t o = (l * HD + n) * K1E + k;
        gW1T_hi[o] = hi; gW1T_lo[o] = lo;
    }
}
__global__ void prep_w2(const float* __restrict__ W) {
    size_t tot = (size_t)NL * HD * ED;
    for (size_t i = (size_t)blockIdx.x * blockDim.x + threadIdx.x; i < tot;
         i += (size_t)gridDim.x * blockDim.x) {
        size_t l = i / ((size_t)HD * ED);
        size_t rem = i - l * (size_t)HD * ED;
        size_t k = rem / ED, n = rem - k * ED;
        float w = W[i];
        u16 hi = bf_hi(w), lo = bf_hi(w - bf_f(hi));
        size_t o = (l * ED + n) * HD + k;
        gW2T_hi[o] = hi; gW2T_lo[o] = lo;
    }
}
__global__ void prep_wn1(const float* __restrict__ W) {
    size_t tot = (size_t)NL * K1N * HD;
    for (size_t i = (size_t)blockIdx.x * blockDim.x + threadIdx.x; i < tot;
         i += (size_t)gridDim.x * blockDim.x) {
        size_t l = i / ((size_t)K1N * HD);
        size_t rem = i - l * (size_t)K1N * HD;
        size_t k = rem / HD, n = rem - k * HD;
        float w = W[i];
        u16 hi = bf_hi(w), lo = bf_hi(w - bf_f(hi));
        size_t o = (l * HD + n) * K1N + k;
        gWn1T_hi[o] = hi; gWn1T_lo[o] = lo;
    }
}
__global__ void prep_wn2(const float* __restrict__ W) {
    size_t tot = (size_t)NL * HD * ND;
    for (size_t i = (size_t)blockIdx.x * blockDim.x + threadIdx.x; i < tot;
         i += (size_t)gridDim.x * blockDim.x) {
        size_t l = i / ((size_t)HD * ND);
        size_t rem = i - l * (size_t)HD * ND;
        size_t k = rem / ND, n = rem - k * ND;
        float w = W[i];
        u16 hi = bf_hi(w), lo = bf_hi(w - bf_f(hi));
        size_t o = (l * ND + n) * HD + k;
        gWn2T_hi[o] = hi; gWn2T_lo[o] = lo;
    }
}

__global__ void zero_agg_kernel() {
    size_t n = (size_t)NB * NNODE * ED;
    for (size_t i = (size_t)blockIdx.x * blockDim.x + threadIdx.x; i < n;
         i += (size_t)gridDim.x * blockDim.x)
        g_agg[i] = 0.0f;
}

// ===================== EDGE KERNEL (HMMA + ldmatrix) ==================
#define SA 584    /* A row stride: 1168B = 73 x 16B (odd) */
#define SB 72     /* B slab row stride: 144B = 9 x 16B    */
#define SH 136    /* h / W2 row stride: 272B = 17 x 16B   */
#define OFF_A  0
#define OFF_B  149504
#define OFF_W2 186368
#define EDGE_DSMEM 221184

__global__ void __launch_bounds__(256, 1)
edge_kernel_mma(const float* __restrict__ x, const int* __restrict__ eidx,
                const float* __restrict__ be1, const float* __restrict__ be2,
                const float* __restrict__ geW, const float* __restrict__ bleW, int l)
{
    extern __shared__ char dyn[];
    u16* sAh = (u16*)(dyn + OFF_A);
    u16* sAl = sAh + 64 * SA;
    u16* sBh = (u16*)(dyn + OFF_B);
    u16* sBl = sBh + 128 * SB;
    u16* sW2h = (u16*)(dyn + OFF_W2);
    u16* sW2l = sW2h + 64 * SH;
    u16* sHh = sBh;
    u16* sHl = sHh + 64 * SH;
    float* sm_p = (float*)(dyn + OFF_A);

    __shared__ int s_src[64], s_dst[64];
    __shared__ float s_b1[512], s_b2[64], s_g[64], s_bb[64];
    __shared__ float s_mu[64], s_rs[64];

    const int tid = threadIdx.x;
    const int lane = tid & 31;
    const int w = tid >> 5;
    const int g = lane >> 2;
    const int t = lane & 3;
    const int m0 = (w & 3) * 16;
    const int ngrp = w >> 2;
    const int b = blockIdx.y;
    const int e0 = blockIdx.x * 64;

    if (tid < 64) {
        s_src[tid] = eidx[e0 + tid];
        s_dst[tid] = eidx[NEDGE + e0 + tid];
    }
    for (int i = tid; i < 512; i += 256) s_b1[i] = be1[l * HD + i];
    if (tid < 64) {
        s_b2[tid] = be2[l * ED + tid];
        s_g[tid]  = geW[l * ED + tid];
        s_bb[tid] = bleW[l * ED + tid];
    }
    __syncthreads();

    const float* xb = x + (size_t)b * NNODE * ND;
    const float* eb = g_e + (size_t)b * NEDGE * ED;

    for (int i = tid; i < 64 * 144; i += 256) {
        int r = i / 144, q4 = i - r * 144;
        int k = q4 * 4;
        float4 v;
        if (k < 64)       v = *(const float4*)(eb + (size_t)(e0 + r) * ED + k);
        else if (k < 320) v = *(const float4*)(xb + (size_t)s_src[r] * ND + (k - 64));
        else              v = *(const float4*)(xb + (size_t)s_dst[r] * ND + (k - 320));
        u16 h0 = bf_hi(v.x), h1 = bf_hi(v.y), h2 = bf_hi(v.z), h3 = bf_hi(v.w);
        u16 l0 = bf_hi(v.x - bf_f(h0)), l1 = bf_hi(v.y - bf_f(h1));
        u16 l2 = bf_hi(v.z - bf_f(h2)), l3 = bf_hi(v.w - bf_f(h3));
        size_t o = (size_t)r * SA + k;
        *(ull*)(sAh + o) = (ull)h0 | ((ull)h1 << 16) | ((ull)h2 << 32) | ((ull)h3 << 48);
        *(ull*)(sAl + o) = (ull)l0 | ((ull)l1 << 16) | ((ull)l2 << 32) | ((ull)l3 << 48);
    }
    __syncthreads();

    const u16* W1h = gW1T_hi + (size_t)l * HD * K1E;
    const u16* W1l = gW1T_lo + (size_t)l * HD * K1E;
    const u16* W2h = gW2T_hi + (size_t)l * ED * HD;
    const u16* W2l = gW2T_lo + (size_t)l * ED * HD;

    // ldmatrix base addresses (per-lane)
    const u32 aRowH = smem_u32(sAh) + (m0 + (lane & 15)) * SA * 2 + ((lane >> 4) * 8) * 2;
    const u32 aRowL = smem_u32(sAl) + (m0 + (lane & 15)) * SA * 2 + ((lane >> 4) * 8) * 2;
    const u32 bRowH = smem_u32(sBh) + (ngrp * 64 + (lane & 7)) * SB * 2 + ((lane >> 3) & 1) * 16;
    const u32 bRowL = smem_u32(sBl) + (ngrp * 64 + (lane & 7)) * SB * 2 + ((lane >> 3) & 1) * 16;
    const u32 hRowH = smem_u32(sHh) + (m0 + (lane & 15)) * SH * 2 + ((lane >> 4) * 8) * 2;
    const u32 hRowL = smem_u32(sHl) + (m0 + (lane & 15)) * SH * 2 + ((lane >> 4) * 8) * 2;
    const u32 wRowH = smem_u32(sW2h) + (ngrp * 32 + (lane & 7)) * SH * 2 + ((lane >> 3) & 1) * 16;
    const u32 wRowL = smem_u32(sW2l) + (ngrp * 32 + (lane & 7)) * SH * 2 + ((lane >> 3) & 1) * 16;

    float acc2[4][4];
    #pragma unroll
    for (int j = 0; j < 4; j++)
        #pragma unroll
        for (int q = 0; q < 4; q++) acc2[j][q] = 0.0f;

    for (int nc = 0; nc < 4; nc++) {
        float acc1[8][4];
        #pragma unroll
        for (int j = 0; j < 8; j++)
            #pragma unroll
            for (int q = 0; q < 4; q++) acc1[j][q] = 0.0f;

        uint4 ph[4], pl[4];
        #pragma unroll
        for (int j = 0; j < 4; j++) {
            int lin = j * 256 + tid;
            int n = lin >> 3, q = lin & 7;
            size_t go = (size_t)(nc * 128 + n) * K1E + q * 8;
            ph[j] = *(const uint4*)(W1h + go);
            pl[j] = *(const uint4*)(W1l + go);
        }

        for (int kc = 0; kc < 9; kc++) {
            #pragma unroll
            for (int j = 0; j < 4; j++) {
                int lin = j * 256 + tid;
                int n = lin >> 3, q = lin & 7;
                *(uint4*)(sBh + n * SB + q * 8) = ph[j];
                *(uint4*)(sBl + n * SB + q * 8) = pl[j];
            }
            __syncthreads();
            if (kc < 8) {
                #pragma unroll
                for (int j = 0; j < 4; j++) {
                    int lin = j * 256 + tid;
                    int n = lin >> 3, q = lin & 7;
                    size_t go = (size_t)(nc * 128 + n) * K1E + (kc + 1) * 64 + q * 8;
                    ph[j] = *(const uint4*)(W1h + go);
                    pl[j] = *(const uint4*)(W1l + go);
                }
            }
            #pragma unroll
            for (int ks = 0; ks < 4; ks++) {
                int kA = (kc * 64 + ks * 16) * 2;
                u32 ah[4], al[4];
                ldm_x4(ah, aRowH + kA);
                ldm_x4(al, aRowL + kA);
                int kB = (ks * 16) * 2;
                #pragma unroll
                for (int j = 0; j < 8; j++) {
                    u32 bh0, bh1, bl0, bl1;
                    ldm_x2(bh0, bh1, bRowH + j * (8 * SB * 2) + kB);
                    ldm_x2(bl0, bl1, bRowL + j * (8 * SB * 2) + kB);
                    mma16816(acc1[j], ah, bh0, bh1);
                    mma16816(acc1[j], ah, bl0, bl1);
                    mma16816(acc1[j], al, bh0, bh1);
                }
            }
            __syncthreads();
        }

        // silu + bias -> h (bf16 hi/lo) into B region
        #pragma unroll
        for (int j = 0; j < 8; j++) {
            int col = ngrp * 64 + j * 8 + 2 * t;
            int bc = nc * 128 + col;
            float v0 = silu_f(acc1[j][0] + s_b1[bc]);
            float v1 = silu_f(acc1[j][1] + s_b1[bc + 1]);
            float v2 = silu_f(acc1[j][2] + s_b1[bc]);
            float v3 = silu_f(acc1[j][3] + s_b1[bc + 1]);
            u16 h0 = bf_hi(v0), h1 = bf_hi(v1);
            u16 h2 = bf_hi(v2), h3 = bf_hi(v3);
            *(u32*)(sHh + (m0 + g) * SH + col)     = (u32)h0 | ((u32)h1 << 16);
            *(u32*)(sHh + (m0 + g + 8) * SH + col) = (u32)h2 | ((u32)h3 << 16);
            u16 q0 = bf_hi(v0 - bf_f(h0)), q1 = bf_hi(v1 - bf_f(h1));
            u16 q2 = bf_hi(v2 - bf_f(h2)), q3 = bf_hi(v3 - bf_f(h3));
            *(u32*)(sHl + (m0 + g) * SH + col)     = (u32)q0 | ((u32)q1 << 16);
            *(u32*)(sHl + (m0 + g + 8) * SH + col) = (u32)q2 | ((u32)q3 << 16);
        }
        #pragma unroll
        for (int j = 0; j < 4; j++) {
            int lin = j * 256 + tid;
            int n = lin >> 4, q = lin & 15;
            size_t go = (size_t)n * HD + nc * 128 + q * 8;
            *(uint4*)(sW2h + n * SH + q * 8) = *(const uint4*)(W2h + go);
            *(uint4*)(sW2l + n * SH + q * 8) = *(const uint4*)(W2l + go);
        }
        __syncthreads();

        #pragma unroll
        for (int ks = 0; ks < 8; ks++) {
            int k0 = (ks * 16) * 2;
            u32 ah[4], al[4];
            ldm_x4(ah, hRowH + k0);
            ldm_x4(al, hRowL + k0);
            #pragma unroll
            for (int j = 0; j < 4; j++) {
                u32 bh0, bh1, bl0, bl1;
                ldm_x2(bh0, bh1, wRowH + j * (8 * SH * 2) + k0);
                ldm_x2(bl0, bl1, wRowL + j * (8 * SH * 2) + k0);
                mma16816(acc2[j], ah, bh0, bh1);
                mma16816(acc2[j], ah, bl0, bl1);
                mma16816(acc2[j], al, bh0, bh1);
            }
        }
        __syncthreads();
    }

    // epilogue
    #pragma unroll
    for (int j = 0; j < 4; j++) {
        int col = ngrp * 32 + j * 8 + 2 * t;
        sm_p[(m0 + g) * 68 + col]         = acc2[j][0] + s_b2[col];
        sm_p[(m0 + g) * 68 + col + 1]     = acc2[j][1] + s_b2[col + 1];
        sm_p[(m0 + g + 8) * 68 + col]     = acc2[j][2] + s_b2[col];
        sm_p[(m0 + g + 8) * 68 + col + 1] = acc2[j][3] + s_b2[col + 1];
    }
    __syncthreads();
    {
        int r = tid >> 2, sub = tid & 3;
        float s = 0.f, s2 = 0.f;
        #pragma unroll
        for (int cc = 0; cc < 16; cc++) {
            float v = sm_p[r * 68 + sub * 16 + cc];
            s += v; s2 += v * v;
        }
        s  += __shfl_xor_sync(0xffffffffu, s, 1);
        s  += __shfl_xor_sync(0xffffffffu, s, 2);
        s2 += __shfl_xor_sync(0xffffffffu, s2, 1);
        s2 += __shfl_xor_sync(0xffffffffu, s2, 2);
        if (sub == 0) {
            float mu = s * (1.0f / 64.0f);
            s_mu[r] = mu;
            s_rs[r] = rsqrtf(s2 * (1.0f / 64.0f) - mu * mu + 1e-5f);
        }
    }
    __syncthreads();
    {
        int c = tid & 63, grp = tid >> 6;
        float gv = s_g[c], bv = s_bb[c];
        float* eo = g_e + (size_t)b * NEDGE * ED;
        float* ag = g_agg + (size_t)b * NNODE * ED;
        #pragma unroll 4
        for (int rr = 0; rr < 16; rr++) {
            int r = grp * 16 + rr;
            float p = sm_p[r * 68 + c];
            float en = eo[(size_t)(e0 + r) * ED + c]
                     + (p - s_mu[r]) * s_rs[r] * gv + bv;
            eo[(size_t)(e0 + r) * ED + c] = en;
            atomicAdd(ag + (size_t)s_dst[r] * ED + c, en);
        }
    }
}

// ===================== NODE KERNEL (HMMA + ldmatrix) =================
#define SA2 328   /* node A stride: 656B = 41 x 16B */
#define NOFF_A  0
#define NOFF_B  83968
#define NOFF_W2 120832
#define NODE_DSMEM 194560

__global__ void __launch_bounds__(256, 1)
node_kernel_mma(float* __restrict__ x,
                const float* __restrict__ bn1, const float* __restrict__ bn2,
                const float* __restrict__ gnW, const float* __restrict__ blnW, int l)
{
    extern __shared__ char dyn[];
    u16* sAh = (u16*)(dyn + NOFF_A);
    u16* sAl = sAh + 64 * SA2;
    u16* sBh = (u16*)(dyn + NOFF_B);
    u16* sBl = sBh + 128 * SB;
    u16* sW2h = (u16*)(dyn + NOFF_W2);
    u16* sW2l = sW2h + 256 * SB;
    u16* sHh = sBh;
    u16* sHl = sHh + 64 * SH;
    float* sm_p = (float*)(dyn + NOFF_A);     // overlay [64][260]

    __shared__ float s_b1[512], s_b2[256], s_g[256], s_bb[256];
    __shared__ float s_mu[64], s_rs[64];

    const int tid = threadIdx.x;
    const int lane = tid & 31;
    const int w = tid >> 5;
    const int g = lane >> 2;
    const int t = lane & 3;
    const int m0 = (w & 3) * 16;
    const int ngrp = w >> 2;
    const int b = blockIdx.y;
    const int n0 = blockIdx.x * 64;

    for (int i = tid; i < 512; i += 256) s_b1[i] = bn1[l * HD + i];
    if (tid < 256) {
        s_b2[tid] = bn2[l * ND + tid];
        s_g[tid]  = gnW[l * ND + tid];
        s_bb[tid] = blnW[l * ND + tid];
    }

    const float* xb = x + (size_t)b * NNODE * ND;
    const float* ab = g_agg + (size_t)b * NNODE * ED;

    // gather + split-convert [x|agg] 64 x 320
    for (int i = tid; i < 64 * 80; i += 256) {
        int r = i / 80, q4 = i - r * 80;
        int k = q4 * 4;
        int node = min(n0 + r, NNODE - 1);
        float4 v = (k < 256) ? *(const float4*)(xb + (size_t)node * ND + k)
                             : *(const float4*)(ab + (size_t)node * ED + (k - 256));
        u16 h0 = bf_hi(v.x), h1 = bf_hi(v.y), h2 = bf_hi(v.z), h3 = bf_hi(v.w);
        u16 l0 = bf_hi(v.x - bf_f(h0)), l1 = bf_hi(v.y - bf_f(h1));
        u16 l2 = bf_hi(v.z - bf_f(h2)), l3 = bf_hi(v.w - bf_f(h3));
        size_t o = (size_t)r * SA2 + k;
        *(ull*)(sAh + o) = (ull)h0 | ((ull)h1 << 16) | ((ull)h2 << 32) | ((ull)h3 << 48);
        *(ull*)(sAl + o) = (ull)l0 | ((ull)l1 << 16) | ((ull)l2 << 32) | ((ull)l3 << 48);
    }
    __syncthreads();

    const u16* W1h = gWn1T_hi + (size_t)l * HD * K1N;
    const u16* W1l = gWn1T_lo + (size_t)l * HD * K1N;
    const u16* W2h = gWn2T_hi + (size_t)l * ND * HD;
    const u16* W2l = gWn2T_lo + (size_t)l * ND * HD;

    const u32 aRowH = smem_u32(sAh) + (m0 + (lane & 15)) * SA2 * 2 + ((lane >> 4) * 8) * 2;
    const u32 aRowL = smem_u32(sAl) + (m0 + (lane & 15)) * SA2 * 2 + ((lane >> 4) * 8) * 2;
    const u32 bRowH = smem_u32(sBh) + (ngrp * 64 + (lane & 7)) * SB * 2 + ((lane >> 3) & 1) * 16;
    const u32 bRowL = smem_u32(sBl) + (ngrp * 64 + (lane & 7)) * SB * 2 + ((lane >> 3) & 1) * 16;
    const u32 hRowH = smem_u32(sHh) + (m0 + (lane & 15)) * SH * 2 + ((lane >> 4) * 8) * 2;
    const u32 hRowL = smem_u32(sHl) + (m0 + (lane & 15)) * SH * 2 + ((lane >> 4) * 8) * 2;
    const u32 wRowH = smem_u32(sW2h) + (ngrp * 128 + (lane & 7)) * SB * 2 + ((lane >> 3) & 1) * 16;
    const u32 wRowL = smem_u32(sW2l) + (ngrp * 128 + (lane & 7)) * SB * 2 + ((lane >> 3) & 1) * 16;

    float acc2[16][4];    // 16m x 128n per warp, all hidden chunks
    #pragma unroll
    for (int j = 0; j < 16; j++)
        #pragma unroll
        for (int q = 0; q < 4; q++) acc2[j][q] = 0.0f;

    for (int nc = 0; nc < 4; nc++) {
        float acc1[8][4];
        #pragma unroll
        for (int j = 0; j < 8; j++)
            #pragma unroll
            for (int q = 0; q < 4; q++) acc1[j][q] = 0.0f;

        uint4 ph[4], pl[4];
        #pragma unroll
        for (int j = 0; j < 4; j++) {
            int lin = j * 256 + tid;
            int n = lin >> 3, q = lin & 7;
            size_t go = (size_t)(nc * 128 + n) * K1N + q * 8;
            ph[j] = *(const uint4*)(W1h + go);
            pl[j] = *(const uint4*)(W1l + go);
        }

        for (int kc = 0; kc < 5; kc++) {
            #pragma unroll
            for (int j = 0; j < 4; j++) {
                int lin = j * 256 + tid;
                int n = lin >> 3, q = lin & 7;
                *(uint4*)(sBh + n * SB + q * 8) = ph[j];
                *(uint4*)(sBl + n * SB + q * 8) = pl[j];
            }
            __syncthreads();
            if (kc < 4) {
                #pragma unroll
                for (int j = 0; j < 4; j++) {
                    int lin = j * 256 + tid;
                    int n = lin >> 3, q = lin & 7;
                    size_t go = (size_t)(nc * 128 + n) * K1N + (kc + 1) * 64 + q * 8;
                    ph[j] = *(const uint4*)(W1h + go);
                    pl[j] = *(const uint4*)(W1l + go);
                }
            }
            #pragma unroll
            for (int ks = 0; ks < 4; ks++) {
                int kA = (kc * 64 + ks * 16) * 2;
                u32 ah[4], al[4];
                ldm_x4(ah, aRowH + kA);
                ldm_x4(al, aRowL + kA);
                int kB = (ks * 16) * 2;
                #pragma unroll
                for (int j = 0; j < 8; j++) {
                    u32 bh0, bh1, bl0, bl1;
                    ldm_x2(bh0, bh1, bRowH + j * (8 * SB * 2) + kB);
                    ldm_x2(bl0, bl1, bRowL + j * (8 * SB * 2) + kB);
                    mma16816(acc1[j], ah, bh0, bh1);
                    mma16816(acc1[j], ah, bl0, bl1);
                    mma16816(acc1[j], al, bh0, bh1);
                }
            }
            __syncthreads();
        }

        // silu + bias -> h (bf16 hi/lo) into B region
        #pragma unroll
        for (int j = 0; j < 8; j++) {
            int col = ngrp * 64 + j * 8 + 2 * t;
            int bc = nc * 128 + col;
            float v0 = silu_f(acc1[j][0] + s_b1[bc]);
            float v1 = silu_f(acc1[j][1] + s_b1[bc + 1]);
            float v2 = silu_f(acc1[j][2] + s_b1[bc]);
            float v3 = silu_f(acc1[j][3] + s_b1[bc + 1]);
            u16 h0 = bf_hi(v0), h1 = bf_hi(v1);
            u16 h2 = bf_hi(v2), h3 = bf_hi(v3);
            *(u32*)(sHh + (m0 + g) * SH + col)     = (u32)h0 | ((u32)h1 << 16);
            *(u32*)(sHh + (m0 + g + 8) * SH + col) = (u32)h2 | ((u32)h3 << 16);
            u16 q0 = bf_hi(v0 - bf_f(h0)), q1 = bf_hi(v1 - bf_f(h1));
            u16 q2 = bf_hi(v2 - bf_f(h2)), q3 = bf_hi(v3 - bf_f(h3));
            *(u32*)(sHl + (m0 + g) * SH + col)     = (u32)q0 | ((u32)q1 << 16);
            *(u32*)(sHl + (m0 + g + 8) * SH + col) = (u32)q2 | ((u32)q3 << 16);
        }

        // GEMM2 over two 64-k slabs of this hidden chunk
        for (int s = 0; s < 2; s++) {
            for (int i = tid; i < 2048; i += 256) {     // W2 slab [256n][64k]
                int n = i >> 3, q = i & 7;
                size_t go = (size_t)n * HD + nc * 128 + s * 64 + q * 8;
                *(uint4*)(sW2h + n * SB + q * 8) = *(const uint4*)(W2h + go);
                *(uint4*)(sW2l + n * SB + q * 8) = *(const uint4*)(W2l + go);
            }
            __syncthreads();
            #pragma unroll
            for (int ks = 0; ks < 4; ks++) {
                int kH = (s * 64 + ks * 16) * 2;
                int kW = (ks * 16) * 2;
                u32 ah[4], al[4];
                ldm_x4(ah, hRowH + kH);
                ldm_x4(al, hRowL + kH);
                #pragma unroll
                for (int j = 0; j < 16; j++) {
                    u32 bh0, bh1, bl0, bl1;
                    ldm_x2(bh0, bh1, wRowH + j * (8 * SB * 2) + kW);
                    ldm_x2(bl0, bl1, wRowL + j * (8 * SB * 2) + kW);
                    mma16816(acc2[j], ah, bh0, bh1);
                    mma16816(acc2[j], ah, bl0, bl1);
                    mma16816(acc2[j], al, bh0, bh1);
                }
            }
            __syncthreads();
        }
    }

    // epilogue: bias -> sm_p (overlay A), LN(256), residual, store
    #pragma unroll
    for (int j = 0; j < 16; j++) {
        int col = ngrp * 128 + j * 8 + 2 * t;
        sm_p[(m0 + g) * 260 + col]         = acc2[j][0] + s_b2[col];
        sm_p[(m0 + g) * 260 + col + 1]     = acc2[j][1] + s_b2[col + 1];
        sm_p[(m0 + g + 8) * 260 + col]     = acc2[j][2] + s_b2[col];
        sm_p[(m0 + g + 8) * 260 + col + 1] = acc2[j][3] + s_b2[col + 1];
    }
    __syncthreads();
    {
        int r = tid >> 2, sub = tid & 3;
        float s = 0.f, s2 = 0.f;
        #pragma unroll 8
        for (int cc = 0; cc < 64; cc++) {
            float v = sm_p[r * 260 + sub * 64 + cc];
            s += v; s2 += v * v;
        }
        s  += __shfl_xor_sync(0xffffffffu, s, 1);
        s  += __shfl_xor_sync(0xffffffffu, s, 2);
        s2 += __shfl_xor_sync(0xffffffffu, s2, 1);
        s2 += __shfl_xor_sync(0xffffffffu, s2, 2);
        if (sub == 0) {
            float mu = s * (1.0f / 256.0f);
            s_mu[r] = mu;
            s_rs[r] = rsqrtf(s2 * (1.0f / 256.0f) - mu * mu + 1e-5f);
        }
    }
    __syncthreads();
    {
        int c = tid;
        float gv = s_g[c], bv = s_bb[c];
        float* xo = x + (size_t)b * NNODE * ND;
        for (int rr = 0; rr < 64; rr++) {
            if (n0 + rr < NNODE) {
                float v = sm_p[rr * 260 + c];
                size_t o = (size_t)(n0 + rr) * ND + c;
                xo[o] = xo[o] + (v - s_mu[rr]) * s_rs[rr] * gv + bv;
            }
        }
    }
}

// ============================== LAUNCH ===============================
extern "C" void kernel_launch(void* const* d_in, const int* in_sizes, int n_in,
                              void* d_out, int out_size) {
    const float* nf  = (const float*)d_in[0];
    const float* ef  = (const float*)d_in[1];
    const float* We1 = (const float*)d_in[2];
    const float* be1 = (const float*)d_in[3];
    const float* We2 = (const float*)d_in[4];
    const float* be2 = (const float*)d_in[5];
    const float* geW = (const float*)d_in[6];
    const float* ble = (const float*)d_in[7];
    const float* Wn1 = (const float*)d_in[8];
    const float* bn1 = (const float*)d_in[9];
    const float* Wn2 = (const float*)d_in[10];
    const float* bn2 = (const float*)d_in[11];
    const float* gnW = (const float*)d_in[12];
    const float* bln = (const float*)d_in[13];
    const int*  eidx = (const int*)d_in[14];
    float* x = (float*)d_out;

    cudaFuncSetAttribute(edge_kernel_mma, cudaFuncAttributeMaxDynamicSharedMemorySize, EDGE_DSMEM);
    cudaFuncSetAttribute(node_kernel_mma, cudaFuncAttributeMaxDynamicSharedMemorySize, NODE_DSMEM);

    prep_w1<<<2048, 256>>>(We1);
    prep_w2<<<512, 256>>>(We2);
    prep_wn1<<<1024, 256>>>(Wn1);
    prep_wn2<<<1024, 256>>>(Wn2);

    cudaMemcpyAsync(x, nf, sizeof(float) * (size_t)NB * NNODE * ND,
                    cudaMemcpyDeviceToDevice, 0);
    size_t ebytes = sizeof(float) * (size_t)NEDGE * ED;
    cudaMemcpyToSymbolAsync(g_e, ef, ebytes, 0, cudaMemcpyDeviceToDevice, 0);
    cudaMemcpyToSymbolAsync(g_e, ef, ebytes, ebytes, cudaMemcpyDeviceToDevice, 0);

    dim3 eg(NEDGE / 64, NB);
    dim3 ng((NNODE + 63) / 64, NB);
    for (int l = 0; l < NL; l++) {
        zero_agg_kernel<<<512, 256>>>();
        edge_kernel_mma<<<eg, 256, EDGE_DSMEM>>>(x, eidx, be1, be2, geW, ble, l);
        node_kernel_mma<<<ng, 256, NODE_DSMEM>>>(x, bn1, bn2, gnW, bln, l);
    }
}

// round 10
// speedup vs baseline: 3.1788x; 1.0538x over previous
#include <cuda_runtime.h>
#include <cuda_bf16.h>
#include <cstdint>

#define NB 2
#define NNODE 40962
#define NEDGE 327680
#define ND 256
#define ED 64
#define HD 512
#define NL 16
#define K1E 576   /* ED + 2*ND */
#define K1N 320   /* ND + ED   */

typedef unsigned long long ull;
typedef unsigned int u32;
typedef unsigned short u16;

// ----------------------------- scratch ------------------------------
__device__ float g_e[(size_t)NB * NEDGE * ED];
__device__ float g_agg[(size_t)NB * NNODE * ED];
__device__ u16 gW1T_hi[(size_t)NL * HD * K1E];
__device__ u16 gW1T_lo[(size_t)NL * HD * K1E];
__device__ u16 gW2T_hi[(size_t)NL * ED * HD];
__device__ u16 gW2T_lo[(size_t)NL * ED * HD];
__device__ u16 gWn1T_hi[(size_t)NL * HD * K1N];
__device__ u16 gWn1T_lo[(size_t)NL * HD * K1N];
__device__ u16 gWn2T_hi[(size_t)NL * ND * HD];
__device__ u16 gWn2T_lo[(size_t)NL * ND * HD];

// --------------------------- helpers --------------------------------
__device__ __forceinline__ u16 bf_hi(float v) {
    return __bfloat16_as_ushort(__float2bfloat16_rn(v));
}
__device__ __forceinline__ float bf_f(u16 h) {
    return __bfloat162float(__ushort_as_bfloat16(h));
}
__device__ __forceinline__ float silu_f(float v) {
    return __fdividef(v, 1.0f + __expf(-v));
}
__device__ __forceinline__ u32 smem_u32(const void* p) {
    u32 a; asm("{ .reg .u64 t; cvta.to.shared.u64 t, %1; cvt.u32.u64 %0, t; }"
               : "=r"(a) : "l"(p));
    return a;
}
__device__ __forceinline__ void mma16816(float* d, const u32* a, u32 b0, u32 b1) {
    asm volatile(
        "mma.sync.aligned.m16n8k16.row.col.f32.bf16.bf16.f32 "
        "{%0,%1,%2,%3}, {%4,%5,%6,%7}, {%8,%9}, {%0,%1,%2,%3};"
        : "+f"(d[0]), "+f"(d[1]), "+f"(d[2]), "+f"(d[3])
        : "r"(a[0]), "r"(a[1]), "r"(a[2]), "r"(a[3]), "r"(b0), "r"(b1));
}
__device__ __forceinline__ void ldm_x4(u32* r, u32 a) {
    asm volatile("ldmatrix.sync.aligned.m8n8.x4.shared.b16 {%0,%1,%2,%3}, [%4];"
        : "=r"(r[0]), "=r"(r[1]), "=r"(r[2]), "=r"(r[3]) : "r"(a));
}
__device__ __forceinline__ void ldm_x2(u32& r0, u32& r1, u32 a) {
    asm volatile("ldmatrix.sync.aligned.m8n8.x2.shared.b16 {%0,%1}, [%2];"
        : "=r"(r0), "=r"(r1) : "r"(a));
}

// --------------------------- prep kernels ---------------------------
__global__ void prep_w1(const float* __restrict__ W) {
    size_t tot = (size_t)NL * K1E * HD;
    for (size_t i = (size_t)blockIdx.x * blockDim.x + threadIdx.x; i < tot;
         i += (size_t)gridDim.x * blockDim.x) {
        size_t l = i / ((size_t)K1E * HD);
        size_t rem = i - l * (size_t)K1E * HD;
        size_t k = rem / HD, n = rem - k * HD;
        float w = W[i];
        u16 hi = bf_hi(w), lo = bf_hi(w - bf_f(hi));
        size_t o = (l * HD + n) * K1E + k;
        gW1T_hi[o] = hi; gW1T_lo[o] = lo;
    }
}
__global__ void prep_w2(const float* __restrict__ W) {
    size_t tot = (size_t)NL * HD * ED;
    for (size_t i = (size_t)blockIdx.x * blockDim.x + threadIdx.x; i < tot;
         i += (size_t)gridDim.x * blockDim.x) {
        size_t l = i / ((size_t)HD * ED);
        size_t rem = i - l * (size_t)HD * ED;
        size_t k = rem / ED, n = rem - k * ED;
        float w = W[i];
        u16 hi = bf_hi(w), lo = bf_hi(w - bf_f(hi));
        size_t o = (l * ED + n) * HD + k;
        gW2T_hi[o] = hi; gW2T_lo[o] = lo;
    }
}
__global__ void prep_wn1(const float* __restrict__ W) {
    size_t tot = (size_t)NL * K1N * HD;
    for (size_t i = (size_t)blockIdx.x * blockDim.x + threadIdx.x; i < tot;
         i += (size_t)gridDim.x * blockDim.x) {
        size_t l = i / ((size_t)K1N * HD);
        size_t rem = i - l * (size_t)K1N * HD;
        size_t k = rem / HD, n = rem - k * HD;
        float w = W[i];
        u16 hi = bf_hi(w), lo = bf_hi(w - bf_f(hi));
        size_t o = (l * HD + n) * K1N + k;
        gWn1T_hi[o] = hi; gWn1T_lo[o] = lo;
    }
}
__global__ void prep_wn2(const float* __restrict__ W) {
    size_t tot = (size_t)NL * HD * ND;
    for (size_t i = (size_t)blockIdx.x * blockDim.x + threadIdx.x; i < tot;
         i += (size_t)gridDim.x * blockDim.x) {
        size_t l = i / ((size_t)HD * ND);
        size_t rem = i - l * (size_t)HD * ND;
        size_t k = rem / ND, n = rem - k * ND;
        float w = W[i];
        u16 hi = bf_hi(w), lo = bf_hi(w - bf_f(hi));
        size_t o = (l * ND + n) * HD + k;
        gWn2T_hi[o] = hi; gWn2T_lo[o] = lo;
    }
}

__global__ void zero_agg_kernel() {
    size_t n = (size_t)NB * NNODE * ED;
    for (size_t i = (size_t)blockIdx.x * blockDim.x + threadIdx.x; i < n;
         i += (size_t)gridDim.x * blockDim.x)
        g_agg[i] = 0.0f;
}

// strides
#define SA 584    /* edge A row stride */
#define SA2 328   /* node A row stride */
#define SB 72     /* B slab row stride */
#define SH 136    /* h / edge-W2 row stride */
#define BUFSZ 36864           /* one B buffer: hi+lo, 128 x SB x 2B x 2 */

// ===================== EDGE KERNEL ===================================
#define OFF_R2 149504                 /* 2 * 64*SA*2 */
#define EDGE_DSMEM (OFF_R2 + 2 * BUFSZ)   /* 223232 */

__global__ void __launch_bounds__(256, 1)
edge_kernel_mma(const float* __restrict__ x, const int* __restrict__ eidx,
                const float* __restrict__ be1, const float* __restrict__ be2,
                const float* __restrict__ geW, const float* __restrict__ bleW, int l)
{
    extern __shared__ char dyn[];
    u16* sAh = (u16*)(dyn);
    u16* sAl = sAh + 64 * SA;
    // B double buffers at OFF_R2 (+cur*BUFSZ); lo at +18432
    // GEMM2 overlay: H in buf0 region, W2 in buf1 region
    u16* sHh = (u16*)(dyn + OFF_R2);
    u16* sHl = sHh + 64 * SH;
    u16* sW2h = (u16*)(dyn + OFF_R2 + BUFSZ);
    u16* sW2l = sW2h + 64 * SH;
    float* sm_p = (float*)(dyn);      // epilogue overlay in A region

    __shared__ int s_src[64], s_dst[64];
    __shared__ float s_b1[512], s_b2[64], s_g[64], s_bb[64];
    __shared__ float s_mu[64], s_rs[64];

    const int tid = threadIdx.x;
    const int lane = tid & 31;
    const int w = tid >> 5;
    const int g = lane >> 2;
    const int t = lane & 3;
    const int mgrp = w & 1;
    const int ngrp = w >> 1;          // 0..3
    const int m0 = mgrp * 32;
    const int b = blockIdx.y;
    const int e0 = blockIdx.x * 64;

    if (tid < 64) {
        s_src[tid] = eidx[e0 + tid];
        s_dst[tid] = eidx[NEDGE + e0 + tid];
    }
    for (int i = tid; i < 512; i += 256) s_b1[i] = be1[l * HD + i];
    if (tid < 64) {
        s_b2[tid] = be2[l * ED + tid];
        s_g[tid]  = geW[l * ED + tid];
        s_bb[tid] = bleW[l * ED + tid];
    }
    __syncthreads();

    const float* xb = x + (size_t)b * NNODE * ND;
    const float* eb = g_e + (size_t)b * NEDGE * ED;

    // gather + split-convert A[64][576]
    for (int i = tid; i < 64 * 144; i += 256) {
        int r = i / 144, q4 = i - r * 144;
        int k = q4 * 4;
        float4 v;
        if (k < 64)       v = *(const float4*)(eb + (size_t)(e0 + r) * ED + k);
        else if (k < 320) v = *(const float4*)(xb + (size_t)s_src[r] * ND + (k - 64));
        else              v = *(const float4*)(xb + (size_t)s_dst[r] * ND + (k - 320));
        u16 h0 = bf_hi(v.x), h1 = bf_hi(v.y), h2 = bf_hi(v.z), h3 = bf_hi(v.w);
        u16 l0 = bf_hi(v.x - bf_f(h0)), l1 = bf_hi(v.y - bf_f(h1));
        u16 l2 = bf_hi(v.z - bf_f(h2)), l3 = bf_hi(v.w - bf_f(h3));
        size_t o = (size_t)r * SA + k;
        *(ull*)(sAh + o) = (ull)h0 | ((ull)h1 << 16) | ((ull)h2 << 32) | ((ull)h3 << 48);
        *(ull*)(sAl + o) = (ull)l0 | ((ull)l1 << 16) | ((ull)l2 << 32) | ((ull)l3 << 48);
    }
    __syncthreads();

    const u16* W1h = gW1T_hi + (size_t)l * HD * K1E;
    const u16* W1l = gW1T_lo + (size_t)l * HD * K1E;
    const u16* W2h = gW2T_hi + (size_t)l * ED * HD;
    const u16* W2l = gW2T_lo + (size_t)l * ED * HD;

    // ldmatrix bases
    u32 aH[2], aL[2];
    #pragma unroll
    for (int i = 0; i < 2; i++) {
        aH[i] = smem_u32(sAh) + (m0 + i * 16 + (lane & 15)) * SA * 2 + (lane >> 4) * 16;
        aL[i] = smem_u32(sAl) + (m0 + i * 16 + (lane & 15)) * SA * 2 + (lane >> 4) * 16;
    }
    const u32 bBase = smem_u32(dyn + OFF_R2)
                    + (ngrp * 32 + (lane & 7)) * SB * 2 + ((lane >> 3) & 1) * 16;
    const u32 hH = smem_u32(sHh) + (m0 + (lane & 15)) * SH * 2 + (lane >> 4) * 16;
    const u32 hL = smem_u32(sHl) + (m0 + (lane & 15)) * SH * 2 + (lane >> 4) * 16;
    const u32 wBase = smem_u32(sW2h)
                    + (ngrp * 16 + (lane & 7)) * SH * 2 + ((lane >> 3) & 1) * 16;

    u16* bufH[2] = { (u16*)(dyn + OFF_R2), (u16*)(dyn + OFF_R2 + BUFSZ) };
    u16* bufL[2] = { bufH[0] + 128 * SB, bufH[1] + 128 * SB };

    float acc2[2][2][4];
    #pragma unroll
    for (int i = 0; i < 2; i++)
        #pragma unroll
        for (int j = 0; j < 2; j++)
            #pragma unroll
            for (int q = 0; q < 4; q++) acc2[i][j][q] = 0.0f;

    const int nlin = tid >> 3, qlin = tid & 7;   // B slab store coords

    for (int nc = 0; nc < 4; nc++) {
        float acc1[2][4][4];
        #pragma unroll
        for (int i = 0; i < 2; i++)
            #pragma unroll
            for (int j = 0; j < 4; j++)
                #pragma unroll
                for (int q = 0; q < 4; q++) acc1[i][j][q] = 0.0f;

        uint4 ph[4], pl[4];
        #pragma unroll
        for (int j = 0; j < 4; j++) {
            int n = j * 32 + nlin;
            size_t go = (size_t)(nc * 128 + n) * K1E + qlin * 8;
            ph[j] = *(const uint4*)(W1h + go);
            pl[j] = *(const uint4*)(W1l + go);
        }
        #pragma unroll
        for (int j = 0; j < 4; j++) {
            int n = j * 32 + nlin;
            *(uint4*)(bufH[0] + n * SB + qlin * 8) = ph[j];
            *(uint4*)(bufL[0] + n * SB + qlin * 8) = pl[j];
        }
        __syncthreads();

        for (int kc = 0; kc < 9; kc++) {
            int cur = kc & 1;
            if (kc < 8) {
                #pragma unroll
                for (int j = 0; j < 4; j++) {
                    int n = j * 32 + nlin;
                    size_t go = (size_t)(nc * 128 + n) * K1E + (kc + 1) * 64 + qlin * 8;
                    ph[j] = *(const uint4*)(W1h + go);
                    pl[j] = *(const uint4*)(W1l + go);
                }
            }
            u32 curH = bBase + cur * BUFSZ;
            u32 curL = curH + 128 * SB * 2;
            #pragma unroll
            for (int ks = 0; ks < 4; ks++) {
                int kA = (kc * 64 + ks * 16) * 2;
                u32 ah[2][4], al[2][4];
                ldm_x4(ah[0], aH[0] + kA); ldm_x4(ah[1], aH[1] + kA);
                ldm_x4(al[0], aL[0] + kA); ldm_x4(al[1], aL[1] + kA);
                int kB = (ks * 16) * 2;
                #pragma unroll
                for (int j = 0; j < 4; j++) {
                    u32 bh0, bh1, bl0, bl1;
                    u32 off = j * (8 * SB * 2) + kB;
                    ldm_x2(bh0, bh1, curH + off);
                    ldm_x2(bl0, bl1, curL + off);
                    #pragma unroll
                    for (int i = 0; i < 2; i++) {
                        mma16816(acc1[i][j], ah[i], bh0, bh1);
                        mma16816(acc1[i][j], ah[i], bl0, bl1);
                        mma16816(acc1[i][j], al[i], bh0, bh1);
                    }
                }
            }
            if (kc < 8) {
                #pragma unroll
                for (int j = 0; j < 4; j++) {
                    int n = j * 32 + nlin;
                    *(uint4*)(bufH[cur ^ 1] + n * SB + qlin * 8) = ph[j];
                    *(uint4*)(bufL[cur ^ 1] + n * SB + qlin * 8) = pl[j];
                }
            }
            __syncthreads();
        }

        // silu + bias -> h (buf0 region)
        #pragma unroll
        for (int i = 0; i < 2; i++)
            #pragma unroll
            for (int j = 0; j < 4; j++) {
                int col = ngrp * 32 + j * 8 + 2 * t;
                int bc = nc * 128 + col;
                int r0 = m0 + i * 16 + g, r1 = r0 + 8;
                float v0 = silu_f(acc1[i][j][0] + s_b1[bc]);
                float v1 = silu_f(acc1[i][j][1] + s_b1[bc + 1]);
                float v2 = silu_f(acc1[i][j][2] + s_b1[bc]);
                float v3 = silu_f(acc1[i][j][3] + s_b1[bc + 1]);
                u16 h0 = bf_hi(v0), h1 = bf_hi(v1), h2 = bf_hi(v2), h3 = bf_hi(v3);
                *(u32*)(sHh + r0 * SH + col) = (u32)h0 | ((u32)h1 << 16);
                *(u32*)(sHh + r1 * SH + col) = (u32)h2 | ((u32)h3 << 16);
                u16 q0 = bf_hi(v0 - bf_f(h0)), q1 = bf_hi(v1 - bf_f(h1));
                u16 q2 = bf_hi(v2 - bf_f(h2)), q3 = bf_hi(v3 - bf_f(h3));
                *(u32*)(sHl + r0 * SH + col) = (u32)q0 | ((u32)q1 << 16);
                *(u32*)(sHl + r1 * SH + col) = (u32)q2 | ((u32)q3 << 16);
            }
        // W2 chunk [64][128] -> buf1 region
        #pragma unroll
        for (int j = 0; j < 4; j++) {
            int lin = j * 256 + tid;
            int n = lin >> 4, q = lin & 15;
            size_t go = (size_t)n * HD + nc * 128 + q * 8;
            *(uint4*)(sW2h + n * SH + q * 8) = *(const uint4*)(W2h + go);
            *(uint4*)(sW2l + n * SH + q * 8) = *(const uint4*)(W2l + go);
        }
        __syncthreads();

        // GEMM2: acc2 += h @ W2
        #pragma unroll
        for (int ks = 0; ks < 8; ks++) {
            int k0 = (ks * 16) * 2;
            u32 ah[2][4], al[2][4];
            ldm_x4(ah[0], hH + k0); ldm_x4(ah[1], hH + 16 * SH * 2 + k0);
            ldm_x4(al[0], hL + k0); ldm_x4(al[1], hL + 16 * SH * 2 + k0);
            #pragma unroll
            for (int j = 0; j < 2; j++) {
                u32 bh0, bh1, bl0, bl1;
                u32 off = j * (8 * SH * 2) + k0;
                ldm_x2(bh0, bh1, wBase + off);
                ldm_x2(bl0, bl1, wBase + 64 * SH * 2 + off);
                #pragma unroll
                for (int i = 0; i < 2; i++) {
                    mma16816(acc2[i][j], ah[i], bh0, bh1);
                    mma16816(acc2[i][j], ah[i], bl0, bl1);
                    mma16816(acc2[i][j], al[i], bh0, bh1);
                }
            }
        }
        __syncthreads();
    }

    // epilogue: bias -> sm_p (A overlay), LN(64), residual, scatter
    #pragma unroll
    for (int i = 0; i < 2; i++)
        #pragma unroll
        for (int j = 0; j < 2; j++) {
            int col = ngrp * 16 + j * 8 + 2 * t;
            int r0 = m0 + i * 16 + g, r1 = r0 + 8;
            sm_p[r0 * 68 + col]     = acc2[i][j][0] + s_b2[col];
            sm_p[r0 * 68 + col + 1] = acc2[i][j][1] + s_b2[col + 1];
            sm_p[r1 * 68 + col]     = acc2[i][j][2] + s_b2[col];
            sm_p[r1 * 68 + col + 1] = acc2[i][j][3] + s_b2[col + 1];
        }
    __syncthreads();
    {
        int r = tid >> 2, sub = tid & 3;
        float s = 0.f, s2 = 0.f;
        #pragma unroll
        for (int cc = 0; cc < 16; cc++) {
            float v = sm_p[r * 68 + sub * 16 + cc];
            s += v; s2 += v * v;
        }
        s  += __shfl_xor_sync(0xffffffffu, s, 1);
        s  += __shfl_xor_sync(0xffffffffu, s, 2);
        s2 += __shfl_xor_sync(0xffffffffu, s2, 1);
        s2 += __shfl_xor_sync(0xffffffffu, s2, 2);
        if (sub == 0) {
            float mu = s * (1.0f / 64.0f);
            s_mu[r] = mu;
            s_rs[r] = rsqrtf(s2 * (1.0f / 64.0f) - mu * mu + 1e-5f);
        }
    }
    __syncthreads();
    {
        int c = tid & 63, grp = tid >> 6;
        float gv = s_g[c], bv = s_bb[c];
        float* eo = g_e + (size_t)b * NEDGE * ED;
        float* ag = g_agg + (size_t)b * NNODE * ED;
        #pragma unroll 4
        for (int rr = 0; rr < 16; rr++) {
            int r = grp * 16 + rr;
            float p = sm_p[r * 68 + c];
            float en = eo[(size_t)(e0 + r) * ED + c]
                     + (p - s_mu[r]) * s_rs[r] * gv + bv;
            eo[(size_t)(e0 + r) * ED + c] = en;
            atomicAdd(ag + (size_t)s_dst[r] * ED + c, en);
        }
    }
}

// ===================== NODE KERNEL ===================================
#define NOFF_R2 83968                 /* 2 * 64*SA2*2 */
#define NOFF_H  (NOFF_R2 + 2 * BUFSZ) /* 157696 */
#define NODE_DSMEM (NOFF_H + 34816)   /* 192512 */

__global__ void __launch_bounds__(256, 1)
node_kernel_mma(float* __restrict__ x,
                const float* __restrict__ bn1, const float* __restrict__ bn2,
                const float* __restrict__ gnW, const float* __restrict__ blnW, int l)
{
    extern __shared__ char dyn[];
    u16* sAh = (u16*)(dyn);
    u16* sAl = sAh + 64 * SA2;
    u16* sW2h = (u16*)(dyn + NOFF_R2);            // GEMM2: W2 slab hi in buf0
    u16* sW2l = (u16*)(dyn + NOFF_R2 + BUFSZ);    //        lo in buf1
    u16* sHh = (u16*)(dyn + NOFF_H);
    u16* sHl = sHh + 64 * SH;
    float* sm_p = (float*)(dyn);                  // epilogue overlay [64][260]

    __shared__ float s_b1[512], s_b2[256], s_g[256], s_bb[256];
    __shared__ float s_mu[64], s_rs[64];

    const int tid = threadIdx.x;
    const int lane = tid & 31;
    const int w = tid >> 5;
    const int g = lane >> 2;
    const int t = lane & 3;
    const int mgrp = w & 1;
    const int ngrp = w >> 1;
    const int m0 = mgrp * 32;
    const int b = blockIdx.y;
    const int n0 = blockIdx.x * 64;

    for (int i = tid; i < 512; i += 256) s_b1[i] = bn1[l * HD + i];
    if (tid < 256) {
        s_b2[tid] = bn2[l * ND + tid];
        s_g[tid]  = gnW[l * ND + tid];
        s_bb[tid] = blnW[l * ND + tid];
    }

    const float* xb = x + (size_t)b * NNODE * ND;
    const float* ab = g_agg + (size_t)b * NNODE * ED;

    for (int i = tid; i < 64 * 80; i += 256) {
        int r = i / 80, q4 = i - r * 80;
        int k = q4 * 4;
        int node = min(n0 + r, NNODE - 1);
        float4 v = (k < 256) ? *(const float4*)(xb + (size_t)node * ND + k)
                             : *(const float4*)(ab + (size_t)node * ED + (k - 256));
        u16 h0 = bf_hi(v.x), h1 = bf_hi(v.y), h2 = bf_hi(v.z), h3 = bf_hi(v.w);
        u16 l0 = bf_hi(v.x - bf_f(h0)), l1 = bf_hi(v.y - bf_f(h1));
        u16 l2 = bf_hi(v.z - bf_f(h2)), l3 = bf_hi(v.w - bf_f(h3));
        size_t o = (size_t)r * SA2 + k;
        *(ull*)(sAh + o) = (ull)h0 | ((ull)h1 << 16) | ((ull)h2 << 32) | ((ull)h3 << 48);
        *(ull*)(sAl + o) = (ull)l0 | ((ull)l1 << 16) | ((ull)l2 << 32) | ((ull)l3 << 48);
    }
    __syncthreads();

    const u16* W1h = gWn1T_hi + (size_t)l * HD * K1N;
    const u16* W1l = gWn1T_lo + (size_t)l * HD * K1N;
    const u16* W2h = gWn2T_hi + (size_t)l * ND * HD;
    const u16* W2l = gWn2T_lo + (size_t)l * ND * HD;

    u32 aH[2], aL[2];
    #pragma unroll
    for (int i = 0; i < 2; i++) {
        aH[i] = smem_u32(sAh) + (m0 + i * 16 + (lane & 15)) * SA2 * 2 + (lane >> 4) * 16;
        aL[i] = smem_u32(sAl) + (m0 + i * 16 + (lane & 15)) * SA2 * 2 + (lane >> 4) * 16;
    }
    const u32 bBase = smem_u32(dyn + NOFF_R2)
                    + (ngrp * 32 + (lane & 7)) * SB * 2 + ((lane >> 3) & 1) * 16;
    const u32 hH = smem_u32(sHh) + (m0 + (lane & 15)) * SH * 2 + (lane >> 4) * 16;
    const u32 hL = smem_u32(sHl) + (m0 + (lane & 15)) * SH * 2 + (lane >> 4) * 16;
    const u32 wBase = smem_u32(sW2h)
                    + (ngrp * 64 + (lane & 7)) * SB * 2 + ((lane >> 3) & 1) * 16;
    const u32 wBaseL = wBase + BUFSZ;

    u16* bufH[2] = { (u16*)(dyn + NOFF_R2), (u16*)(dyn + NOFF_R2 + BUFSZ) };
    u16* bufL[2] = { bufH[0] + 128 * SB, bufH[1] + 128 * SB };

    float acc2[2][8][4];
    #pragma unroll
    for (int i = 0; i < 2; i++)
        #pragma unroll
        for (int j = 0; j < 8; j++)
            #pragma unroll
            for (int q = 0; q < 4; q++) acc2[i][j][q] = 0.0f;

    const int nlin = tid >> 3, qlin = tid & 7;

    for (int nc = 0; nc < 4; nc++) {
        float acc1[2][4][4];
        #pragma unroll
        for (int i = 0; i < 2; i++)
            #pragma unroll
            for (int j = 0; j < 4; j++)
                #pragma unroll
                for (int q = 0; q < 4; q++) acc1[i][j][q] = 0.0f;

        uint4 ph[4], pl[4];
        #pragma unroll
        for (int j = 0; j < 4; j++) {
            int n = j * 32 + nlin;
            size_t go = (size_t)(nc * 128 + n) * K1N + qlin * 8;
            ph[j] = *(const uint4*)(W1h + go);
            pl[j] = *(const uint4*)(W1l + go);
        }
        #pragma unroll
        for (int j = 0; j < 4; j++) {
            int n = j * 32 + nlin;
            *(uint4*)(bufH[0] + n * SB + qlin * 8) = ph[j];
            *(uint4*)(bufL[0] + n * SB + qlin * 8) = pl[j];
        }
        __syncthreads();

        for (int kc = 0; kc < 5; kc++) {
            int cur = kc & 1;
            if (kc < 4) {
                #pragma unroll
                for (int j = 0; j < 4; j++) {
                    int n = j * 32 + nlin;
                    size_t go = (size_t)(nc * 128 + n) * K1N + (kc + 1) * 64 + qlin * 8;
                    ph[j] = *(const uint4*)(W1h + go);
                    pl[j] = *(const uint4*)(W1l + go);
                }
            }
            u32 curH = bBase + cur * BUFSZ;
            u32 curL = curH + 128 * SB * 2;
            #pragma unroll
            for (int ks = 0; ks < 4; ks++) {
                int kA = (kc * 64 + ks * 16) * 2;
                u32 ah[2][4], al[2][4];
                ldm_x4(ah[0], aH[0] + kA); ldm_x4(ah[1], aH[1] + kA);
                ldm_x4(al[0], aL[0] + kA); ldm_x4(al[1], aL[1] + kA);
                int kB = (ks * 16) * 2;
                #pragma unroll
                for (int j = 0; j < 4; j++) {
                    u32 bh0, bh1, bl0, bl1;
                    u32 off = j * (8 * SB * 2) + kB;
                    ldm_x2(bh0, bh1, curH + off);
                    ldm_x2(bl0, bl1, curL + off);
                    #pragma unroll
                    for (int i = 0; i < 2; i++) {
                        mma16816(acc1[i][j], ah[i], bh0, bh1);
                        mma16816(acc1[i][j], ah[i], bl0, bl1);
                        mma16816(acc1[i][j], al[i], bh0, bh1);
                    }
                }
            }
            if (kc < 4) {
                #pragma unroll
                for (int j = 0; j < 4; j++) {
                    int n = j * 32 + nlin;
                    *(uint4*)(bufH[cur ^ 1] + n * SB + qlin * 8) = ph[j];
                    *(uint4*)(bufL[cur ^ 1] + n * SB + qlin * 8) = pl[j];
                }
            }
            __syncthreads();
        }

        // silu + bias -> h (separate region)
        #pragma unroll
        for (int i = 0; i < 2; i++)
            #pragma unroll
            for (int j = 0; j < 4; j++) {
                int col = ngrp * 32 + j * 8 + 2 * t;
                int bc = nc * 128 + col;
                int r0 = m0 + i * 16 + g, r1 = r0 + 8;
                float v0 = silu_f(acc1[i][j][0] + s_b1[bc]);
                float v1 = silu_f(acc1[i][j][1] + s_b1[bc + 1]);
                float v2 = silu_f(acc1[i][j][2] + s_b1[bc]);
                float v3 = silu_f(acc1[i][j][3] + s_b1[bc + 1]);
                u16 h0 = bf_hi(v0), h1 = bf_hi(v1), h2 = bf_hi(v2), h3 = bf_hi(v3);
                *(u32*)(sHh + r0 * SH + col) = (u32)h0 | ((u32)h1 << 16);
                *(u32*)(sHh + r1 * SH + col) = (u32)h2 | ((u32)h3 << 16);
                u16 q0 = bf_hi(v0 - bf_f(h0)), q1 = bf_hi(v1 - bf_f(h1));
                u16 q2 = bf_hi(v2 - bf_f(h2)), q3 = bf_hi(v3 - bf_f(h3));
                *(u32*)(sHl + r0 * SH + col) = (u32)q0 | ((u32)q1 << 16);
                *(u32*)(sHl + r1 * SH + col) = (u32)q2 | ((u32)q3 << 16);
            }
        __syncthreads();

        // GEMM2 over two 64-k slabs; W2 slab [256n][64k] hi->buf0, lo->buf1
        for (int s = 0; s < 2; s++) {
            for (int i = tid; i < 2048; i += 256) {
                int n = i >> 3, q = i & 7;
                size_t go = (size_t)n * HD + nc * 128 + s * 64 + q * 8;
                *(uint4*)(sW2h + n * SB + q * 8) = *(const uint4*)(W2h + go);
                *(uint4*)(sW2l + n * SB + q * 8) = *(const uint4*)(W2l + go);
            }
            __syncthreads();
            #pragma unroll
            for (int ks = 0; ks < 4; ks++) {
                int kH = (s * 64 + ks * 16) * 2;
                int kW = (ks * 16) * 2;
                u32 ah[2][4], al[2][4];
                ldm_x4(ah[0], hH + kH); ldm_x4(ah[1], hH + 16 * SH * 2 + kH);
                ldm_x4(al[0], hL + kH); ldm_x4(al[1], hL + 16 * SH * 2 + kH);
                #pragma unroll
                for (int j = 0; j < 8; j++) {
                    u32 bh0, bh1, bl0, bl1;
                    u32 off = j * (8 * SB * 2) + kW;
                    ldm_x2(bh0, bh1, wBase + off);
                    ldm_x2(bl0, bl1, wBaseL + off);
                    #pragma unroll
                    for (int i = 0; i < 2; i++) {
                        mma16816(acc2[i][j], ah[i], bh0, bh1);
                        mma16816(acc2[i][j], ah[i], bl0, bl1);
                        mma16816(acc2[i][j], al[i], bh0, bh1);
                    }
                }
            }
            __syncthreads();
        }
    }

    // epilogue: bias -> sm_p (A overlay), LN(256), residual, store
    #pragma unroll
    for (int i = 0; i < 2; i++)
        #pragma unroll
        for (int j = 0; j < 8; j++) {
            int col = ngrp * 64 + j * 8 + 2 * t;
            int r0 = m0 + i * 16 + g, r1 = r0 + 8;
            sm_p[r0 * 260 + col]     = acc2[i][j][0] + s_b2[col];
            sm_p[r0 * 260 + col + 1] = acc2[i][j][1] + s_b2[col + 1];
            sm_p[r1 * 260 + col]     = acc2[i][j][2] + s_b2[col];
            sm_p[r1 * 260 + col + 1] = acc2[i][j][3] + s_b2[col + 1];
        }
    __syncthreads();
    {
        int r = tid >> 2, sub = tid & 3;
        float s = 0.f, s2 = 0.f;
        #pragma unroll 8
        for (int cc = 0; cc < 64; cc++) {
            float v = sm_p[r * 260 + sub * 64 + cc];
            s += v; s2 += v * v;
        }
        s  += __shfl_xor_sync(0xffffffffu, s, 1);
        s  += __shfl_xor_sync(0xffffffffu, s, 2);
        s2 += __shfl_xor_sync(0xffffffffu, s2, 1);
        s2 += __shfl_xor_sync(0xffffffffu, s2, 2);
        if (sub == 0) {
            float mu = s * (1.0f / 256.0f);
            s_mu[r] = mu;
            s_rs[r] = rsqrtf(s2 * (1.0f / 256.0f) - mu * mu + 1e-5f);
        }
    }
    __syncthreads();
    {
        int c = tid;
        float gv = s_g[c], bv = s_bb[c];
        float* xo = x + (size_t)b * NNODE * ND;
        for (int rr = 0; rr < 64; rr++) {
            if (n0 + rr < NNODE) {
                float v = sm_p[rr * 260 + c];
                size_t o = (size_t)(n0 + rr) * ND + c;
                xo[o] = xo[o] + (v - s_mu[rr]) * s_rs[rr] * gv + bv;
            }
        }
    }
}

// ============================== LAUNCH ===============================
extern "C" void kernel_launch(void* const* d_in, const int* in_sizes, int n_in,
                              void* d_out, int out_size) {
    const float* nf  = (const float*)d_in[0];
    const float* ef  = (const float*)d_in[1];
    const float* We1 = (const float*)d_in[2];
    const float* be1 = (const float*)d_in[3];
    const float* We2 = (const float*)d_in[4];
    const float* be2 = (const float*)d_in[5];
    const float* geW = (const float*)d_in[6];
    const float* ble = (const float*)d_in[7];
    const float* Wn1 = (const float*)d_in[8];
    const float* bn1 = (const float*)d_in[9];
    const float* Wn2 = (const float*)d_in[10];
    const float* bn2 = (const float*)d_in[11];
    const float* gnW = (const float*)d_in[12];
    const float* bln = (const float*)d_in[13];
    const int*  eidx = (const int*)d_in[14];
    float* x = (float*)d_out;

    cudaFuncSetAttribute(edge_kernel_mma, cudaFuncAttributeMaxDynamicSharedMemorySize, EDGE_DSMEM);
    cudaFuncSetAttribute(node_kernel_mma, cudaFuncAttributeMaxDynamicSharedMemorySize, NODE_DSMEM);

    prep_w1<<<2048, 256>>>(We1);
    prep_w2<<<512, 256>>>(We2);
    prep_wn1<<<1024, 256>>>(Wn1);
    prep_wn2<<<1024, 256>>>(Wn2);

    cudaMemcpyAsync(x, nf, sizeof(float) * (size_t)NB * NNODE * ND,
                    cudaMemcpyDeviceToDevice, 0);
    size_t ebytes = sizeof(float) * (size_t)NEDGE * ED;
    cudaMemcpyToSymbolAsync(g_e, ef, ebytes, 0, cudaMemcpyDeviceToDevice, 0);
    cudaMemcpyToSymbolAsync(g_e, ef, ebytes, ebytes, cudaMemcpyDeviceToDevice, 0);

    dim3 eg(NEDGE / 64, NB);
    dim3 ng((NNODE + 63) / 64, NB);
    for (int l = 0; l < NL; l++) {
        zero_agg_kernel<<<512, 256>>>();
        edge_kernel_mma<<<eg, 256, EDGE_DSMEM>>>(x, eidx, be1, be2, geW, ble, l);
        node_kernel_mma<<<ng, 256, NODE_DSMEM>>>(x, bn1, bn2, gnW, bln, l);
    }
}

// round 12
// speedup vs baseline: 4.1989x; 1.3209x over previous
#include <cuda_runtime.h>
#include <cuda_fp16.h>
#include <cstdint>

#define NB 2
#define NNODE 40962
#define NEDGE 327680
#define ND 256
#define ED 64
#define HD 512
#define NL 16
#define K1E 576   /* ED + 2*ND */
#define K1N 320   /* ND + ED   */

typedef unsigned long long ull;
typedef unsigned int u32;
typedef unsigned short u16;

// ----------------------------- scratch ------------------------------
__device__ float g_e[(size_t)NB * NEDGE * ED];
__device__ float g_agg[(size_t)NB * NNODE * ED];
// fp16 transposed weights (hi only — B side of the 2-product split)
__device__ u16 gW1T[(size_t)NL * HD * K1E];
__device__ u16 gW2T[(size_t)NL * ED * HD];
__device__ u16 gWn1T[(size_t)NL * HD * K1N];
__device__ u16 gWn2T[(size_t)NL * ND * HD];

// --------------------------- helpers --------------------------------
__device__ __forceinline__ u16 hf(float v) {
    return __half_as_ushort(__float2half_rn(v));
}
__device__ __forceinline__ float hf_f(u16 h) {
    return __half2float(__ushort_as_half(h));
}
__device__ __forceinline__ float silu_f(float v) {
    return __fdividef(v, 1.0f + __expf(-v));
}
__device__ __forceinline__ u32 smem_u32(const void* p) {
    u32 a; asm("{ .reg .u64 t; cvta.to.shared.u64 t, %1; cvt.u32.u64 %0, t; }"
               : "=r"(a) : "l"(p));
    return a;
}
__device__ __forceinline__ void mma16816(float* d, const u32* a, u32 b0, u32 b1) {
    asm volatile(
        "mma.sync.aligned.m16n8k16.row.col.f32.f16.f16.f32 "
        "{%0,%1,%2,%3}, {%4,%5,%6,%7}, {%8,%9}, {%0,%1,%2,%3};"
        : "+f"(d[0]), "+f"(d[1]), "+f"(d[2]), "+f"(d[3])
        : "r"(a[0]), "r"(a[1]), "r"(a[2]), "r"(a[3]), "r"(b0), "r"(b1));
}
__device__ __forceinline__ void ldm_x4(u32* r, u32 a) {
    asm volatile("ldmatrix.sync.aligned.m8n8.x4.shared.b16 {%0,%1,%2,%3}, [%4];"
        : "=r"(r[0]), "=r"(r[1]), "=r"(r[2]), "=r"(r[3]) : "r"(a));
}
__device__ __forceinline__ void ldm_x2(u32& r0, u32& r1, u32 a) {
    asm volatile("ldmatrix.sync.aligned.m8n8.x2.shared.b16 {%0,%1}, [%2];"
        : "=r"(r0), "=r"(r1) : "r"(a));
}

// --------------------------- prep kernels ---------------------------
__global__ void prep_w1(const float* __restrict__ W) {
    size_t tot = (size_t)NL * K1E * HD;
    for (size_t i = (size_t)blockIdx.x * blockDim.x + threadIdx.x; i < tot;
         i += (size_t)gridDim.x * blockDim.x) {
        size_t l = i / ((size_t)K1E * HD);
        size_t rem = i - l * (size_t)K1E * HD;
        size_t k = rem / HD, n = rem - k * HD;
        gW1T[(l * HD + n) * K1E + k] = hf(W[i]);
    }
}
__global__ void prep_w2(const float* __restrict__ W) {
    size_t tot = (size_t)NL * HD * ED;
    for (size_t i = (size_t)blockIdx.x * blockDim.x + threadIdx.x; i < tot;
         i += (size_t)gridDim.x * blockDim.x) {
        size_t l = i / ((size_t)HD * ED);
        size_t rem = i - l * (size_t)HD * ED;
        size_t k = rem / ED, n = rem - k * ED;
        gW2T[(l * ED + n) * HD + k] = hf(W[i]);
    }
}
__global__ void prep_wn1(const float* __restrict__ W) {
    size_t tot = (size_t)NL * K1N * HD;
    for (size_t i = (size_t)blockIdx.x * blockDim.x + threadIdx.x; i < tot;
         i += (size_t)gridDim.x * blockDim.x) {
        size_t l = i / ((size_t)K1N * HD);
        size_t rem = i - l * (size_t)K1N * HD;
        size_t k = rem / HD, n = rem - k * HD;
        gWn1T[(l * HD + n) * K1N + k] = hf(W[i]);
    }
}
__global__ void prep_wn2(const float* __restrict__ W) {
    size_t tot = (size_t)NL * HD * ND;
    for (size_t i = (size_t)blockIdx.x * blockDim.x + threadIdx.x; i < tot;
         i += (size_t)gridDim.x * blockDim.x) {
        size_t l = i / ((size_t)HD * ND);
        size_t rem = i - l * (size_t)HD * ND;
        size_t k = rem / ND, n = rem - k * ND;
        gWn2T[(l * ND + n) * HD + k] = hf(W[i]);
    }
}

__global__ void zero_agg_kernel() {
    size_t n = (size_t)NB * NNODE * ED;
    for (size_t i = (size_t)blockIdx.x * blockDim.x + threadIdx.x; i < n;
         i += (size_t)gridDim.x * blockDim.x)
        g_agg[i] = 0.0f;
}

// strides (u16 units)
#define SA 584    /* edge A row stride */
#define SA2 328   /* node A row stride */
#define SB 72     /* B slab row stride */
#define SH 136    /* h / edge-W2 row stride */
#define BUFSZ 18432           /* one B buffer: hi only, 128 x SB x 2B */

// ===================== EDGE KERNEL ===================================
#define OFF_R2 149504                 /* 2 * 64*SA*2 (A hi+lo) */
#define OFF_W2E (OFF_R2 + 2 * BUFSZ)  /* 186368 */
#define EDGE_DSMEM (OFF_W2E + 17408)  /* 203776 */

__global__ void __launch_bounds__(256, 1)
edge_kernel_mma(const float* __restrict__ x, const int* __restrict__ eidx,
                const float* __restrict__ be1, const float* __restrict__ be2,
                const float* __restrict__ geW, const float* __restrict__ bleW, int l)
{
    extern __shared__ char dyn[];
    u16* sAh = (u16*)(dyn);
    u16* sAl = sAh + 64 * SA;
    // B double buffers at OFF_R2 (+cur*BUFSZ)
    // GEMM2 overlay: H hi/lo spans the two B buffers; W2 hi separate
    u16* sHh = (u16*)(dyn + OFF_R2);
    u16* sHl = sHh + 64 * SH;
    u16* sW2 = (u16*)(dyn + OFF_W2E);
    float* sm_p = (float*)(dyn);      // epilogue overlay in A region

    __shared__ int s_src[64], s_dst[64];
    __shared__ float s_b1[512], s_b2[64], s_g[64], s_bb[64];
    __shared__ float s_mu[64], s_rs[64];

    const int tid = threadIdx.x;
    const int lane = tid & 31;
    const int w = tid >> 5;
    const int g = lane >> 2;
    const int t = lane & 3;
    const int mgrp = w & 1;
    const int ngrp = w >> 1;          // 0..3
    const int m0 = mgrp * 32;
    const int b = blockIdx.y;
    const int e0 = blockIdx.x * 64;

    if (tid < 64) {
        s_src[tid] = eidx[e0 + tid];
        s_dst[tid] = eidx[NEDGE + e0 + tid];
    }
    for (int i = tid; i < 512; i += 256) s_b1[i] = be1[l * HD + i];
    if (tid < 64) {
        s_b2[tid] = be2[l * ED + tid];
        s_g[tid]  = geW[l * ED + tid];
        s_bb[tid] = bleW[l * ED + tid];
    }
    __syncthreads();

    const float* xb = x + (size_t)b * NNODE * ND;
    const float* eb = g_e + (size_t)b * NEDGE * ED;

    // gather + fp16 split-convert A[64][576]
    for (int i = tid; i < 64 * 144; i += 256) {
        int r = i / 144, q4 = i - r * 144;
        int k = q4 * 4;
        float4 v;
        if (k < 64)       v = *(const float4*)(eb + (size_t)(e0 + r) * ED + k);
        else if (k < 320) v = *(const float4*)(xb + (size_t)s_src[r] * ND + (k - 64));
        else              v = *(const float4*)(xb + (size_t)s_dst[r] * ND + (k - 320));
        u16 h0 = hf(v.x), h1 = hf(v.y), h2 = hf(v.z), h3 = hf(v.w);
        u16 l0 = hf(v.x - hf_f(h0)), l1 = hf(v.y - hf_f(h1));
        u16 l2 = hf(v.z - hf_f(h2)), l3 = hf(v.w - hf_f(h3));
        size_t o = (size_t)r * SA + k;
        *(ull*)(sAh + o) = (ull)h0 | ((ull)h1 << 16) | ((ull)h2 << 32) | ((ull)h3 << 48);
        *(ull*)(sAl + o) = (ull)l0 | ((ull)l1 << 16) | ((ull)l2 << 32) | ((ull)l3 << 48);
    }
    __syncthreads();

    const u16* W1 = gW1T + (size_t)l * HD * K1E;
    const u16* W2 = gW2T + (size_t)l * ED * HD;

    // ldmatrix bases
    u32 aH[2], aL[2];
    #pragma unroll
    for (int i = 0; i < 2; i++) {
        aH[i] = smem_u32(sAh) + (m0 + i * 16 + (lane & 15)) * SA * 2 + (lane >> 4) * 16;
        aL[i] = smem_u32(sAl) + (m0 + i * 16 + (lane & 15)) * SA * 2 + (lane >> 4) * 16;
    }
    const u32 bBase = smem_u32(dyn + OFF_R2)
                    + (ngrp * 32 + (lane & 7)) * SB * 2 + ((lane >> 3) & 1) * 16;
    const u32 hH = smem_u32(sHh) + (m0 + (lane & 15)) * SH * 2 + (lane >> 4) * 16;
    const u32 hL = smem_u32(sHl) + (m0 + (lane & 15)) * SH * 2 + (lane >> 4) * 16;
    const u32 wBase = smem_u32(sW2)
                    + (ngrp * 16 + (lane & 7)) * SH * 2 + ((lane >> 3) & 1) * 16;

    u16* bufB[2] = { (u16*)(dyn + OFF_R2), (u16*)(dyn + OFF_R2 + BUFSZ) };

    float acc2[2][2][4];
    #pragma unroll
    for (int i = 0; i < 2; i++)
        #pragma unroll
        for (int j = 0; j < 2; j++)
            #pragma unroll
            for (int q = 0; q < 4; q++) acc2[i][j][q] = 0.0f;

    const int nlin = tid >> 3, qlin = tid & 7;   // B slab store coords

    for (int nc = 0; nc < 4; nc++) {
        float acc1[2][4][4];
        #pragma unroll
        for (int i = 0; i < 2; i++)
            #pragma unroll
            for (int j = 0; j < 4; j++)
                #pragma unroll
                for (int q = 0; q < 4; q++) acc1[i][j][q] = 0.0f;

        uint4 ph[4];
        #pragma unroll
        for (int j = 0; j < 4; j++) {
            int n = j * 32 + nlin;
            ph[j] = *(const uint4*)(W1 + (size_t)(nc * 128 + n) * K1E + qlin * 8);
        }
        #pragma unroll
        for (int j = 0; j < 4; j++) {
            int n = j * 32 + nlin;
            *(uint4*)(bufB[0] + n * SB + qlin * 8) = ph[j];
        }
        __syncthreads();

        for (int kc = 0; kc < 9; kc++) {
            int cur = kc & 1;
            if (kc < 8) {
                #pragma unroll
                for (int j = 0; j < 4; j++) {
                    int n = j * 32 + nlin;
                    ph[j] = *(const uint4*)(W1 + (size_t)(nc * 128 + n) * K1E
                                            + (kc + 1) * 64 + qlin * 8);
                }
            }
            u32 curB = bBase + cur * BUFSZ;
            #pragma unroll
            for (int ks = 0; ks < 4; ks++) {
                int kA = (kc * 64 + ks * 16) * 2;
                u32 ah[2][4], al[2][4];
                ldm_x4(ah[0], aH[0] + kA); ldm_x4(ah[1], aH[1] + kA);
                ldm_x4(al[0], aL[0] + kA); ldm_x4(al[1], aL[1] + kA);
                int kB = (ks * 16) * 2;
                #pragma unroll
                for (int j = 0; j < 4; j++) {
                    u32 bh0, bh1;
                    ldm_x2(bh0, bh1, curB + j * (8 * SB * 2) + kB);
                    #pragma unroll
                    for (int i = 0; i < 2; i++) {
                        mma16816(acc1[i][j], ah[i], bh0, bh1);
                        mma16816(acc1[i][j], al[i], bh0, bh1);
                    }
                }
            }
            if (kc < 8) {
                #pragma unroll
                for (int j = 0; j < 4; j++) {
                    int n = j * 32 + nlin;
                    *(uint4*)(bufB[cur ^ 1] + n * SB + qlin * 8) = ph[j];
                }
            }
            __syncthreads();
        }

        // silu + bias -> h (fp16 hi/lo) into B-buffer region
        #pragma unroll
        for (int i = 0; i < 2; i++)
            #pragma unroll
            for (int j = 0; j < 4; j++) {
                int col = ngrp * 32 + j * 8 + 2 * t;
                int bc = nc * 128 + col;
                int r0 = m0 + i * 16 + g, r1 = r0 + 8;
                float v0 = silu_f(acc1[i][j][0] + s_b1[bc]);
                float v1 = silu_f(acc1[i][j][1] + s_b1[bc + 1]);
                float v2 = silu_f(acc1[i][j][2] + s_b1[bc]);
                float v3 = silu_f(acc1[i][j][3] + s_b1[bc + 1]);
                u16 h0 = hf(v0), h1 = hf(v1), h2 = hf(v2), h3 = hf(v3);
                *(u32*)(sHh + r0 * SH + col) = (u32)h0 | ((u32)h1 << 16);
                *(u32*)(sHh + r1 * SH + col) = (u32)h2 | ((u32)h3 << 16);
                u16 q0 = hf(v0 - hf_f(h0)), q1 = hf(v1 - hf_f(h1));
                u16 q2 = hf(v2 - hf_f(h2)), q3 = hf(v3 - hf_f(h3));
                *(u32*)(sHl + r0 * SH + col) = (u32)q0 | ((u32)q1 << 16);
                *(u32*)(sHl + r1 * SH + col) = (u32)q2 | ((u32)q3 << 16);
            }
        // W2 chunk [64 n][128 k] hi -> its region  (1024 uint4: j < 4 — R11's bug was j < 2)
        #pragma unroll
        for (int j = 0; j < 4; j++) {
            int lin = j * 256 + tid;
            int n = lin >> 4, q = lin & 15;
            *(uint4*)(sW2 + n * SH + q * 8) =
                *(const uint4*)(W2 + (size_t)n * HD + nc * 128 + q * 8);
        }
        __syncthreads();

        // GEMM2: acc2 += (Hh + Hl) @ W2
        #pragma unroll
        for (int ks = 0; ks < 8; ks++) {
            int k0 = (ks * 16) * 2;
            u32 ah[2][4], al[2][4];
            ldm_x4(ah[0], hH + k0); ldm_x4(ah[1], hH + 16 * SH * 2 + k0);
            ldm_x4(al[0], hL + k0); ldm_x4(al[1], hL + 16 * SH * 2 + k0);
            #pragma unroll
            for (int j = 0; j < 2; j++) {
                u32 bh0, bh1;
                ldm_x2(bh0, bh1, wBase + j * (8 * SH * 2) + k0);
                #pragma unroll
                for (int i = 0; i < 2; i++) {
                    mma16816(acc2[i][j], ah[i], bh0, bh1);
                    mma16816(acc2[i][j], al[i], bh0, bh1);
                }
            }
        }
        __syncthreads();
    }

    // epilogue: bias -> sm_p (A overlay), LN(64), residual, scatter
    #pragma unroll
    for (int i = 0; i < 2; i++)
        #pragma unroll
        for (int j = 0; j < 2; j++) {
            int col = ngrp * 16 + j * 8 + 2 * t;
            int r0 = m0 + i * 16 + g, r1 = r0 + 8;
            sm_p[r0 * 68 + col]     = acc2[i][j][0] + s_b2[col];
            sm_p[r0 * 68 + col + 1] = acc2[i][j][1] + s_b2[col + 1];
            sm_p[r1 * 68 + col]     = acc2[i][j][2] + s_b2[col];
            sm_p[r1 * 68 + col + 1] = acc2[i][j][3] + s_b2[col + 1];
        }
    __syncthreads();
    {
        int r = tid >> 2, sub = tid & 3;
        float s = 0.f, s2 = 0.f;
        #pragma unroll
        for (int cc = 0; cc < 16; cc++) {
            float v = sm_p[r * 68 + sub * 16 + cc];
            s += v; s2 += v * v;
        }
        s  += __shfl_xor_sync(0xffffffffu, s, 1);
        s  += __shfl_xor_sync(0xffffffffu, s, 2);
        s2 += __shfl_xor_sync(0xffffffffu, s2, 1);
        s2 += __shfl_xor_sync(0xffffffffu, s2, 2);
        if (sub == 0) {
            float mu = s * (1.0f / 64.0f);
            s_mu[r] = mu;
            s_rs[r] = rsqrtf(s2 * (1.0f / 64.0f) - mu * mu + 1e-5f);
        }
    }
    __syncthreads();
    {
        int c = tid & 63, grp = tid >> 6;
        float gv = s_g[c], bv = s_bb[c];
        float* eo = g_e + (size_t)b * NEDGE * ED;
        float* ag = g_agg + (size_t)b * NNODE * ED;
        #pragma unroll 4
        for (int rr = 0; rr < 16; rr++) {
            int r = grp * 16 + rr;
            float p = sm_p[r * 68 + c];
            float en = eo[(size_t)(e0 + r) * ED + c]
                     + (p - s_mu[r]) * s_rs[r] * gv + bv;
            eo[(size_t)(e0 + r) * ED + c] = en;
            atomicAdd(ag + (size_t)s_dst[r] * ED + c, en);
        }
    }
}

// ===================== NODE KERNEL ===================================
#define NOFF_R2 83968                 /* 2 * 64*SA2*2 */
#define NOFF_H  (NOFF_R2 + 2 * BUFSZ) /* 120832 */
#define NODE_DSMEM (NOFF_H + 34816)   /* 155648 */

__global__ void __launch_bounds__(256, 1)
node_kernel_mma(float* __restrict__ x,
                const float* __restrict__ bn1, const float* __restrict__ bn2,
                const float* __restrict__ gnW, const float* __restrict__ blnW, int l)
{
    extern __shared__ char dyn[];
    u16* sAh = (u16*)(dyn);
    u16* sAl = sAh + 64 * SA2;
    u16* sW2 = (u16*)(dyn + NOFF_R2);   // GEMM2 W2 slab spans both B buffers
    u16* sHh = (u16*)(dyn + NOFF_H);
    u16* sHl = sHh + 64 * SH;
    float* sm_p = (float*)(dyn);        // epilogue overlay [64][260]

    __shared__ float s_b1[512], s_b2[256], s_g[256], s_bb[256];
    __shared__ float s_mu[64], s_rs[64];

    const int tid = threadIdx.x;
    const int lane = tid & 31;
    const int w = tid >> 5;
    const int g = lane >> 2;
    const int t = lane & 3;
    const int mgrp = w & 1;
    const int ngrp = w >> 1;
    const int m0 = mgrp * 32;
    const int b = blockIdx.y;
    const int n0 = blockIdx.x * 64;

    for (int i = tid; i < 512; i += 256) s_b1[i] = bn1[l * HD + i];
    if (tid < 256) {
        s_b2[tid] = bn2[l * ND + tid];
        s_g[tid]  = gnW[l * ND + tid];
        s_bb[tid] = blnW[l * ND + tid];
    }

    const float* xb = x + (size_t)b * NNODE * ND;
    const float* ab = g_agg + (size_t)b * NNODE * ED;

    for (int i = tid; i < 64 * 80; i += 256) {
        int r = i / 80, q4 = i - r * 80;
        int k = q4 * 4;
        int node = min(n0 + r, NNODE - 1);
        float4 v = (k < 256) ? *(const float4*)(xb + (size_t)node * ND + k)
                             : *(const float4*)(ab + (size_t)node * ED + (k - 256));
        u16 h0 = hf(v.x), h1 = hf(v.y), h2 = hf(v.z), h3 = hf(v.w);
        u16 l0 = hf(v.x - hf_f(h0)), l1 = hf(v.y - hf_f(h1));
        u16 l2 = hf(v.z - hf_f(h2)), l3 = hf(v.w - hf_f(h3));
        size_t o = (size_t)r * SA2 + k;
        *(ull*)(sAh + o) = (ull)h0 | ((ull)h1 << 16) | ((ull)h2 << 32) | ((ull)h3 << 48);
        *(ull*)(sAl + o) = (ull)l0 | ((ull)l1 << 16) | ((ull)l2 << 32) | ((ull)l3 << 48);
    }
    __syncthreads();

    const u16* W1 = gWn1T + (size_t)l * HD * K1N;
    const u16* W2 = gWn2T + (size_t)l * ND * HD;

    u32 aH[2], aL[2];
    #pragma unroll
    for (int i = 0; i < 2; i++) {
        aH[i] = smem_u32(sAh) + (m0 + i * 16 + (lane & 15)) * SA2 * 2 + (lane >> 4) * 16;
        aL[i] = smem_u32(sAl) + (m0 + i * 16 + (lane & 15)) * SA2 * 2 + (lane >> 4) * 16;
    }
    const u32 bBase = smem_u32(dyn + NOFF_R2)
                    + (ngrp * 32 + (lane & 7)) * SB * 2 + ((lane >> 3) & 1) * 16;
    const u32 hH = smem_u32(sHh) + (m0 + (lane & 15)) * SH * 2 + (lane >> 4) * 16;
    const u32 hL = smem_u32(sHl) + (m0 + (lane & 15)) * SH * 2 + (lane >> 4) * 16;
    const u32 wBase = smem_u32(sW2)
                    + (ngrp * 64 + (lane & 7)) * SB * 2 + ((lane >> 3) & 1) * 16;

    u16* bufB[2] = { (u16*)(dyn + NOFF_R2), (u16*)(dyn + NOFF_R2 + BUFSZ) };

    float acc2[2][8][4];
    #pragma unroll
    for (int i = 0; i < 2; i++)
        #pragma unroll
        for (int j = 0; j < 8; j++)
            #pragma unroll
            for (int q = 0; q < 4; q++) acc2[i][j][q] = 0.0f;

    const int nlin = tid >> 3, qlin = tid & 7;

    for (int nc = 0; nc < 4; nc++) {
        float acc1[2][4][4];
        #pragma unroll
        for (int i = 0; i < 2; i++)
            #pragma unroll
            for (int j = 0; j < 4; j++)
                #pragma unroll
                for (int q = 0; q < 4; q++) acc1[i][j][q] = 0.0f;

        uint4 ph[4];
        #pragma unroll
        for (int j = 0; j < 4; j++) {
            int n = j * 32 + nlin;
            ph[j] = *(const uint4*)(W1 + (size_t)(nc * 128 + n) * K1N + qlin * 8);
        }
        #pragma unroll
        for (int j = 0; j < 4; j++) {
            int n = j * 32 + nlin;
            *(uint4*)(bufB[0] + n * SB + qlin * 8) = ph[j];
        }
        __syncthreads();

        for (int kc = 0; kc < 5; kc++) {
            int cur = kc & 1;
            if (kc < 4) {
                #pragma unroll
                for (int j = 0; j < 4; j++) {
                    int n = j * 32 + nlin;
                    ph[j] = *(const uint4*)(W1 + (size_t)(nc * 128 + n) * K1N
                                            + (kc + 1) * 64 + qlin * 8);
                }
            }
            u32 curB = bBase + cur * BUFSZ;
            #pragma unroll
            for (int ks = 0; ks < 4; ks++) {
                int kA = (kc * 64 + ks * 16) * 2;
                u32 ah[2][4], al[2][4];
                ldm_x4(ah[0], aH[0] + kA); ldm_x4(ah[1], aH[1] + kA);
                ldm_x4(al[0], aL[0] + kA); ldm_x4(al[1], aL[1] + kA);
                int kB = (ks * 16) * 2;
                #pragma unroll
                for (int j = 0; j < 4; j++) {
                    u32 bh0, bh1;
                    ldm_x2(bh0, bh1, curB + j * (8 * SB * 2) + kB);
                    #pragma unroll
                    for (int i = 0; i < 2; i++) {
                        mma16816(acc1[i][j], ah[i], bh0, bh1);
                        mma16816(acc1[i][j], al[i], bh0, bh1);
                    }
                }
            }
            if (kc < 4) {
                #pragma unroll
                for (int j = 0; j < 4; j++) {
                    int n = j * 32 + nlin;
                    *(uint4*)(bufB[cur ^ 1] + n * SB + qlin * 8) = ph[j];
                }
            }
            __syncthreads();
        }

        // silu + bias -> h (fp16 hi/lo, separate region)
        #pragma unroll
        for (int i = 0; i < 2; i++)
            #pragma unroll
            for (int j = 0; j < 4; j++) {
                int col = ngrp * 32 + j * 8 + 2 * t;
                int bc = nc * 128 + col;
                int r0 = m0 + i * 16 + g, r1 = r0 + 8;
                float v0 = silu_f(acc1[i][j][0] + s_b1[bc]);
                float v1 = silu_f(acc1[i][j][1] + s_b1[bc + 1]);
                float v2 = silu_f(acc1[i][j][2] + s_b1[bc]);
                float v3 = silu_f(acc1[i][j][3] + s_b1[bc + 1]);
                u16 h0 = hf(v0), h1 = hf(v1), h2 = hf(v2), h3 = hf(v3);
                *(u32*)(sHh + r0 * SH + col) = (u32)h0 | ((u32)h1 << 16);
                *(u32*)(sHh + r1 * SH + col) = (u32)h2 | ((u32)h3 << 16);
                u16 q0 = hf(v0 - hf_f(h0)), q1 = hf(v1 - hf_f(h1));
                u16 q2 = hf(v2 - hf_f(h2)), q3 = hf(v3 - hf_f(h3));
                *(u32*)(sHl + r0 * SH + col) = (u32)q0 | ((u32)q1 << 16);
                *(u32*)(sHl + r1 * SH + col) = (u32)q2 | ((u32)q3 << 16);
            }
        __syncthreads();

        // GEMM2 over two 64-k slabs; W2 slab [256n][64k] hi only
        for (int s = 0; s < 2; s++) {
            for (int i = tid; i < 2048; i += 256) {
                int n = i >> 3, q = i & 7;
                *(uint4*)(sW2 + n * SB + q * 8) =
                    *(const uint4*)(W2 + (size_t)n * HD + nc * 128 + s * 64 + q * 8);
            }
            __syncthreads();
            #pragma unroll
            for (int ks = 0; ks < 4; ks++) {
                int kH = (s * 64 + ks * 16) * 2;
                int kW = (ks * 16) * 2;
                u32 ah[2][4], al[2][4];
                ldm_x4(ah[0], hH + kH); ldm_x4(ah[1], hH + 16 * SH * 2 + kH);
                ldm_x4(al[0], hL + kH); ldm_x4(al[1], hL + 16 * SH * 2 + kH);
                #pragma unroll
                for (int j = 0; j < 8; j++) {
                    u32 bh0, bh1;
                    ldm_x2(bh0, bh1, wBase + j * (8 * SB * 2) + kW);
                    #pragma unroll
                    for (int i = 0; i < 2; i++) {
                        mma16816(acc2[i][j], ah[i], bh0, bh1);
                        mma16816(acc2[i][j], al[i], bh0, bh1);
                    }
                }
            }
            __syncthreads();
        }
    }

    // epilogue: bias -> sm_p (A overlay), LN(256), residual, store
    #pragma unroll
    for (int i = 0; i < 2; i++)
        #pragma unroll
        for (int j = 0; j < 8; j++) {
            int col = ngrp * 64 + j * 8 + 2 * t;
            int r0 = m0 + i * 16 + g, r1 = r0 + 8;
            sm_p[r0 * 260 + col]     = acc2[i][j][0] + s_b2[col];
            sm_p[r0 * 260 + col + 1] = acc2[i][j][1] + s_b2[col + 1];
            sm_p[r1 * 260 + col]     = acc2[i][j][2] + s_b2[col];
            sm_p[r1 * 260 + col + 1] = acc2[i][j][3] + s_b2[col + 1];
        }
    __syncthreads();
    {
        int r = tid >> 2, sub = tid & 3;
        float s = 0.f, s2 = 0.f;
        #pragma unroll 8
        for (int cc = 0; cc < 64; cc++) {
            float v = sm_p[r * 260 + sub * 64 + cc];
            s += v; s2 += v * v;
        }
        s  += __shfl_xor_sync(0xffffffffu, s, 1);
        s  += __shfl_xor_sync(0xffffffffu, s, 2);
        s2 += __shfl_xor_sync(0xffffffffu, s2, 1);
        s2 += __shfl_xor_sync(0xffffffffu, s2, 2);
        if (sub == 0) {
            float mu = s * (1.0f / 256.0f);
            s_mu[r] = mu;
            s_rs[r] = rsqrtf(s2 * (1.0f / 256.0f) - mu * mu + 1e-5f);
        }
    }
    __syncthreads();
    {
        int c = tid;
        float gv = s_g[c], bv = s_bb[c];
        float* xo = x + (size_t)b * NNODE * ND;
        for (int rr = 0; rr < 64; rr++) {
            if (n0 + rr < NNODE) {
                float v = sm_p[rr * 260 + c];
                size_t o = (size_t)(n0 + rr) * ND + c;
                xo[o] = xo[o] + (v - s_mu[rr]) * s_rs[rr] * gv + bv;
            }
        }
    }
}

// ============================== LAUNCH ===============================
extern "C" void kernel_launch(void* const* d_in, const int* in_sizes, int n_in,
                              void* d_out, int out_size) {
    const float* nf  = (const float*)d_in[0];
    const float* ef  = (const float*)d_in[1];
    const float* We1 = (const float*)d_in[2];
    const float* be1 = (const float*)d_in[3];
    const float* We2 = (const float*)d_in[4];
    const float* be2 = (const float*)d_in[5];
    const float* geW = (const float*)d_in[6];
    const float* ble = (const float*)d_in[7];
    const float* Wn1 = (const float*)d_in[8];
    const float* bn1 = (const float*)d_in[9];
    const float* Wn2 = (const float*)d_in[10];
    const float* bn2 = (const float*)d_in[11];
    const float* gnW = (const float*)d_in[12];
    const float* bln = (const float*)d_in[13];
    const int*  eidx = (const int*)d_in[14];
    float* x = (float*)d_out;

    cudaFuncSetAttribute(edge_kernel_mma, cudaFuncAttributeMaxDynamicSharedMemorySize, EDGE_DSMEM);
    cudaFuncSetAttribute(node_kernel_mma, cudaFuncAttributeMaxDynamicSharedMemorySize, NODE_DSMEM);

    prep_w1<<<2048, 256>>>(We1);
    prep_w2<<<512, 256>>>(We2);
    prep_wn1<<<1024, 256>>>(Wn1);
    prep_wn2<<<1024, 256>>>(Wn2);

    cudaMemcpyAsync(x, nf, sizeof(float) * (size_t)NB * NNODE * ND,
                    cudaMemcpyDeviceToDevice, 0);
    size_t ebytes = sizeof(float) * (size_t)NEDGE * ED;
    cudaMemcpyToSymbolAsync(g_e, ef, ebytes, 0, cudaMemcpyDeviceToDevice, 0);
    cudaMemcpyToSymbolAsync(g_e, ef, ebytes, ebytes, cudaMemcpyDeviceToDevice, 0);

    dim3 eg(NEDGE / 64, NB);
    dim3 ng((NNODE + 63) / 64, NB);
    for (int l = 0; l < NL; l++) {
        zero_agg_kernel<<<512, 256>>>();
        edge_kernel_mma<<<eg, 256, EDGE_DSMEM>>>(x, eidx, be1, be2, geW, ble, l);
        node_kernel_mma<<<ng, 256, NODE_DSMEM>>>(x, bn1, bn2, gnW, bln, l);
    }
}

// round 13
// speedup vs baseline: 4.5009x; 1.0719x over previous
#include <cuda_runtime.h>
#include <cuda_fp16.h>
#include <cstdint>

#define NB 2
#define NNODE 40962
#define NEDGE 327680
#define ND 256
#define ED 64
#define HD 512
#define NL 16
#define K1E 576   /* ED + 2*ND */
#define K1N 320   /* ND + ED   */

typedef unsigned long long ull;
typedef unsigned int u32;
typedef unsigned short u16;

// ----------------------------- scratch ------------------------------
__device__ float g_e[(size_t)NB * NEDGE * ED];
__device__ float g_agg[(size_t)NB * NNODE * ED];
__device__ u16 gW1T[(size_t)NL * HD * K1E];
__device__ u16 gW2T[(size_t)NL * ED * HD];
__device__ u16 gWn1T[(size_t)NL * HD * K1N];
__device__ u16 gWn2T[(size_t)NL * ND * HD];

// --------------------------- helpers --------------------------------
__device__ __forceinline__ u16 hf(float v) {
    return __half_as_ushort(__float2half_rn(v));
}
__device__ __forceinline__ float hf_f(u16 h) {
    return __half2float(__ushort_as_half(h));
}
__device__ __forceinline__ float silu_f(float v) {
    return __fdividef(v, 1.0f + __expf(-v));
}
__device__ __forceinline__ u32 smem_u32(const void* p) {
    u32 a; asm("{ .reg .u64 t; cvta.to.shared.u64 t, %1; cvt.u32.u64 %0, t; }"
               : "=r"(a) : "l"(p));
    return a;
}
__device__ __forceinline__ void mma16816(float* d, const u32* a, u32 b0, u32 b1) {
    asm volatile(
        "mma.sync.aligned.m16n8k16.row.col.f32.f16.f16.f32 "
        "{%0,%1,%2,%3}, {%4,%5,%6,%7}, {%8,%9}, {%0,%1,%2,%3};"
        : "+f"(d[0]), "+f"(d[1]), "+f"(d[2]), "+f"(d[3])
        : "r"(a[0]), "r"(a[1]), "r"(a[2]), "r"(a[3]), "r"(b0), "r"(b1));
}
__device__ __forceinline__ void ldm_x4(u32* r, u32 a) {
    asm volatile("ldmatrix.sync.aligned.m8n8.x4.shared.b16 {%0,%1,%2,%3}, [%4];"
        : "=r"(r[0]), "=r"(r[1]), "=r"(r[2]), "=r"(r[3]) : "r"(a));
}
__device__ __forceinline__ void ldm_x2(u32& r0, u32& r1, u32 a) {
    asm volatile("ldmatrix.sync.aligned.m8n8.x2.shared.b16 {%0,%1}, [%2];"
        : "=r"(r0), "=r"(r1) : "r"(a));
}

// --------------------------- prep kernels ---------------------------
__global__ void prep_w1(const float* __restrict__ W) {
    size_t tot = (size_t)NL * K1E * HD;
    for (size_t i = (size_t)blockIdx.x * blockDim.x + threadIdx.x; i < tot;
         i += (size_t)gridDim.x * blockDim.x) {
        size_t l = i / ((size_t)K1E * HD);
        size_t rem = i - l * (size_t)K1E * HD;
        size_t k = rem / HD, n = rem - k * HD;
        gW1T[(l * HD + n) * K1E + k] = hf(W[i]);
    }
}
__global__ void prep_w2(const float* __restrict__ W) {
    size_t tot = (size_t)NL * HD * ED;
    for (size_t i = (size_t)blockIdx.x * blockDim.x + threadIdx.x; i < tot;
         i += (size_t)gridDim.x * blockDim.x) {
        size_t l = i / ((size_t)HD * ED);
        size_t rem = i - l * (size_t)HD * ED;
        size_t k = rem / ED, n = rem - k * ED;
        gW2T[(l * ED + n) * HD + k] = hf(W[i]);
    }
}
__global__ void prep_wn1(const float* __restrict__ W) {
    size_t tot = (size_t)NL * K1N * HD;
    for (size_t i = (size_t)blockIdx.x * blockDim.x + threadIdx.x; i < tot;
         i += (size_t)gridDim.x * blockDim.x) {
        size_t l = i / ((size_t)K1N * HD);
        size_t rem = i - l * (size_t)K1N * HD;
        size_t k = rem / HD, n = rem - k * HD;
        gWn1T[(l * HD + n) * K1N + k] = hf(W[i]);
    }
}
__global__ void prep_wn2(const float* __restrict__ W) {
    size_t tot = (size_t)NL * HD * ND;
    for (size_t i = (size_t)blockIdx.x * blockDim.x + threadIdx.x; i < tot;
         i += (size_t)gridDim.x * blockDim.x) {
        size_t l = i / ((size_t)HD * ND);
        size_t rem = i - l * (size_t)HD * ND;
        size_t k = rem / ND, n = rem - k * ND;
        gWn2T[(l * ND + n) * HD + k] = hf(W[i]);
    }
}

__global__ void zero_agg_kernel() {
    size_t n = (size_t)NB * NNODE * ED;
    for (size_t i = (size_t)blockIdx.x * blockDim.x + threadIdx.x; i < n;
         i += (size_t)gridDim.x * blockDim.x)
        g_agg[i] = 0.0f;
}

// strides (u16 units)
#define SAS 72    /* edge A slab row stride (64k + 8 pad) */
#define SA2 328   /* node A row stride */
#define SB 72     /* B slab row stride */
#define SH 136    /* h / edge-W2 row stride */
#define ABUF 18432            /* one A slab buffer: hi+lo = 64*72*2*2 */
#define BUFSZ 18432           /* one B buffer: hi only, 128 x SB x 2B */

// ===================== EDGE KERNEL (streamed A, 2 CTA/SM) ============
#define OFF_B (2 * ABUF)              /* 36864 */
#define OFF_W2E (OFF_B + 2 * BUFSZ)   /* 73728 */
#define EDGE_DSMEM (OFF_W2E + 17408)  /* 91136 */

__global__ void __launch_bounds__(256, 2)
edge_kernel_mma(const float* __restrict__ x, const int* __restrict__ eidx,
                const float* __restrict__ be1, const float* __restrict__ be2,
                const float* __restrict__ geW, const float* __restrict__ bleW, int l)
{
    extern __shared__ char dyn[];
    // A slab double buffers at dyn + ab*ABUF (hi [64][SAS], lo at +9216)
    // B double buffers at dyn + OFF_B + bb*BUFSZ
    // GEMM2 overlay: H hi/lo in B region; W2 hi at OFF_W2E; sm_p overlays W2
    u16* sHh = (u16*)(dyn + OFF_B);
    u16* sHl = sHh + 64 * SH;
    u16* sW2 = (u16*)(dyn + OFF_W2E);
    float* sm_p = (float*)(dyn + OFF_W2E);

    __shared__ int s_src[64], s_dst[64];
    __shared__ float s_b1[512], s_b2[64], s_g[64], s_bb[64];
    __shared__ float s_mu[64], s_rs[64];

    const int tid = threadIdx.x;
    const int lane = tid & 31;
    const int w = tid >> 5;
    const int g = lane >> 2;
    const int t = lane & 3;
    const int mgrp = w & 1;
    const int ngrp = w >> 1;          // 0..3
    const int m0 = mgrp * 32;
    const int b = blockIdx.y;
    const int e0 = blockIdx.x * 64;

    if (tid < 64) {
        s_src[tid] = eidx[e0 + tid];
        s_dst[tid] = eidx[NEDGE + e0 + tid];
    }
    for (int i = tid; i < 512; i += 256) s_b1[i] = be1[l * HD + i];
    if (tid < 64) {
        s_b2[tid] = be2[l * ED + tid];
        s_g[tid]  = geW[l * ED + tid];
        s_bb[tid] = bleW[l * ED + tid];
    }
    __syncthreads();

    const float* xb = x + (size_t)b * NNODE * ND;
    const float* eb = g_e + (size_t)b * NEDGE * ED;

    const u16* W1 = gW1T + (size_t)l * HD * K1E;
    const u16* W2 = gW2T + (size_t)l * ED * HD;

    // ldmatrix base offsets (within a buffer)
    u32 aOff[2];
    #pragma unroll
    for (int i = 0; i < 2; i++)
        aOff[i] = (u32)((m0 + i * 16 + (lane & 15)) * SAS * 2 + (lane >> 4) * 16);
    const u32 dynBase = smem_u32(dyn);
    const u32 bBase = dynBase + OFF_B
                    + (ngrp * 32 + (lane & 7)) * SB * 2 + ((lane >> 3) & 1) * 16;
    const u32 hH = dynBase + OFF_B + (m0 + (lane & 15)) * SH * 2 + (lane >> 4) * 16;
    const u32 hL = hH + 17408;
    const u32 wBase = dynBase + OFF_W2E
                    + (ngrp * 16 + (lane & 7)) * SH * 2 + ((lane >> 3) & 1) * 16;

    u16* bufB[2] = { (u16*)(dyn + OFF_B), (u16*)(dyn + OFF_B + BUFSZ) };

    float acc2[2][2][4];
    #pragma unroll
    for (int i = 0; i < 2; i++)
        #pragma unroll
        for (int j = 0; j < 2; j++)
            #pragma unroll
            for (int q = 0; q < 4; q++) acc2[i][j][q] = 0.0f;

    const int nlin = tid >> 3, qlin = tid & 7;   // B slab store coords

    for (int nc = 0; nc < 4; nc++) {
        float acc1[2][4][4];
        #pragma unroll
        for (int i = 0; i < 2; i++)
            #pragma unroll
            for (int j = 0; j < 4; j++)
                #pragma unroll
                for (int q = 0; q < 4; q++) acc1[i][j][q] = 0.0f;

        // preload B(0) and store into buf0
        uint4 ph[4];
        #pragma unroll
        for (int j = 0; j < 4; j++) {
            int n = j * 32 + nlin;
            ph[j] = *(const uint4*)(W1 + (size_t)(nc * 128 + n) * K1E + qlin * 8);
        }
        #pragma unroll
        for (int j = 0; j < 4; j++) {
            int n = j * 32 + nlin;
            *(uint4*)(bufB[0] + n * SB + qlin * 8) = ph[j];
        }
        // convert A slab 0 into A buf0
        #pragma unroll
        for (int j = 0; j < 4; j++) {
            int lin = j * 256 + tid;
            int r = lin >> 4, kl = (lin & 15) * 4;
            int k = kl;      // kc = 0
            float4 v;
            if (k < 64)       v = *(const float4*)(eb + (size_t)(e0 + r) * ED + k);
            else if (k < 320) v = *(const float4*)(xb + (size_t)s_src[r] * ND + (k - 64));
            else              v = *(const float4*)(xb + (size_t)s_dst[r] * ND + (k - 320));
            u16 h0 = hf(v.x), h1 = hf(v.y), h2 = hf(v.z), h3 = hf(v.w);
            u16 l0 = hf(v.x - hf_f(h0)), l1 = hf(v.y - hf_f(h1));
            u16 l2 = hf(v.z - hf_f(h2)), l3 = hf(v.w - hf_f(h3));
            size_t o = (size_t)r * SAS + kl;
            *(ull*)((u16*)dyn + o)        = (ull)h0 | ((ull)h1 << 16) | ((ull)h2 << 32) | ((ull)h3 << 48);
            *(ull*)((u16*)dyn + 4608 + o) = (ull)l0 | ((ull)l1 << 16) | ((ull)l2 << 32) | ((ull)l3 << 48);
        }
        __syncthreads();

        for (int kc = 0; kc < 9; kc++) {
            int cur = kc & 1;
            if (kc < 8) {
                #pragma unroll
                for (int j = 0; j < 4; j++) {
                    int n = j * 32 + nlin;
                    ph[j] = *(const uint4*)(W1 + (size_t)(nc * 128 + n) * K1E
                                            + (kc + 1) * 64 + qlin * 8);
                }
            }
            const u32 curB = bBase + cur * BUFSZ;
            const u32 aBaseH = dynBase + cur * ABUF;
            const u32 aBaseL = aBaseH + 9216;
            #pragma unroll
            for (int ks = 0; ks < 4; ks++) {
                int kA = ks * 32;             // within-slab byte offset
                u32 ah[2][4], al[2][4];
                ldm_x4(ah[0], aBaseH + aOff[0] + kA); ldm_x4(ah[1], aBaseH + aOff[1] + kA);
                ldm_x4(al[0], aBaseL + aOff[0] + kA); ldm_x4(al[1], aBaseL + aOff[1] + kA);
                int kB = ks * 32;
                #pragma unroll
                for (int j = 0; j < 4; j++) {
                    u32 bh0, bh1;
                    ldm_x2(bh0, bh1, curB + j * (8 * SB * 2) + kB);
                    #pragma unroll
                    for (int i = 0; i < 2; i++) {
                        mma16816(acc1[i][j], ah[i], bh0, bh1);
                        mma16816(acc1[i][j], al[i], bh0, bh1);
                    }
                }
            }
            if (kc < 8) {
                // store next B slab into other buffer
                #pragma unroll
                for (int j = 0; j < 4; j++) {
                    int n = j * 32 + nlin;
                    *(uint4*)(bufB[cur ^ 1] + n * SB + qlin * 8) = ph[j];
                }
                // convert next A slab into other A buffer
                u16* aDstH = (u16*)(dyn + (cur ^ 1) * ABUF);
                #pragma unroll
                for (int j = 0; j < 4; j++) {
                    int lin = j * 256 + tid;
                    int r = lin >> 4, kl = (lin & 15) * 4;
                    int k = (kc + 1) * 64 + kl;
                    float4 v;
                    if (k < 64)       v = *(const float4*)(eb + (size_t)(e0 + r) * ED + k);
                    else if (k < 320) v = *(const float4*)(xb + (size_t)s_src[r] * ND + (k - 64));
                    else              v = *(const float4*)(xb + (size_t)s_dst[r] * ND + (k - 320));
                    u16 h0 = hf(v.x), h1 = hf(v.y), h2 = hf(v.z), h3 = hf(v.w);
                    u16 l0 = hf(v.x - hf_f(h0)), l1 = hf(v.y - hf_f(h1));
                    u16 l2 = hf(v.z - hf_f(h2)), l3 = hf(v.w - hf_f(h3));
                    size_t o = (size_t)r * SAS + kl;
                    *(ull*)(aDstH + o)        = (ull)h0 | ((ull)h1 << 16) | ((ull)h2 << 32) | ((ull)h3 << 48);
                    *(ull*)(aDstH + 4608 + o) = (ull)l0 | ((ull)l1 << 16) | ((ull)l2 << 32) | ((ull)l3 << 48);
                }
            }
            __syncthreads();
        }

        // silu + bias -> h (fp16 hi/lo) into B-buffer region
        #pragma unroll
        for (int i = 0; i < 2; i++)
            #pragma unroll
            for (int j = 0; j < 4; j++) {
                int col = ngrp * 32 + j * 8 + 2 * t;
                int bc = nc * 128 + col;
                int r0 = m0 + i * 16 + g, r1 = r0 + 8;
                float v0 = silu_f(acc1[i][j][0] + s_b1[bc]);
                float v1 = silu_f(acc1[i][j][1] + s_b1[bc + 1]);
                float v2 = silu_f(acc1[i][j][2] + s_b1[bc]);
                float v3 = silu_f(acc1[i][j][3] + s_b1[bc + 1]);
                u16 h0 = hf(v0), h1 = hf(v1), h2 = hf(v2), h3 = hf(v3);
                *(u32*)(sHh + r0 * SH + col) = (u32)h0 | ((u32)h1 << 16);
                *(u32*)(sHh + r1 * SH + col) = (u32)h2 | ((u32)h3 << 16);
                u16 q0 = hf(v0 - hf_f(h0)), q1 = hf(v1 - hf_f(h1));
                u16 q2 = hf(v2 - hf_f(h2)), q3 = hf(v3 - hf_f(h3));
                *(u32*)(sHl + r0 * SH + col) = (u32)q0 | ((u32)q1 << 16);
                *(u32*)(sHl + r1 * SH + col) = (u32)q2 | ((u32)q3 << 16);
            }
        // W2 chunk [64 n][128 k] hi -> its region (1024 uint4)
        #pragma unroll
        for (int j = 0; j < 4; j++) {
            int lin = j * 256 + tid;
            int n = lin >> 4, q = lin & 15;
            *(uint4*)(sW2 + n * SH + q * 8) =
                *(const uint4*)(W2 + (size_t)n * HD + nc * 128 + q * 8);
        }
        __syncthreads();

        // GEMM2: acc2 += (Hh + Hl) @ W2
        #pragma unroll
        for (int ks = 0; ks < 8; ks++) {
            int k0 = (ks * 16) * 2;
            u32 ah[2][4], al[2][4];
            ldm_x4(ah[0], hH + k0); ldm_x4(ah[1], hH + 16 * SH * 2 + k0);
            ldm_x4(al[0], hL + k0); ldm_x4(al[1], hL + 16 * SH * 2 + k0);
            #pragma unroll
            for (int j = 0; j < 2; j++) {
                u32 bh0, bh1;
                ldm_x2(bh0, bh1, wBase + j * (8 * SH * 2) + k0);
                #pragma unroll
                for (int i = 0; i < 2; i++) {
                    mma16816(acc2[i][j], ah[i], bh0, bh1);
                    mma16816(acc2[i][j], al[i], bh0, bh1);
                }
            }
        }
        __syncthreads();
    }

    // epilogue: bias -> sm_p (W2 overlay), LN(64), residual, scatter
    #pragma unroll
    for (int i = 0; i < 2; i++)
        #pragma unroll
        for (int j = 0; j < 2; j++) {
            int col = ngrp * 16 + j * 8 + 2 * t;
            int r0 = m0 + i * 16 + g, r1 = r0 + 8;
            sm_p[r0 * 68 + col]     = acc2[i][j][0] + s_b2[col];
            sm_p[r0 * 68 + col + 1] = acc2[i][j][1] + s_b2[col + 1];
            sm_p[r1 * 68 + col]     = acc2[i][j][2] + s_b2[col];
            sm_p[r1 * 68 + col + 1] = acc2[i][j][3] + s_b2[col + 1];
        }
    __syncthreads();
    {
        int r = tid >> 2, sub = tid & 3;
        float s = 0.f, s2 = 0.f;
        #pragma unroll
        for (int cc = 0; cc < 16; cc++) {
            float v = sm_p[r * 68 + sub * 16 + cc];
            s += v; s2 += v * v;
        }
        s  += __shfl_xor_sync(0xffffffffu, s, 1);
        s  += __shfl_xor_sync(0xffffffffu, s, 2);
        s2 += __shfl_xor_sync(0xffffffffu, s2, 1);
        s2 += __shfl_xor_sync(0xffffffffu, s2, 2);
        if (sub == 0) {
            float mu = s * (1.0f / 64.0f);
            s_mu[r] = mu;
            s_rs[r] = rsqrtf(s2 * (1.0f / 64.0f) - mu * mu + 1e-5f);
        }
    }
    __syncthreads();
    {
        int c = tid & 63, grp = tid >> 6;
        float gv = s_g[c], bv = s_bb[c];
        float* eo = g_e + (size_t)b * NEDGE * ED;
        float* ag = g_agg + (size_t)b * NNODE * ED;
        #pragma unroll 4
        for (int rr = 0; rr < 16; rr++) {
            int r = grp * 16 + rr;
            float p = sm_p[r * 68 + c];
            float en = eo[(size_t)(e0 + r) * ED + c]
                     + (p - s_mu[r]) * s_rs[r] * gv + bv;
            eo[(size_t)(e0 + r) * ED + c] = en;
            atomicAdd(ag + (size_t)s_dst[r] * ED + c, en);
        }
    }
}

// ===================== NODE KERNEL (validated R12) ===================
#define NOFF_R2 83968                 /* 2 * 64*SA2*2 */
#define NOFF_H  (NOFF_R2 + 2 * BUFSZ) /* 120832 */
#define NODE_DSMEM (NOFF_H + 34816)   /* 155648 */

__global__ void __launch_bounds__(256, 1)
node_kernel_mma(float* __restrict__ x,
                const float* __restrict__ bn1, const float* __restrict__ bn2,
                const float* __restrict__ gnW, const float* __restrict__ blnW, int l)
{
    extern __shared__ char dyn[];
    u16* sAh = (u16*)(dyn);
    u16* sAl = sAh + 64 * SA2;
    u16* sW2 = (u16*)(dyn + NOFF_R2);
    u16* sHh = (u16*)(dyn + NOFF_H);
    u16* sHl = sHh + 64 * SH;
    float* sm_p = (float*)(dyn);

    __shared__ float s_b1[512], s_b2[256], s_g[256], s_bb[256];
    __shared__ float s_mu[64], s_rs[64];

    const int tid = threadIdx.x;
    const int lane = tid & 31;
    const int w = tid >> 5;
    const int g = lane >> 2;
    const int t = lane & 3;
    const int mgrp = w & 1;
    const int ngrp = w >> 1;
    const int m0 = mgrp * 32;
    const int b = blockIdx.y;
    const int n0 = blockIdx.x * 64;

    for (int i = tid; i < 512; i += 256) s_b1[i] = bn1[l * HD + i];
    if (tid < 256) {
        s_b2[tid] = bn2[l * ND + tid];
        s_g[tid]  = gnW[l * ND + tid];
        s_bb[tid] = blnW[l * ND + tid];
    }

    const float* xb = x + (size_t)b * NNODE * ND;
    const float* ab = g_agg + (size_t)b * NNODE * ED;

    for (int i = tid; i < 64 * 80; i += 256) {
        int r = i / 80, q4 = i - r * 80;
        int k = q4 * 4;
        int node = min(n0 + r, NNODE - 1);
        float4 v = (k < 256) ? *(const float4*)(xb + (size_t)node * ND + k)
                             : *(const float4*)(ab + (size_t)node * ED + (k - 256));
        u16 h0 = hf(v.x), h1 = hf(v.y), h2 = hf(v.z), h3 = hf(v.w);
        u16 l0 = hf(v.x - hf_f(h0)), l1 = hf(v.y - hf_f(h1));
        u16 l2 = hf(v.z - hf_f(h2)), l3 = hf(v.w - hf_f(h3));
        size_t o = (size_t)r * SA2 + k;
        *(ull*)(sAh + o) = (ull)h0 | ((ull)h1 << 16) | ((ull)h2 << 32) | ((ull)h3 << 48);
        *(ull*)(sAl + o) = (ull)l0 | ((ull)l1 << 16) | ((ull)l2 << 32) | ((ull)l3 << 48);
    }
    __syncthreads();

    const u16* W1 = gWn1T + (size_t)l * HD * K1N;
    const u16* W2 = gWn2T + (size_t)l * ND * HD;

    u32 aH[2], aL[2];
    #pragma unroll
    for (int i = 0; i < 2; i++) {
        aH[i] = smem_u32(sAh) + (m0 + i * 16 + (lane & 15)) * SA2 * 2 + (lane >> 4) * 16;
        aL[i] = smem_u32(sAl) + (m0 + i * 16 + (lane & 15)) * SA2 * 2 + (lane >> 4) * 16;
    }
    const u32 bBase = smem_u32(dyn + NOFF_R2)
                    + (ngrp * 32 + (lane & 7)) * SB * 2 + ((lane >> 3) & 1) * 16;
    const u32 hH = smem_u32(sHh) + (m0 + (lane & 15)) * SH * 2 + (lane >> 4) * 16;
    const u32 hL = smem_u32(sHl) + (m0 + (lane & 15)) * SH * 2 + (lane >> 4) * 16;
    const u32 wBase = smem_u32(sW2)
                    + (ngrp * 64 + (lane & 7)) * SB * 2 + ((lane >> 3) & 1) * 16;

    u16* bufB[2] = { (u16*)(dyn + NOFF_R2), (u16*)(dyn + NOFF_R2 + BUFSZ) };

    float acc2[2][8][4];
    #pragma unroll
    for (int i = 0; i < 2; i++)
        #pragma unroll
        for (int j = 0; j < 8; j++)
            #pragma unroll
            for (int q = 0; q < 4; q++) acc2[i][j][q] = 0.0f;

    const int nlin = tid >> 3, qlin = tid & 7;

    for (int nc = 0; nc < 4; nc++) {
        float acc1[2][4][4];
        #pragma unroll
        for (int i = 0; i < 2; i++)
            #pragma unroll
            for (int j = 0; j < 4; j++)
                #pragma unroll
                for (int q = 0; q < 4; q++) acc1[i][j][q] = 0.0f;

        uint4 ph[4];
        #pragma unroll
        for (int j = 0; j < 4; j++) {
            int n = j * 32 + nlin;
            ph[j] = *(const uint4*)(W1 + (size_t)(nc * 128 + n) * K1N + qlin * 8);
        }
        #pragma unroll
        for (int j = 0; j < 4; j++) {
            int n = j * 32 + nlin;
            *(uint4*)(bufB[0] + n * SB + qlin * 8) = ph[j];
        }
        __syncthreads();

        for (int kc = 0; kc < 5; kc++) {
            int cur = kc & 1;
            if (kc < 4) {
                #pragma unroll
                for (int j = 0; j < 4; j++) {
                    int n = j * 32 + nlin;
                    ph[j] = *(const uint4*)(W1 + (size_t)(nc * 128 + n) * K1N
                                            + (kc + 1) * 64 + qlin * 8);
                }
            }
            u32 curB = bBase + cur * BUFSZ;
            #pragma unroll
            for (int ks = 0; ks < 4; ks++) {
                int kA = (kc * 64 + ks * 16) * 2;
                u32 ah[2][4], al[2][4];
                ldm_x4(ah[0], aH[0] + kA); ldm_x4(ah[1], aH[1] + kA);
                ldm_x4(al[0], aL[0] + kA); ldm_x4(al[1], aL[1] + kA);
                int kB = (ks * 16) * 2;
                #pragma unroll
                for (int j = 0; j < 4; j++) {
                    u32 bh0, bh1;
                    ldm_x2(bh0, bh1, curB + j * (8 * SB * 2) + kB);
                    #pragma unroll
                    for (int i = 0; i < 2; i++) {
                        mma16816(acc1[i][j], ah[i], bh0, bh1);
                        mma16816(acc1[i][j], al[i], bh0, bh1);
                    }
                }
            }
            if (kc < 4) {
                #pragma unroll
                for (int j = 0; j < 4; j++) {
                    int n = j * 32 + nlin;
                    *(uint4*)(bufB[cur ^ 1] + n * SB + qlin * 8) = ph[j];
                }
            }
            __syncthreads();
        }

        #pragma unroll
        for (int i = 0; i < 2; i++)
            #pragma unroll
            for (int j = 0; j < 4; j++) {
                int col = ngrp * 32 + j * 8 + 2 * t;
                int bc = nc * 128 + col;
                int r0 = m0 + i * 16 + g, r1 = r0 + 8;
                float v0 = silu_f(acc1[i][j][0] + s_b1[bc]);
                float v1 = silu_f(acc1[i][j][1] + s_b1[bc + 1]);
                float v2 = silu_f(acc1[i][j][2] + s_b1[bc]);
                float v3 = silu_f(acc1[i][j][3] + s_b1[bc + 1]);
                u16 h0 = hf(v0), h1 = hf(v1), h2 = hf(v2), h3 = hf(v3);
                *(u32*)(sHh + r0 * SH + col) = (u32)h0 | ((u32)h1 << 16);
                *(u32*)(sHh + r1 * SH + col) = (u32)h2 | ((u32)h3 << 16);
                u16 q0 = hf(v0 - hf_f(h0)), q1 = hf(v1 - hf_f(h1));
                u16 q2 = hf(v2 - hf_f(h2)), q3 = hf(v3 - hf_f(h3));
                *(u32*)(sHl + r0 * SH + col) = (u32)q0 | ((u32)q1 << 16);
                *(u32*)(sHl + r1 * SH + col) = (u32)q2 | ((u32)q3 << 16);
            }
        __syncthreads();

        for (int s = 0; s < 2; s++) {
            for (int i = tid; i < 2048; i += 256) {
                int n = i >> 3, q = i & 7;
                *(uint4*)(sW2 + n * SB + q * 8) =
                    *(const uint4*)(W2 + (size_t)n * HD + nc * 128 + s * 64 + q * 8);
            }
            __syncthreads();
            #pragma unroll
            for (int ks = 0; ks < 4; ks++) {
                int kH = (s * 64 + ks * 16) * 2;
                int kW = (ks * 16) * 2;
                u32 ah[2][4], al[2][4];
                ldm_x4(ah[0], hH + kH); ldm_x4(ah[1], hH + 16 * SH * 2 + kH);
                ldm_x4(al[0], hL + kH); ldm_x4(al[1], hL + 16 * SH * 2 + kH);
                #pragma unroll
                for (int j = 0; j < 8; j++) {
                    u32 bh0, bh1;
                    ldm_x2(bh0, bh1, wBase + j * (8 * SB * 2) + kW);
                    #pragma unroll
                    for (int i = 0; i < 2; i++) {
                        mma16816(acc2[i][j], ah[i], bh0, bh1);
                        mma16816(acc2[i][j], al[i], bh0, bh1);
                    }
                }
            }
            __syncthreads();
        }
    }

    #pragma unroll
    for (int i = 0; i < 2; i++)
        #pragma unroll
        for (int j = 0; j < 8; j++) {
            int col = ngrp * 64 + j * 8 + 2 * t;
            int r0 = m0 + i * 16 + g, r1 = r0 + 8;
            sm_p[r0 * 260 + col]     = acc2[i][j][0] + s_b2[col];
            sm_p[r0 * 260 + col + 1] = acc2[i][j][1] + s_b2[col + 1];
            sm_p[r1 * 260 + col]     = acc2[i][j][2] + s_b2[col];
            sm_p[r1 * 260 + col + 1] = acc2[i][j][3] + s_b2[col + 1];
        }
    __syncthreads();
    {
        int r = tid >> 2, sub = tid & 3;
        float s = 0.f, s2 = 0.f;
        #pragma unroll 8
        for (int cc = 0; cc < 64; cc++) {
            float v = sm_p[r * 260 + sub * 64 + cc];
            s += v; s2 += v * v;
        }
        s  += __shfl_xor_sync(0xffffffffu, s, 1);
        s  += __shfl_xor_sync(0xffffffffu, s, 2);
        s2 += __shfl_xor_sync(0xffffffffu, s2, 1);
        s2 += __shfl_xor_sync(0xffffffffu, s2, 2);
        if (sub == 0) {
            float mu = s * (1.0f / 256.0f);
            s_mu[r] = mu;
            s_rs[r] = rsqrtf(s2 * (1.0f / 256.0f) - mu * mu + 1e-5f);
        }
    }
    __syncthreads();
    {
        int c = tid;
        float gv = s_g[c], bv = s_bb[c];
        float* xo = x + (size_t)b * NNODE * ND;
        for (int rr = 0; rr < 64; rr++) {
            if (n0 + rr < NNODE) {
                float v = sm_p[rr * 260 + c];
                size_t o = (size_t)(n0 + rr) * ND + c;
                xo[o] = xo[o] + (v - s_mu[rr]) * s_rs[rr] * gv + bv;
            }
        }
    }
}

// ============================== LAUNCH ===============================
extern "C" void kernel_launch(void* const* d_in, const int* in_sizes, int n_in,
                              void* d_out, int out_size) {
    const float* nf  = (const float*)d_in[0];
    const float* ef  = (const float*)d_in[1];
    const float* We1 = (const float*)d_in[2];
    const float* be1 = (const float*)d_in[3];
    const float* We2 = (const float*)d_in[4];
    const float* be2 = (const float*)d_in[5];
    const float* geW = (const float*)d_in[6];
    const float* ble = (const float*)d_in[7];
    const float* Wn1 = (const float*)d_in[8];
    const float* bn1 = (const float*)d_in[9];
    const float* Wn2 = (const float*)d_in[10];
    const float* bn2 = (const float*)d_in[11];
    const float* gnW = (const float*)d_in[12];
    const float* bln = (const float*)d_in[13];
    const int*  eidx = (const int*)d_in[14];
    float* x = (float*)d_out;

    cudaFuncSetAttribute(edge_kernel_mma, cudaFuncAttributeMaxDynamicSharedMemorySize, EDGE_DSMEM);
    cudaFuncSetAttribute(node_kernel_mma, cudaFuncAttributeMaxDynamicSharedMemorySize, NODE_DSMEM);

    prep_w1<<<2048, 256>>>(We1);
    prep_w2<<<512, 256>>>(We2);
    prep_wn1<<<1024, 256>>>(Wn1);
    prep_wn2<<<1024, 256>>>(Wn2);

    cudaMemcpyAsync(x, nf, sizeof(float) * (size_t)NB * NNODE * ND,
                    cudaMemcpyDeviceToDevice, 0);
    size_t ebytes = sizeof(float) * (size_t)NEDGE * ED;
    cudaMemcpyToSymbolAsync(g_e, ef, ebytes, 0, cudaMemcpyDeviceToDevice, 0);
    cudaMemcpyToSymbolAsync(g_e, ef, ebytes, ebytes, cudaMemcpyDeviceToDevice, 0);

    dim3 eg(NEDGE / 64, NB);
    dim3 ng((NNODE + 63) / 64, NB);
    for (int l = 0; l < NL; l++) {
        zero_agg_kernel<<<512, 256>>>();
        edge_kernel_mma<<<eg, 256, EDGE_DSMEM>>>(x, eidx, be1, be2, geW, ble, l);
        node_kernel_mma<<<ng, 256, NODE_DSMEM>>>(x, bn1, bn2, gnW, bln, l);
    }
}

// round 14
// speedup vs baseline: 4.6479x; 1.0327x over previous
#include <cuda_runtime.h>
#include <cuda_fp16.h>
#include <cstdint>

#define NB 2
#define NNODE 40962
#define NEDGE 327680
#define ND 256
#define ED 64
#define HD 512
#define NL 16
#define K1E 576   /* ED + 2*ND */
#define K1N 320   /* ND + ED   */

typedef unsigned long long ull;
typedef unsigned int u32;
typedef unsigned short u16;

// ----------------------------- scratch ------------------------------
__device__ float g_e[(size_t)NB * NEDGE * ED];
__device__ float g_agg[(size_t)NB * NNODE * ED];
__device__ u16 gW1T[(size_t)NL * HD * K1E];
__device__ u16 gW2T[(size_t)NL * ED * HD];
__device__ u16 gWn1T[(size_t)NL * HD * K1N];
__device__ u16 gWn2T[(size_t)NL * ND * HD];

// --------------------------- helpers --------------------------------
__device__ __forceinline__ u16 hf(float v) {
    return __half_as_ushort(__float2half_rn(v));
}
__device__ __forceinline__ float hf_f(u16 h) {
    return __half2float(__ushort_as_half(h));
}
__device__ __forceinline__ float silu_f(float v) {
    return __fdividef(v, 1.0f + __expf(-v));
}
__device__ __forceinline__ u32 smem_u32(const void* p) {
    u32 a; asm("{ .reg .u64 t; cvta.to.shared.u64 t, %1; cvt.u32.u64 %0, t; }"
               : "=r"(a) : "l"(p));
    return a;
}
__device__ __forceinline__ void mma16816(float* d, const u32* a, u32 b0, u32 b1) {
    asm volatile(
        "mma.sync.aligned.m16n8k16.row.col.f32.f16.f16.f32 "
        "{%0,%1,%2,%3}, {%4,%5,%6,%7}, {%8,%9}, {%0,%1,%2,%3};"
        : "+f"(d[0]), "+f"(d[1]), "+f"(d[2]), "+f"(d[3])
        : "r"(a[0]), "r"(a[1]), "r"(a[2]), "r"(a[3]), "r"(b0), "r"(b1));
}
__device__ __forceinline__ void ldm_x4(u32* r, u32 a) {
    asm volatile("ldmatrix.sync.aligned.m8n8.x4.shared.b16 {%0,%1,%2,%3}, [%4];"
        : "=r"(r[0]), "=r"(r[1]), "=r"(r[2]), "=r"(r[3]) : "r"(a));
}
__device__ __forceinline__ void ldm_x2(u32& r0, u32& r1, u32 a) {
    asm volatile("ldmatrix.sync.aligned.m8n8.x2.shared.b16 {%0,%1}, [%2];"
        : "=r"(r0), "=r"(r1) : "r"(a));
}
__device__ __forceinline__ void cp16(u32 sdst, const void* gsrc) {
    asm volatile("cp.async.cg.shared.global [%0], [%1], 16;"
                 :: "r"(sdst), "l"(gsrc) : "memory");
}
__device__ __forceinline__ void cp_commit() {
    asm volatile("cp.async.commit_group;" ::: "memory");
}
__device__ __forceinline__ void cp_wait0() {
    asm volatile("cp.async.wait_group 0;" ::: "memory");
}

// --------------------------- prep kernels ---------------------------
__global__ void prep_w1(const float* __restrict__ W) {
    size_t tot = (size_t)NL * K1E * HD;
    for (size_t i = (size_t)blockIdx.x * blockDim.x + threadIdx.x; i < tot;
         i += (size_t)gridDim.x * blockDim.x) {
        size_t l = i / ((size_t)K1E * HD);
        size_t rem = i - l * (size_t)K1E * HD;
        size_t k = rem / HD, n = rem - k * HD;
        gW1T[(l * HD + n) * K1E + k] = hf(W[i]);
    }
}
__global__ void prep_w2(const float* __restrict__ W) {
    size_t tot = (size_t)NL * HD * ED;
    for (size_t i = (size_t)blockIdx.x * blockDim.x + threadIdx.x; i < tot;
         i += (size_t)gridDim.x * blockDim.x) {
        size_t l = i / ((size_t)HD * ED);
        size_t rem = i - l * (size_t)HD * ED;
        size_t k = rem / ED, n = rem - k * ED;
        gW2T[(l * ED + n) * HD + k] = hf(W[i]);
    }
}
__global__ void prep_wn1(const float* __restrict__ W) {
    size_t tot = (size_t)NL * K1N * HD;
    for (size_t i = (size_t)blockIdx.x * blockDim.x + threadIdx.x; i < tot;
         i += (size_t)gridDim.x * blockDim.x) {
        size_t l = i / ((size_t)K1N * HD);
        size_t rem = i - l * (size_t)K1N * HD;
        size_t k = rem / HD, n = rem - k * HD;
        gWn1T[(l * HD + n) * K1N + k] = hf(W[i]);
    }
}
__global__ void prep_wn2(const float* __restrict__ W) {
    size_t tot = (size_t)NL * HD * ND;
    for (size_t i = (size_t)blockIdx.x * blockDim.x + threadIdx.x; i < tot;
         i += (size_t)gridDim.x * blockDim.x) {
        size_t l = i / ((size_t)HD * ND);
        size_t rem = i - l * (size_t)HD * ND;
        size_t k = rem / ND, n = rem - k * ND;
        gWn2T[(l * ND + n) * HD + k] = hf(W[i]);
    }
}

__global__ void zero_agg_kernel() {
    size_t n = (size_t)NB * NNODE * ED;
    for (size_t i = (size_t)blockIdx.x * blockDim.x + threadIdx.x; i < n;
         i += (size_t)gridDim.x * blockDim.x)
        g_agg[i] = 0.0f;
}

// strides (u16 units)
#define SAS 72    /* A slab row stride (64k + 8 pad) */
#define SB 72     /* B slab row stride */
#define SH 136    /* h / edge-W2 row stride */
#define ABUF 18432            /* one A slab buffer: hi+lo = 64*72*2*2 */
#define BUFSZ 18432           /* one B buffer: hi only, 128 x SB x 2B */

// ===================== EDGE KERNEL (streamed A, 2 CTA/SM) ============
#define OFF_B (2 * ABUF)              /* 36864 */
#define OFF_W2E (OFF_B + 2 * BUFSZ)   /* 73728 */
#define EDGE_DSMEM (OFF_W2E + 17408)  /* 91136 */

__global__ void __launch_bounds__(256, 2)
edge_kernel_mma(const float* __restrict__ x, const int* __restrict__ eidx,
                const float* __restrict__ be1, const float* __restrict__ be2,
                const float* __restrict__ geW, const float* __restrict__ bleW, int l)
{
    extern __shared__ char dyn[];
    u16* sHh = (u16*)(dyn + OFF_B);
    u16* sHl = sHh + 64 * SH;
    u16* sW2 = (u16*)(dyn + OFF_W2E);
    float* sm_p = (float*)(dyn + OFF_W2E);

    __shared__ int s_src[64], s_dst[64];
    __shared__ float s_b1[512], s_b2[64], s_g[64], s_bb[64];
    __shared__ float s_mu[64], s_rs[64];

    const int tid = threadIdx.x;
    const int lane = tid & 31;
    const int w = tid >> 5;
    const int g = lane >> 2;
    const int t = lane & 3;
    const int mgrp = w & 1;
    const int ngrp = w >> 1;
    const int m0 = mgrp * 32;
    const int b = blockIdx.y;
    const int e0 = blockIdx.x * 64;

    if (tid < 64) {
        s_src[tid] = eidx[e0 + tid];
        s_dst[tid] = eidx[NEDGE + e0 + tid];
    }
    for (int i = tid; i < 512; i += 256) s_b1[i] = be1[l * HD + i];
    if (tid < 64) {
        s_b2[tid] = be2[l * ED + tid];
        s_g[tid]  = geW[l * ED + tid];
        s_bb[tid] = bleW[l * ED + tid];
    }
    __syncthreads();

    const float* xb = x + (size_t)b * NNODE * ND;
    const float* eb = g_e + (size_t)b * NEDGE * ED;

    const u16* W1 = gW1T + (size_t)l * HD * K1E;
    const u16* W2 = gW2T + (size_t)l * ED * HD;

    u32 aOff[2];
    #pragma unroll
    for (int i = 0; i < 2; i++)
        aOff[i] = (u32)((m0 + i * 16 + (lane & 15)) * SAS * 2 + (lane >> 4) * 16);
    const u32 dynBase = smem_u32(dyn);
    const u32 bBase = dynBase + OFF_B
                    + (ngrp * 32 + (lane & 7)) * SB * 2 + ((lane >> 3) & 1) * 16;
    const u32 hH = dynBase + OFF_B + (m0 + (lane & 15)) * SH * 2 + (lane >> 4) * 16;
    const u32 hL = hH + 17408;
    const u32 wBase = dynBase + OFF_W2E
                    + (ngrp * 16 + (lane & 7)) * SH * 2 + ((lane >> 3) & 1) * 16;

    u16* bufB[2] = { (u16*)(dyn + OFF_B), (u16*)(dyn + OFF_B + BUFSZ) };

    float acc2[2][2][4];
    #pragma unroll
    for (int i = 0; i < 2; i++)
        #pragma unroll
        for (int j = 0; j < 2; j++)
            #pragma unroll
            for (int q = 0; q < 4; q++) acc2[i][j][q] = 0.0f;

    const int nlin = tid >> 3, qlin = tid & 7;

    for (int nc = 0; nc < 4; nc++) {
        float acc1[2][4][4];
        #pragma unroll
        for (int i = 0; i < 2; i++)
            #pragma unroll
            for (int j = 0; j < 4; j++)
                #pragma unroll
                for (int q = 0; q < 4; q++) acc1[i][j][q] = 0.0f;

        uint4 ph[4];
        #pragma unroll
        for (int j = 0; j < 4; j++) {
            int n = j * 32 + nlin;
            ph[j] = *(const uint4*)(W1 + (size_t)(nc * 128 + n) * K1E + qlin * 8);
        }
        #pragma unroll
        for (int j = 0; j < 4; j++) {
            int n = j * 32 + nlin;
            *(uint4*)(bufB[0] + n * SB + qlin * 8) = ph[j];
        }
        #pragma unroll
        for (int j = 0; j < 4; j++) {
            int lin = j * 256 + tid;
            int r = lin >> 4, kl = (lin & 15) * 4;
            int k = kl;
            float4 v;
            if (k < 64)       v = *(const float4*)(eb + (size_t)(e0 + r) * ED + k);
            else if (k < 320) v = *(const float4*)(xb + (size_t)s_src[r] * ND + (k - 64));
            else              v = *(const float4*)(xb + (size_t)s_dst[r] * ND + (k - 320));
            u16 h0 = hf(v.x), h1 = hf(v.y), h2 = hf(v.z), h3 = hf(v.w);
            u16 l0 = hf(v.x - hf_f(h0)), l1 = hf(v.y - hf_f(h1));
            u16 l2 = hf(v.z - hf_f(h2)), l3 = hf(v.w - hf_f(h3));
            size_t o = (size_t)r * SAS + kl;
            *(ull*)((u16*)dyn + o)        = (ull)h0 | ((ull)h1 << 16) | ((ull)h2 << 32) | ((ull)h3 << 48);
            *(ull*)((u16*)dyn + 4608 + o) = (ull)l0 | ((ull)l1 << 16) | ((ull)l2 << 32) | ((ull)l3 << 48);
        }
        __syncthreads();

        for (int kc = 0; kc < 9; kc++) {
            int cur = kc & 1;
            if (kc < 8) {
                #pragma unroll
                for (int j = 0; j < 4; j++) {
                    int n = j * 32 + nlin;
                    ph[j] = *(const uint4*)(W1 + (size_t)(nc * 128 + n) * K1E
                                            + (kc + 1) * 64 + qlin * 8);
                }
            }
            const u32 curB = bBase + cur * BUFSZ;
            const u32 aBaseH = dynBase + cur * ABUF;
            const u32 aBaseL = aBaseH + 9216;
            #pragma unroll
            for (int ks = 0; ks < 4; ks++) {
                int kA = ks * 32;
                u32 ah[2][4], al[2][4];
                ldm_x4(ah[0], aBaseH + aOff[0] + kA); ldm_x4(ah[1], aBaseH + aOff[1] + kA);
                ldm_x4(al[0], aBaseL + aOff[0] + kA); ldm_x4(al[1], aBaseL + aOff[1] + kA);
                int kB = ks * 32;
                #pragma unroll
                for (int j = 0; j < 4; j++) {
                    u32 bh0, bh1;
                    ldm_x2(bh0, bh1, curB + j * (8 * SB * 2) + kB);
                    #pragma unroll
                    for (int i = 0; i < 2; i++) {
                        mma16816(acc1[i][j], ah[i], bh0, bh1);
                        mma16816(acc1[i][j], al[i], bh0, bh1);
                    }
                }
            }
            if (kc < 8) {
                #pragma unroll
                for (int j = 0; j < 4; j++) {
                    int n = j * 32 + nlin;
                    *(uint4*)(bufB[cur ^ 1] + n * SB + qlin * 8) = ph[j];
                }
                u16* aDstH = (u16*)(dyn + (cur ^ 1) * ABUF);
                #pragma unroll
                for (int j = 0; j < 4; j++) {
                    int lin = j * 256 + tid;
                    int r = lin >> 4, kl = (lin & 15) * 4;
                    int k = (kc + 1) * 64 + kl;
                    float4 v;
                    if (k < 64)       v = *(const float4*)(eb + (size_t)(e0 + r) * ED + k);
                    else if (k < 320) v = *(const float4*)(xb + (size_t)s_src[r] * ND + (k - 64));
                    else              v = *(const float4*)(xb + (size_t)s_dst[r] * ND + (k - 320));
                    u16 h0 = hf(v.x), h1 = hf(v.y), h2 = hf(v.z), h3 = hf(v.w);
                    u16 l0 = hf(v.x - hf_f(h0)), l1 = hf(v.y - hf_f(h1));
                    u16 l2 = hf(v.z - hf_f(h2)), l3 = hf(v.w - hf_f(h3));
                    size_t o = (size_t)r * SAS + kl;
                    *(ull*)(aDstH + o)        = (ull)h0 | ((ull)h1 << 16) | ((ull)h2 << 32) | ((ull)h3 << 48);
                    *(ull*)(aDstH + 4608 + o) = (ull)l0 | ((ull)l1 << 16) | ((ull)l2 << 32) | ((ull)l3 << 48);
                }
            }
            __syncthreads();
        }

        #pragma unroll
        for (int i = 0; i < 2; i++)
            #pragma unroll
            for (int j = 0; j < 4; j++) {
                int col = ngrp * 32 + j * 8 + 2 * t;
                int bc = nc * 128 + col;
                int r0 = m0 + i * 16 + g, r1 = r0 + 8;
                float v0 = silu_f(acc1[i][j][0] + s_b1[bc]);
                float v1 = silu_f(acc1[i][j][1] + s_b1[bc + 1]);
                float v2 = silu_f(acc1[i][j][2] + s_b1[bc]);
                float v3 = silu_f(acc1[i][j][3] + s_b1[bc + 1]);
                u16 h0 = hf(v0), h1 = hf(v1), h2 = hf(v2), h3 = hf(v3);
                *(u32*)(sHh + r0 * SH + col) = (u32)h0 | ((u32)h1 << 16);
                *(u32*)(sHh + r1 * SH + col) = (u32)h2 | ((u32)h3 << 16);
                u16 q0 = hf(v0 - hf_f(h0)), q1 = hf(v1 - hf_f(h1));
                u16 q2 = hf(v2 - hf_f(h2)), q3 = hf(v3 - hf_f(h3));
                *(u32*)(sHl + r0 * SH + col) = (u32)q0 | ((u32)q1 << 16);
                *(u32*)(sHl + r1 * SH + col) = (u32)q2 | ((u32)q3 << 16);
            }
        #pragma unroll
        for (int j = 0; j < 4; j++) {
            int lin = j * 256 + tid;
            int n = lin >> 4, q = lin & 15;
            *(uint4*)(sW2 + n * SH + q * 8) =
                *(const uint4*)(W2 + (size_t)n * HD + nc * 128 + q * 8);
        }
        __syncthreads();

        #pragma unroll
        for (int ks = 0; ks < 8; ks++) {
            int k0 = (ks * 16) * 2;
            u32 ah[2][4], al[2][4];
            ldm_x4(ah[0], hH + k0); ldm_x4(ah[1], hH + 16 * SH * 2 + k0);
            ldm_x4(al[0], hL + k0); ldm_x4(al[1], hL + 16 * SH * 2 + k0);
            #pragma unroll
            for (int j = 0; j < 2; j++) {
                u32 bh0, bh1;
                ldm_x2(bh0, bh1, wBase + j * (8 * SH * 2) + k0);
                #pragma unroll
                for (int i = 0; i < 2; i++) {
                    mma16816(acc2[i][j], ah[i], bh0, bh1);
                    mma16816(acc2[i][j], al[i], bh0, bh1);
                }
            }
        }
        __syncthreads();
    }

    #pragma unroll
    for (int i = 0; i < 2; i++)
        #pragma unroll
        for (int j = 0; j < 2; j++) {
            int col = ngrp * 16 + j * 8 + 2 * t;
            int r0 = m0 + i * 16 + g, r1 = r0 + 8;
            sm_p[r0 * 68 + col]     = acc2[i][j][0] + s_b2[col];
            sm_p[r0 * 68 + col + 1] = acc2[i][j][1] + s_b2[col + 1];
            sm_p[r1 * 68 + col]     = acc2[i][j][2] + s_b2[col];
            sm_p[r1 * 68 + col + 1] = acc2[i][j][3] + s_b2[col + 1];
        }
    __syncthreads();
    {
        int r = tid >> 2, sub = tid & 3;
        float s = 0.f, s2 = 0.f;
        #pragma unroll
        for (int cc = 0; cc < 16; cc++) {
            float v = sm_p[r * 68 + sub * 16 + cc];
            s += v; s2 += v * v;
        }
        s  += __shfl_xor_sync(0xffffffffu, s, 1);
        s  += __shfl_xor_sync(0xffffffffu, s, 2);
        s2 += __shfl_xor_sync(0xffffffffu, s2, 1);
        s2 += __shfl_xor_sync(0xffffffffu, s2, 2);
        if (sub == 0) {
            float mu = s * (1.0f / 64.0f);
            s_mu[r] = mu;
            s_rs[r] = rsqrtf(s2 * (1.0f / 64.0f) - mu * mu + 1e-5f);
        }
    }
    __syncthreads();
    {
        int c = tid & 63, grp = tid >> 6;
        float gv = s_g[c], bv = s_bb[c];
        float* eo = g_e + (size_t)b * NEDGE * ED;
        float* ag = g_agg + (size_t)b * NNODE * ED;
        #pragma unroll 4
        for (int rr = 0; rr < 16; rr++) {
            int r = grp * 16 + rr;
            float p = sm_p[r * 68 + c];
            float en = eo[(size_t)(e0 + r) * ED + c]
                     + (p - s_mu[r]) * s_rs[r] * gv + bv;
            eo[(size_t)(e0 + r) * ED + c] = en;
            atomicAdd(ag + (size_t)s_dst[r] * ED + c, en);
        }
    }
}

// ===================== NODE KERNEL (streamed A, 2 CTA/SM) ============
#define NOFF_B (2 * ABUF)             /* 36864 */
#define NODE_DSMEM (NOFF_B + 2 * BUFSZ)   /* 73728 */

__global__ void __launch_bounds__(256, 2)
node_kernel_mma(float* __restrict__ x,
                const float* __restrict__ bn1, const float* __restrict__ bn2,
                const float* __restrict__ gnW, const float* __restrict__ blnW, int l)
{
    extern __shared__ char dyn[];
    // A slab double buffers at dyn + a*ABUF (hi [64][SAS], lo at u16 +4608)
    // B double buffers at dyn + NOFF_B + b*BUFSZ
    // GEMM2 overlay: H hi/lo in A region; W2 slab spans the B region
    u16* sHh = (u16*)(dyn);
    u16* sHl = sHh + 64 * SH;
    u16* sW2 = (u16*)(dyn + NOFF_B);
    float* sm_p = (float*)(dyn);        // epilogue overlay [64][260]

    __shared__ float s_b1[512], s_b2[256], s_g[256], s_bb[256];
    __shared__ float s_mu[64], s_rs[64];

    const int tid = threadIdx.x;
    const int lane = tid & 31;
    const int w = tid >> 5;
    const int g = lane >> 2;
    const int t = lane & 3;
    const int mgrp = w & 1;
    const int ngrp = w >> 1;
    const int m0 = mgrp * 32;
    const int b = blockIdx.y;
    const int n0 = blockIdx.x * 64;

    for (int i = tid; i < 512; i += 256) s_b1[i] = bn1[l * HD + i];
    if (tid < 256) {
        s_b2[tid] = bn2[l * ND + tid];
        s_g[tid]  = gnW[l * ND + tid];
        s_bb[tid] = blnW[l * ND + tid];
    }
    __syncthreads();

    const float* xb = x + (size_t)b * NNODE * ND;
    const float* ab = g_agg + (size_t)b * NNODE * ED;

    const u16* W1 = gWn1T + (size_t)l * HD * K1N;
    const u16* W2 = gWn2T + (size_t)l * ND * HD;

    u32 aOff[2];
    #pragma unroll
    for (int i = 0; i < 2; i++)
        aOff[i] = (u32)((m0 + i * 16 + (lane & 15)) * SAS * 2 + (lane >> 4) * 16);
    const u32 dynBase = smem_u32(dyn);
    const u32 bBase = dynBase + NOFF_B
                    + (ngrp * 32 + (lane & 7)) * SB * 2 + ((lane >> 3) & 1) * 16;
    const u32 hH = dynBase + (m0 + (lane & 15)) * SH * 2 + (lane >> 4) * 16;
    const u32 hL = hH + 17408;
    const u32 wBase = dynBase + NOFF_B
                    + (ngrp * 64 + (lane & 7)) * SB * 2 + ((lane >> 3) & 1) * 16;

    const int nlin = tid >> 3, qlin = tid & 7;

    float acc2[2][8][4];
    #pragma unroll
    for (int i = 0; i < 2; i++)
        #pragma unroll
        for (int j = 0; j < 8; j++)
            #pragma unroll
            for (int q = 0; q < 4; q++) acc2[i][j][q] = 0.0f;

    for (int nc = 0; nc < 4; nc++) {
        float acc1[2][4][4];
        #pragma unroll
        for (int i = 0; i < 2; i++)
            #pragma unroll
            for (int j = 0; j < 4; j++)
                #pragma unroll
                for (int q = 0; q < 4; q++) acc1[i][j][q] = 0.0f;

        // B slab 0 via cp.async into buf0
        #pragma unroll
        for (int j = 0; j < 4; j++) {
            int n = j * 32 + nlin;
            cp16(dynBase + NOFF_B + (n * SB + qlin * 8) * 2,
                 W1 + (size_t)(nc * 128 + n) * K1N + qlin * 8);
        }
        cp_commit();
        // convert A slab 0 into A buf0
        #pragma unroll
        for (int j = 0; j < 4; j++) {
            int lin = j * 256 + tid;
            int r = lin >> 4, kl = (lin & 15) * 4;
            int node = min(n0 + r, NNODE - 1);
            float4 v = (kl < 256) ? *(const float4*)(xb + (size_t)node * ND + kl)
                                  : *(const float4*)(ab + (size_t)node * ED + (kl - 256));
            u16 h0 = hf(v.x), h1 = hf(v.y), h2 = hf(v.z), h3 = hf(v.w);
            u16 l0 = hf(v.x - hf_f(h0)), l1 = hf(v.y - hf_f(h1));
            u16 l2 = hf(v.z - hf_f(h2)), l3 = hf(v.w - hf_f(h3));
            size_t o = (size_t)r * SAS + kl;
            *(ull*)((u16*)dyn + o)        = (ull)h0 | ((ull)h1 << 16) | ((ull)h2 << 32) | ((ull)h3 << 48);
            *(ull*)((u16*)dyn + 4608 + o) = (ull)l0 | ((ull)l1 << 16) | ((ull)l2 << 32) | ((ull)l3 << 48);
        }
        cp_wait0();
        __syncthreads();

        for (int kc = 0; kc < 5; kc++) {
            int cur = kc & 1;
            if (kc < 4) {
                // B slab kc+1 via cp.async into other buffer (overlaps MMAs below)
                u32 dst = dynBase + NOFF_B + (cur ^ 1) * BUFSZ;
                #pragma unroll
                for (int j = 0; j < 4; j++) {
                    int n = j * 32 + nlin;
                    cp16(dst + (n * SB + qlin * 8) * 2,
                         W1 + (size_t)(nc * 128 + n) * K1N + (kc + 1) * 64 + qlin * 8);
                }
                cp_commit();
            }
            const u32 curB = bBase + cur * BUFSZ;
            const u32 aBaseH = dynBase + cur * ABUF;
            const u32 aBaseL = aBaseH + 9216;
            #pragma unroll
            for (int ks = 0; ks < 4; ks++) {
                int kA = ks * 32;
                u32 ah[2][4], al[2][4];
                ldm_x4(ah[0], aBaseH + aOff[0] + kA); ldm_x4(ah[1], aBaseH + aOff[1] + kA);
                ldm_x4(al[0], aBaseL + aOff[0] + kA); ldm_x4(al[1], aBaseL + aOff[1] + kA);
                int kB = ks * 32;
                #pragma unroll
                for (int j = 0; j < 4; j++) {
                    u32 bh0, bh1;
                    ldm_x2(bh0, bh1, curB + j * (8 * SB * 2) + kB);
                    #pragma unroll
                    for (int i = 0; i < 2; i++) {
                        mma16816(acc1[i][j], ah[i], bh0, bh1);
                        mma16816(acc1[i][j], al[i], bh0, bh1);
                    }
                }
            }
            if (kc < 4) {
                // convert A slab kc+1 into other A buffer
                u16* aDstH = (u16*)(dyn + (cur ^ 1) * ABUF);
                #pragma unroll
                for (int j = 0; j < 4; j++) {
                    int lin = j * 256 + tid;
                    int r = lin >> 4, kl = (lin & 15) * 4;
                    int k = (kc + 1) * 64 + kl;
                    int node = min(n0 + r, NNODE - 1);
                    float4 v = (k < 256) ? *(const float4*)(xb + (size_t)node * ND + k)
                                         : *(const float4*)(ab + (size_t)node * ED + (k - 256));
                    u16 h0 = hf(v.x), h1 = hf(v.y), h2 = hf(v.z), h3 = hf(v.w);
                    u16 l0 = hf(v.x - hf_f(h0)), l1 = hf(v.y - hf_f(h1));
                    u16 l2 = hf(v.z - hf_f(h2)), l3 = hf(v.w - hf_f(h3));
                    size_t o = (size_t)r * SAS + kl;
                    *(ull*)(aDstH + o)        = (ull)h0 | ((ull)h1 << 16) | ((ull)h2 << 32) | ((ull)h3 << 48);
                    *(ull*)(aDstH + 4608 + o) = (ull)l0 | ((ull)l1 << 16) | ((ull)l2 << 32) | ((ull)l3 << 48);
                }
                cp_wait0();
            }
            __syncthreads();
        }

        // silu + bias -> h (fp16 hi/lo) into A region (A dead for this nc)
        #pragma unroll
        for (int i = 0; i < 2; i++)
            #pragma unroll
            for (int j = 0; j < 4; j++) {
                int col = ngrp * 32 + j * 8 + 2 * t;
                int bc = nc * 128 + col;
                int r0 = m0 + i * 16 + g, r1 = r0 + 8;
                float v0 = silu_f(acc1[i][j][0] + s_b1[bc]);
                float v1 = silu_f(acc1[i][j][1] + s_b1[bc + 1]);
                float v2 = silu_f(acc1[i][j][2] + s_b1[bc]);
                float v3 = silu_f(acc1[i][j][3] + s_b1[bc + 1]);
                u16 h0 = hf(v0), h1 = hf(v1), h2 = hf(v2), h3 = hf(v3);
                *(u32*)(sHh + r0 * SH + col) = (u32)h0 | ((u32)h1 << 16);
                *(u32*)(sHh + r1 * SH + col) = (u32)h2 | ((u32)h3 << 16);
                u16 q0 = hf(v0 - hf_f(h0)), q1 = hf(v1 - hf_f(h1));
                u16 q2 = hf(v2 - hf_f(h2)), q3 = hf(v3 - hf_f(h3));
                *(u32*)(sHl + r0 * SH + col) = (u32)q0 | ((u32)q1 << 16);
                *(u32*)(sHl + r1 * SH + col) = (u32)q2 | ((u32)q3 << 16);
            }
        __syncthreads();

        // GEMM2 over two 64-k slabs; W2 slab [256n][64k] into B region
        for (int s = 0; s < 2; s++) {
            for (int i = tid; i < 2048; i += 256) {
                int n = i >> 3, q = i & 7;
                *(uint4*)(sW2 + n * SB + q * 8) =
                    *(const uint4*)(W2 + (size_t)n * HD + nc * 128 + s * 64 + q * 8);
            }
            __syncthreads();
            #pragma unroll
            for (int ks = 0; ks < 4; ks++) {
                int kH = (s * 64 + ks * 16) * 2;
                int kW = (ks * 16) * 2;
                u32 ah[2][4], al[2][4];
                ldm_x4(ah[0], hH + kH); ldm_x4(ah[1], hH + 16 * SH * 2 + kH);
                ldm_x4(al[0], hL + kH); ldm_x4(al[1], hL + 16 * SH * 2 + kH);
                #pragma unroll
                for (int j = 0; j < 8; j++) {
                    u32 bh0, bh1;
                    ldm_x2(bh0, bh1, wBase + j * (8 * SB * 2) + kW);
                    #pragma unroll
                    for (int i = 0; i < 2; i++) {
                        mma16816(acc2[i][j], ah[i], bh0, bh1);
                        mma16816(acc2[i][j], al[i], bh0, bh1);
                    }
                }
            }
            __syncthreads();
        }
    }

    // epilogue: bias -> sm_p (A+B overlay), LN(256), residual, store
    #pragma unroll
    for (int i = 0; i < 2; i++)
        #pragma unroll
        for (int j = 0; j < 8; j++) {
            int col = ngrp * 64 + j * 8 + 2 * t;
            int r0 = m0 + i * 16 + g, r1 = r0 + 8;
            sm_p[r0 * 260 + col]     = acc2[i][j][0] + s_b2[col];
            sm_p[r0 * 260 + col + 1] = acc2[i][j][1] + s_b2[col + 1];
            sm_p[r1 * 260 + col]     = acc2[i][j][2] + s_b2[col];
            sm_p[r1 * 260 + col + 1] = acc2[i][j][3] + s_b2[col + 1];
        }
    __syncthreads();
    {
        int r = tid >> 2, sub = tid & 3;
        float s = 0.f, s2 = 0.f;
        #pragma unroll 8
        for (int cc = 0; cc < 64; cc++) {
            float v = sm_p[r * 260 + sub * 64 + cc];
            s += v; s2 += v * v;
        }
        s  += __shfl_xor_sync(0xffffffffu, s, 1);
        s  += __shfl_xor_sync(0xffffffffu, s, 2);
        s2 += __shfl_xor_sync(0xffffffffu, s2, 1);
        s2 += __shfl_xor_sync(0xffffffffu, s2, 2);
        if (sub == 0) {
            float mu = s * (1.0f / 256.0f);
            s_mu[r] = mu;
            s_rs[r] = rsqrtf(s2 * (1.0f / 256.0f) - mu * mu + 1e-5f);
        }
    }
    __syncthreads();
    {
        int c = tid;
        float gv = s_g[c], bv = s_bb[c];
        float* xo = x + (size_t)b * NNODE * ND;
        for (int rr = 0; rr < 64; rr++) {
            if (n0 + rr < NNODE) {
                float v = sm_p[rr * 260 + c];
                size_t o = (size_t)(n0 + rr) * ND + c;
                xo[o] = xo[o] + (v - s_mu[rr]) * s_rs[rr] * gv + bv;
            }
        }
    }
}

// ============================== LAUNCH ===============================
extern "C" void kernel_launch(void* const* d_in, const int* in_sizes, int n_in,
                              void* d_out, int out_size) {
    const float* nf  = (const float*)d_in[0];
    const float* ef  = (const float*)d_in[1];
    const float* We1 = (const float*)d_in[2];
    const float* be1 = (const float*)d_in[3];
    const float* We2 = (const float*)d_in[4];
    const float* be2 = (const float*)d_in[5];
    const float* geW = (const float*)d_in[6];
    const float* ble = (const float*)d_in[7];
    const float* Wn1 = (const float*)d_in[8];
    const float* bn1 = (const float*)d_in[9];
    const float* Wn2 = (const float*)d_in[10];
    const float* bn2 = (const float*)d_in[11];
    const float* gnW = (const float*)d_in[12];
    const float* bln = (const float*)d_in[13];
    const int*  eidx = (const int*)d_in[14];
    float* x = (float*)d_out;

    cudaFuncSetAttribute(edge_kernel_mma, cudaFuncAttributeMaxDynamicSharedMemorySize, EDGE_DSMEM);
    cudaFuncSetAttribute(node_kernel_mma, cudaFuncAttributeMaxDynamicSharedMemorySize, NODE_DSMEM);

    prep_w1<<<2048, 256>>>(We1);
    prep_w2<<<512, 256>>>(We2);
    prep_wn1<<<1024, 256>>>(Wn1);
    prep_wn2<<<1024, 256>>>(Wn2);

    cudaMemcpyAsync(x, nf, sizeof(float) * (size_t)NB * NNODE * ND,
                    cudaMemcpyDeviceToDevice, 0);
    size_t ebytes = sizeof(float) * (size_t)NEDGE * ED;
    cudaMemcpyToSymbolAsync(g_e, ef, ebytes, 0, cudaMemcpyDeviceToDevice, 0);
    cudaMemcpyToSymbolAsync(g_e, ef, ebytes, ebytes, cudaMemcpyDeviceToDevice, 0);

    dim3 eg(NEDGE / 64, NB);
    dim3 ng((NNODE + 63) / 64, NB);
    for (int l = 0; l < NL; l++) {
        zero_agg_kernel<<<512, 256>>>();
        edge_kernel_mma<<<eg, 256, EDGE_DSMEM>>>(x, eidx, be1, be2, geW, ble, l);
        node_kernel_mma<<<ng, 256, NODE_DSMEM>>>(x, bn1, bn2, gnW, bln, l);
    }
}

// round 15
// speedup vs baseline: 9.6985x; 2.0866x over previous
#include <cuda_runtime.h>
#include <cuda_fp16.h>
#include <cstdint>

#define NB 2
#define NNODE 40962
#define NEDGE 327680
#define ND 256
#define ED 64
#define HD 512
#define NL 16
#define K1E 576
#define K1N 320

typedef unsigned long long ull;
typedef unsigned int u32;
typedef unsigned short u16;

// ----------------------------- scratch ------------------------------
__device__ float g_e[(size_t)NB * NEDGE * ED];
__device__ float g_agg[(size_t)NB * NNODE * ED];
__device__ float g_psrc[(size_t)NB * NNODE * HD];   // x @ W1[64:320)
__device__ float g_pdst[(size_t)NB * NNODE * HD];   // x @ W1[320:576)
__device__ u16 gW1T[(size_t)NL * HD * K1E];
__device__ u16 gW2T[(size_t)NL * ED * HD];
__device__ u16 gWn1T[(size_t)NL * HD * K1N];
__device__ u16 gWn2T[(size_t)NL * ND * HD];

// --------------------------- helpers --------------------------------
__device__ __forceinline__ u16 hf(float v) {
    return __half_as_ushort(__float2half_rn(v));
}
__device__ __forceinline__ float hf_f(u16 h) {
    return __half2float(__ushort_as_half(h));
}
__device__ __forceinline__ float silu_f(float v) {
    return __fdividef(v, 1.0f + __expf(-v));
}
__device__ __forceinline__ u32 smem_u32(const void* p) {
    u32 a; asm("{ .reg .u64 t; cvta.to.shared.u64 t, %1; cvt.u32.u64 %0, t; }"
               : "=r"(a) : "l"(p));
    return a;
}
__device__ __forceinline__ void mma16816(float* d, const u32* a, u32 b0, u32 b1) {
    asm volatile(
        "mma.sync.aligned.m16n8k16.row.col.f32.f16.f16.f32 "
        "{%0,%1,%2,%3}, {%4,%5,%6,%7}, {%8,%9}, {%0,%1,%2,%3};"
        : "+f"(d[0]), "+f"(d[1]), "+f"(d[2]), "+f"(d[3])
        : "r"(a[0]), "r"(a[1]), "r"(a[2]), "r"(a[3]), "r"(b0), "r"(b1));
}
__device__ __forceinline__ void ldm_x4(u32* r, u32 a) {
    asm volatile("ldmatrix.sync.aligned.m8n8.x4.shared.b16 {%0,%1,%2,%3}, [%4];"
        : "=r"(r[0]), "=r"(r[1]), "=r"(r[2]), "=r"(r[3]) : "r"(a));
}
__device__ __forceinline__ void ldm_x2(u32& r0, u32& r1, u32 a) {
    asm volatile("ldmatrix.sync.aligned.m8n8.x2.shared.b16 {%0,%1}, [%2];"
        : "=r"(r0), "=r"(r1) : "r"(a));
}
__device__ __forceinline__ void cp16(u32 sdst, const void* gsrc) {
    asm volatile("cp.async.cg.shared.global [%0], [%1], 16;"
                 :: "r"(sdst), "l"(gsrc) : "memory");
}
__device__ __forceinline__ void cp_commit() {
    asm volatile("cp.async.commit_group;" ::: "memory");
}
__device__ __forceinline__ void cp_wait0() {
    asm volatile("cp.async.wait_group 0;" ::: "memory");
}

// --------------------------- prep kernels ---------------------------
__global__ void prep_w1(const float* __restrict__ W) {
    size_t tot = (size_t)NL * K1E * HD;
    for (size_t i = (size_t)blockIdx.x * blockDim.x + threadIdx.x; i < tot;
         i += (size_t)gridDim.x * blockDim.x) {
        size_t l = i / ((size_t)K1E * HD);
        size_t rem = i - l * (size_t)K1E * HD;
        size_t k = rem / HD, n = rem - k * HD;
        gW1T[(l * HD + n) * K1E + k] = hf(W[i]);
    }
}
__global__ void prep_w2(const float* __restrict__ W) {
    size_t tot = (size_t)NL * HD * ED;
    for (size_t i = (size_t)blockIdx.x * blockDim.x + threadIdx.x; i < tot;
         i += (size_t)gridDim.x * blockDim.x) {
        size_t l = i / ((size_t)HD * ED);
        size_t rem = i - l * (size_t)HD * ED;
        size_t k = rem / ED, n = rem - k * ED;
        gW2T[(l * ED + n) * HD + k] = hf(W[i]);
    }
}
__global__ void prep_wn1(const float* __restrict__ W) {
    size_t tot = (size_t)NL * K1N * HD;
    for (size_t i = (size_t)blockIdx.x * blockDim.x + threadIdx.x; i < tot;
         i += (size_t)gridDim.x * blockDim.x) {
        size_t l = i / ((size_t)K1N * HD);
        size_t rem = i - l * (size_t)K1N * HD;
        size_t k = rem / HD, n = rem - k * HD;
        gWn1T[(l * HD + n) * K1N + k] = hf(W[i]);
    }
}
__global__ void prep_wn2(const float* __restrict__ W) {
    size_t tot = (size_t)NL * HD * ND;
    for (size_t i = (size_t)blockIdx.x * blockDim.x + threadIdx.x; i < tot;
         i += (size_t)gridDim.x * blockDim.x) {
        size_t l = i / ((size_t)HD * ND);
        size_t rem = i - l * (size_t)HD * ND;
        size_t k = rem / ND, n = rem - k * ND;
        gWn2T[(l * ND + n) * HD + k] = hf(W[i]);
    }
}

__global__ void zero_agg_kernel() {
    size_t n = (size_t)NB * NNODE * ED;
    for (size_t i = (size_t)blockIdx.x * blockDim.x + threadIdx.x; i < n;
         i += (size_t)gridDim.x * blockDim.x)
        g_agg[i] = 0.0f;
}

// strides (u16 units)
#define SAS 72    /* small A row stride (64k + 8 pad) */
#define SAP 264   /* precompute A row stride (256k + 8 pad) */
#define SB 72     /* B slab row stride */
#define SH 136    /* h / edge-W2 row stride */
#define ABUF 18432
#define BUFSZ 18432

// ===================== PRECOMPUTE KERNEL =============================
// P_src[node] = x[node] @ W1T[:, 64:320), P_dst = x @ W1T[:, 320:576)
// A (x, 64 x 256) resident hi/lo; B slabs cp.async double-buffered.
#define POFF_B 67584                   /* 2 * 64*SAP*2 */
#define PRE_DSMEM (POFF_B + 2 * BUFSZ) /* 104448 */

__global__ void __launch_bounds__(256, 2)
precompute_p(const float* __restrict__ x, int l)
{
    extern __shared__ char dyn[];
    __shared__ float dummy;            // keep static smem nonzero-trivial
    (void)dummy;

    const int tid = threadIdx.x;
    const int lane = tid & 31;
    const int w = tid >> 5;
    const int g = lane >> 2;
    const int t = lane & 3;
    const int mgrp = w & 1;
    const int ngrp = w >> 1;
    const int m0 = mgrp * 32;
    const int b = blockIdx.y;
    const int n0 = blockIdx.x * 64;

    const float* xb = x + (size_t)b * NNODE * ND;
    const u16* W1 = gW1T + (size_t)l * HD * K1E;

    // convert A resident: 64 x 256 fp32 -> fp16 hi/lo
    for (int j = 0; j < 16; j++) {
        int lin = j * 256 + tid;
        int r = lin >> 6, kl = (lin & 63) * 4;
        int node = min(n0 + r, NNODE - 1);
        float4 v = *(const float4*)(xb + (size_t)node * ND + kl);
        u16 h0 = hf(v.x), h1 = hf(v.y), h2 = hf(v.z), h3 = hf(v.w);
        u16 l0 = hf(v.x - hf_f(h0)), l1 = hf(v.y - hf_f(h1));
        u16 l2 = hf(v.z - hf_f(h2)), l3 = hf(v.w - hf_f(h3));
        size_t o = (size_t)r * SAP + kl;
        *(ull*)((u16*)dyn + o)         = (ull)h0 | ((ull)h1 << 16) | ((ull)h2 << 32) | ((ull)h3 << 48);
        *(ull*)((u16*)dyn + 16896 + o) = (ull)l0 | ((ull)l1 << 16) | ((ull)l2 << 32) | ((ull)l3 << 48);
    }
    __syncthreads();

    const u32 dynBase = smem_u32(dyn);
    u32 aOff[2];
    #pragma unroll
    for (int i = 0; i < 2; i++)
        aOff[i] = (u32)((m0 + i * 16 + (lane & 15)) * SAP * 2 + (lane >> 4) * 16);
    const u32 bBase = dynBase + POFF_B
                    + (ngrp * 32 + (lane & 7)) * SB * 2 + ((lane >> 3) & 1) * 16;
    const int nlin = tid >> 3, qlin = tid & 7;

    for (int mat = 0; mat < 2; mat++) {
        float* P = (mat ? g_pdst : g_psrc) + (size_t)b * NNODE * HD;
        const int kb = 64 + mat * 256;

        for (int nc = 0; nc < 4; nc++) {
            float acc[2][4][4];
            #pragma unroll
            for (int i = 0; i < 2; i++)
                #pragma unroll
                for (int j = 0; j < 4; j++)
                    #pragma unroll
                    for (int q = 0; q < 4; q++) acc[i][j][q] = 0.0f;

            // B slab 0 -> buf0
            #pragma unroll
            for (int j = 0; j < 4; j++) {
                int n = j * 32 + nlin;
                cp16(dynBase + POFF_B + (n * SB + qlin * 8) * 2,
                     W1 + (size_t)(nc * 128 + n) * K1E + kb + qlin * 8);
            }
            cp_commit(); cp_wait0();
            __syncthreads();

            for (int kc = 0; kc < 4; kc++) {
                int cur = kc & 1;
                if (kc < 3) {
                    u32 dst = dynBase + POFF_B + (cur ^ 1) * BUFSZ;
                    #pragma unroll
                    for (int j = 0; j < 4; j++) {
                        int n = j * 32 + nlin;
                        cp16(dst + (n * SB + qlin * 8) * 2,
                             W1 + (size_t)(nc * 128 + n) * K1E + kb + (kc + 1) * 64 + qlin * 8);
                    }
                    cp_commit();
                }
                const u32 curB = bBase + cur * BUFSZ;
                #pragma unroll
                for (int ks = 0; ks < 4; ks++) {
                    int kA = (kc * 64 + ks * 16) * 2;
                    u32 ah[2][4], al[2][4];
                    ldm_x4(ah[0], dynBase + aOff[0] + kA);
                    ldm_x4(ah[1], dynBase + aOff[1] + kA);
                    ldm_x4(al[0], dynBase + 33792 + aOff[0] + kA);
                    ldm_x4(al[1], dynBase + 33792 + aOff[1] + kA);
                    int kB = ks * 32;
                    #pragma unroll
                    for (int j = 0; j < 4; j++) {
                        u32 bh0, bh1;
                        ldm_x2(bh0, bh1, curB + j * (8 * SB * 2) + kB);
                        #pragma unroll
                        for (int i = 0; i < 2; i++) {
                            mma16816(acc[i][j], ah[i], bh0, bh1);
                            mma16816(acc[i][j], al[i], bh0, bh1);
                        }
                    }
                }
                if (kc < 3) cp_wait0();
                __syncthreads();
            }

            // write P chunk
            #pragma unroll
            for (int i = 0; i < 2; i++)
                #pragma unroll
                for (int j = 0; j < 4; j++) {
                    int c = nc * 128 + ngrp * 32 + j * 8 + 2 * t;
                    int r0 = m0 + i * 16 + g, r1 = r0 + 8;
                    if (n0 + r0 < NNODE) {
                        float2 v = { acc[i][j][0], acc[i][j][1] };
                        *(float2*)(P + (size_t)(n0 + r0) * HD + c) = v;
                    }
                    if (n0 + r1 < NNODE) {
                        float2 v = { acc[i][j][2], acc[i][j][3] };
                        *(float2*)(P + (size_t)(n0 + r1) * HD + c) = v;
                    }
                }
        }
    }
}

// ===================== EDGE KERNEL (factored GEMM1) ==================
// GEMM1: acc = e @ W1[0:64) ; then acc += P_src[src] + P_dst[dst]
#define EOFF_B 18432
#define EOFF_W2 53248
#define EDGE_DSMEM 70656

__global__ void __launch_bounds__(256, 2)
edge_kernel_mma(const float* __restrict__ x, const int* __restrict__ eidx,
                const float* __restrict__ be1, const float* __restrict__ be2,
                const float* __restrict__ geW, const float* __restrict__ bleW, int l)
{
    extern __shared__ char dyn[];
    u16* sB  = (u16*)(dyn + EOFF_B);           // B slab [128][SB]
    u16* sHh = (u16*)(dyn + EOFF_B);           // H hi overlay (post-GEMM1)
    u16* sHl = (u16*)(dyn + 35840);            // H lo
    u16* sW2 = (u16*)(dyn + EOFF_W2);          // W2 chunk [64][SH]
    float* sm_p = (float*)(dyn + EOFF_W2);     // epilogue overlay

    __shared__ int s_src[64], s_dst[64];
    __shared__ float s_b1[512], s_b2[64], s_g[64], s_bb[64];
    __shared__ float s_mu[64], s_rs[64];

    const int tid = threadIdx.x;
    const int lane = tid & 31;
    const int w = tid >> 5;
    const int g = lane >> 2;
    const int t = lane & 3;
    const int mgrp = w & 1;
    const int ngrp = w >> 1;
    const int m0 = mgrp * 32;
    const int b = blockIdx.y;
    const int e0 = blockIdx.x * 64;

    if (tid < 64) {
        s_src[tid] = eidx[e0 + tid];
        s_dst[tid] = eidx[NEDGE + e0 + tid];
    }
    for (int i = tid; i < 512; i += 256) s_b1[i] = be1[l * HD + i];
    if (tid < 64) {
        s_b2[tid] = be2[l * ED + tid];
        s_g[tid]  = geW[l * ED + tid];
        s_bb[tid] = bleW[l * ED + tid];
    }

    const float* eb = g_e + (size_t)b * NEDGE * ED;
    const u16* W1 = gW1T + (size_t)l * HD * K1E;
    const u16* W2 = gW2T + (size_t)l * ED * HD;
    const float* Ps = g_psrc + (size_t)b * NNODE * HD;
    const float* Pd = g_pdst + (size_t)b * NNODE * HD;

    // convert e tile (64 x 64) -> A hi/lo resident at dyn
    #pragma unroll
    for (int j = 0; j < 4; j++) {
        int lin = j * 256 + tid;
        int r = lin >> 4, kl = (lin & 15) * 4;
        float4 v = *(const float4*)(eb + (size_t)(e0 + r) * ED + kl);
        u16 h0 = hf(v.x), h1 = hf(v.y), h2 = hf(v.z), h3 = hf(v.w);
        u16 l0 = hf(v.x - hf_f(h0)), l1 = hf(v.y - hf_f(h1));
        u16 l2 = hf(v.z - hf_f(h2)), l3 = hf(v.w - hf_f(h3));
        size_t o = (size_t)r * SAS + kl;
        *(ull*)((u16*)dyn + o)        = (ull)h0 | ((ull)h1 << 16) | ((ull)h2 << 32) | ((ull)h3 << 48);
        *(ull*)((u16*)dyn + 4608 + o) = (ull)l0 | ((ull)l1 << 16) | ((ull)l2 << 32) | ((ull)l3 << 48);
    }

    const u32 dynBase = smem_u32(dyn);
    u32 aOff[2];
    #pragma unroll
    for (int i = 0; i < 2; i++)
        aOff[i] = (u32)((m0 + i * 16 + (lane & 15)) * SAS * 2 + (lane >> 4) * 16);
    const u32 bBase = dynBase + EOFF_B
                    + (ngrp * 32 + (lane & 7)) * SB * 2 + ((lane >> 3) & 1) * 16;
    const u32 hH = dynBase + EOFF_B + (m0 + (lane & 15)) * SH * 2 + (lane >> 4) * 16;
    const u32 hL = hH + 17408;
    const u32 wBase = dynBase + EOFF_W2
                    + (ngrp * 16 + (lane & 7)) * SH * 2 + ((lane >> 3) & 1) * 16;

    float acc2[2][2][4];
    #pragma unroll
    for (int i = 0; i < 2; i++)
        #pragma unroll
        for (int j = 0; j < 2; j++)
            #pragma unroll
            for (int q = 0; q < 4; q++) acc2[i][j][q] = 0.0f;

    for (int nc = 0; nc < 4; nc++) {
        // B slab [128n][64k] + W2 chunk [64n][128k]
        #pragma unroll
        for (int j = 0; j < 4; j++) {
            int lin = j * 256 + tid;
            int n = lin >> 3, q = lin & 7;
            *(uint4*)(sB + n * SB + q * 8) =
                *(const uint4*)(W1 + (size_t)(nc * 128 + n) * K1E + q * 8);
        }
        #pragma unroll
        for (int j = 0; j < 4; j++) {
            int lin = j * 256 + tid;
            int n = lin >> 4, q = lin & 15;
            *(uint4*)(sW2 + n * SH + q * 8) =
                *(const uint4*)(W2 + (size_t)n * HD + nc * 128 + q * 8);
        }
        __syncthreads();

        float acc1[2][4][4];
        #pragma unroll
        for (int i = 0; i < 2; i++)
            #pragma unroll
            for (int j = 0; j < 4; j++)
                #pragma unroll
                for (int q = 0; q < 4; q++) acc1[i][j][q] = 0.0f;

        // GEMM1: e @ W1[0:64)
        #pragma unroll
        for (int ks = 0; ks < 4; ks++) {
            int kA = ks * 32;
            u32 ah[2][4], al[2][4];
            ldm_x4(ah[0], dynBase + aOff[0] + kA);
            ldm_x4(ah[1], dynBase + aOff[1] + kA);
            ldm_x4(al[0], dynBase + 9216 + aOff[0] + kA);
            ldm_x4(al[1], dynBase + 9216 + aOff[1] + kA);
            #pragma unroll
            for (int j = 0; j < 4; j++) {
                u32 bh0, bh1;
                ldm_x2(bh0, bh1, bBase + j * (8 * SB * 2) + ks * 32);
                #pragma unroll
                for (int i = 0; i < 2; i++) {
                    mma16816(acc1[i][j], ah[i], bh0, bh1);
                    mma16816(acc1[i][j], al[i], bh0, bh1);
                }
            }
        }

        // add gathered P_src + P_dst into fragments (global float2 loads)
        #pragma unroll
        for (int i = 0; i < 2; i++)
            #pragma unroll
            for (int j = 0; j < 4; j++) {
                int c = nc * 128 + ngrp * 32 + j * 8 + 2 * t;
                int r0 = m0 + i * 16 + g, r1 = r0 + 8;
                float2 p0 = *(const float2*)(Ps + (size_t)s_src[r0] * HD + c);
                float2 q0 = *(const float2*)(Pd + (size_t)s_dst[r0] * HD + c);
                acc1[i][j][0] += p0.x + q0.x;
                acc1[i][j][1] += p0.y + q0.y;
                float2 p1 = *(const float2*)(Ps + (size_t)s_src[r1] * HD + c);
                float2 q1 = *(const float2*)(Pd + (size_t)s_dst[r1] * HD + c);
                acc1[i][j][2] += p1.x + q1.x;
                acc1[i][j][3] += p1.y + q1.y;
            }
        __syncthreads();   // B reads done -> H may overwrite B region

        // silu + bias -> H (fp16 hi/lo)
        #pragma unroll
        for (int i = 0; i < 2; i++)
            #pragma unroll
            for (int j = 0; j < 4; j++) {
                int col = ngrp * 32 + j * 8 + 2 * t;
                int bc = nc * 128 + col;
                int r0 = m0 + i * 16 + g, r1 = r0 + 8;
                float v0 = silu_f(acc1[i][j][0] + s_b1[bc]);
                float v1 = silu_f(acc1[i][j][1] + s_b1[bc + 1]);
                float v2 = silu_f(acc1[i][j][2] + s_b1[bc]);
                float v3 = silu_f(acc1[i][j][3] + s_b1[bc + 1]);
                u16 h0 = hf(v0), h1 = hf(v1), h2 = hf(v2), h3 = hf(v3);
                *(u32*)(sHh + r0 * SH + col) = (u32)h0 | ((u32)h1 << 16);
                *(u32*)(sHh + r1 * SH + col) = (u32)h2 | ((u32)h3 << 16);
                u16 q0 = hf(v0 - hf_f(h0)), q1 = hf(v1 - hf_f(h1));
                u16 q2 = hf(v2 - hf_f(h2)), q3 = hf(v3 - hf_f(h3));
                *(u32*)(sHl + r0 * SH + col) = (u32)q0 | ((u32)q1 << 16);
                *(u32*)(sHl + r1 * SH + col) = (u32)q2 | ((u32)q3 << 16);
            }
        __syncthreads();   // H complete before GEMM2

        // GEMM2: acc2 += (Hh + Hl) @ W2
        #pragma unroll
        for (int ks = 0; ks < 8; ks++) {
            int k0 = (ks * 16) * 2;
            u32 ah[2][4], al[2][4];
            ldm_x4(ah[0], hH + k0); ldm_x4(ah[1], hH + 16 * SH * 2 + k0);
            ldm_x4(al[0], hL + k0); ldm_x4(al[1], hL + 16 * SH * 2 + k0);
            #pragma unroll
            for (int j = 0; j < 2; j++) {
                u32 bh0, bh1;
                ldm_x2(bh0, bh1, wBase + j * (8 * SH * 2) + k0);
                #pragma unroll
                for (int i = 0; i < 2; i++) {
                    mma16816(acc2[i][j], ah[i], bh0, bh1);
                    mma16816(acc2[i][j], al[i], bh0, bh1);
                }
            }
        }
        __syncthreads();   // H/W2 dead before next nc loads
    }

    // epilogue: bias -> sm_p (W2 overlay), LN(64), residual, scatter
    #pragma unroll
    for (int i = 0; i < 2; i++)
        #pragma unroll
        for (int j = 0; j < 2; j++) {
            int col = ngrp * 16 + j * 8 + 2 * t;
            int r0 = m0 + i * 16 + g, r1 = r0 + 8;
            sm_p[r0 * 68 + col]     = acc2[i][j][0] + s_b2[col];
            sm_p[r0 * 68 + col + 1] = acc2[i][j][1] + s_b2[col + 1];
            sm_p[r1 * 68 + col]     = acc2[i][j][2] + s_b2[col];
            sm_p[r1 * 68 + col + 1] = acc2[i][j][3] + s_b2[col + 1];
        }
    __syncthreads();
    {
        int r = tid >> 2, sub = tid & 3;
        float s = 0.f, s2 = 0.f;
        #pragma unroll
        for (int cc = 0; cc < 16; cc++) {
            float v = sm_p[r * 68 + sub * 16 + cc];
            s += v; s2 += v * v;
        }
        s  += __shfl_xor_sync(0xffffffffu, s, 1);
        s  += __shfl_xor_sync(0xffffffffu, s, 2);
        s2 += __shfl_xor_sync(0xffffffffu, s2, 1);
        s2 += __shfl_xor_sync(0xffffffffu, s2, 2);
        if (sub == 0) {
            float mu = s * (1.0f / 64.0f);
            s_mu[r] = mu;
            s_rs[r] = rsqrtf(s2 * (1.0f / 64.0f) - mu * mu + 1e-5f);
        }
    }
    __syncthreads();
    {
        int c = tid & 63, grp = tid >> 6;
        float gv = s_g[c], bv = s_bb[c];
        float* eo = g_e + (size_t)b * NEDGE * ED;
        float* ag = g_agg + (size_t)b * NNODE * ED;
        #pragma unroll 4
        for (int rr = 0; rr < 16; rr++) {
            int r = grp * 16 + rr;
            float p = sm_p[r * 68 + c];
            float en = eo[(size_t)(e0 + r) * ED + c]
                     + (p - s_mu[r]) * s_rs[r] * gv + bv;
            eo[(size_t)(e0 + r) * ED + c] = en;
            atomicAdd(ag + (size_t)s_dst[r] * ED + c, en);
        }
    }
}

// ===================== NODE KERNEL (validated R14) ===================
#define NOFF_B (2 * ABUF)
#define NODE_DSMEM (NOFF_B + 2 * BUFSZ)

__global__ void __launch_bounds__(256, 2)
node_kernel_mma(float* __restrict__ x,
                const float* __restrict__ bn1, const float* __restrict__ bn2,
                const float* __restrict__ gnW, const float* __restrict__ blnW, int l)
{
    extern __shared__ char dyn[];
    u16* sHh = (u16*)(dyn);
    u16* sHl = sHh + 64 * SH;
    u16* sW2 = (u16*)(dyn + NOFF_B);
    float* sm_p = (float*)(dyn);

    __shared__ float s_b1[512], s_b2[256], s_g[256], s_bb[256];
    __shared__ float s_mu[64], s_rs[64];

    const int tid = threadIdx.x;
    const int lane = tid & 31;
    const int w = tid >> 5;
    const int g = lane >> 2;
    const int t = lane & 3;
    const int mgrp = w & 1;
    const int ngrp = w >> 1;
    const int m0 = mgrp * 32;
    const int b = blockIdx.y;
    const int n0 = blockIdx.x * 64;

    for (int i = tid; i < 512; i += 256) s_b1[i] = bn1[l * HD + i];
    if (tid < 256) {
        s_b2[tid] = bn2[l * ND + tid];
        s_g[tid]  = gnW[l * ND + tid];
        s_bb[tid] = blnW[l * ND + tid];
    }
    __syncthreads();

    const float* xb = x + (size_t)b * NNODE * ND;
    const float* ab = g_agg + (size_t)b * NNODE * ED;

    const u16* W1 = gWn1T + (size_t)l * HD * K1N;
    const u16* W2 = gWn2T + (size_t)l * ND * HD;

    u32 aOff[2];
    #pragma unroll
    for (int i = 0; i < 2; i++)
        aOff[i] = (u32)((m0 + i * 16 + (lane & 15)) * SAS * 2 + (lane >> 4) * 16);
    const u32 dynBase = smem_u32(dyn);
    const u32 bBase = dynBase + NOFF_B
                    + (ngrp * 32 + (lane & 7)) * SB * 2 + ((lane >> 3) & 1) * 16;
    const u32 hH = dynBase + (m0 + (lane & 15)) * SH * 2 + (lane >> 4) * 16;
    const u32 hL = hH + 17408;
    const u32 wBase = dynBase + NOFF_B
                    + (ngrp * 64 + (lane & 7)) * SB * 2 + ((lane >> 3) & 1) * 16;

    const int nlin = tid >> 3, qlin = tid & 7;

    float acc2[2][8][4];
    #pragma unroll
    for (int i = 0; i < 2; i++)
        #pragma unroll
        for (int j = 0; j < 8; j++)
            #pragma unroll
            for (int q = 0; q < 4; q++) acc2[i][j][q] = 0.0f;

    for (int nc = 0; nc < 4; nc++) {
        float acc1[2][4][4];
        #pragma unroll
        for (int i = 0; i < 2; i++)
            #pragma unroll
            for (int j = 0; j < 4; j++)
                #pragma unroll
                for (int q = 0; q < 4; q++) acc1[i][j][q] = 0.0f;

        #pragma unroll
        for (int j = 0; j < 4; j++) {
            int n = j * 32 + nlin;
            cp16(dynBase + NOFF_B + (n * SB + qlin * 8) * 2,
                 W1 + (size_t)(nc * 128 + n) * K1N + qlin * 8);
        }
        cp_commit();
        #pragma unroll
        for (int j = 0; j < 4; j++) {
            int lin = j * 256 + tid;
            int r = lin >> 4, kl = (lin & 15) * 4;
            int node = min(n0 + r, NNODE - 1);
            float4 v = (kl < 256) ? *(const float4*)(xb + (size_t)node * ND + kl)
                                  : *(const float4*)(ab + (size_t)node * ED + (kl - 256));
            u16 h0 = hf(v.x), h1 = hf(v.y), h2 = hf(v.z), h3 = hf(v.w);
            u16 l0 = hf(v.x - hf_f(h0)), l1 = hf(v.y - hf_f(h1));
            u16 l2 = hf(v.z - hf_f(h2)), l3 = hf(v.w - hf_f(h3));
            size_t o = (size_t)r * SAS + kl;
            *(ull*)((u16*)dyn + o)        = (ull)h0 | ((ull)h1 << 16) | ((ull)h2 << 32) | ((ull)h3 << 48);
            *(ull*)((u16*)dyn + 4608 + o) = (ull)l0 | ((ull)l1 << 16) | ((ull)l2 << 32) | ((ull)l3 << 48);
        }
        cp_wait0();
        __syncthreads();

        for (int kc = 0; kc < 5; kc++) {
            int cur = kc & 1;
            if (kc < 4) {
                u32 dst = dynBase + NOFF_B + (cur ^ 1) * BUFSZ;
                #pragma unroll
                for (int j = 0; j < 4; j++) {
                    int n = j * 32 + nlin;
                    cp16(dst + (n * SB + qlin * 8) * 2,
                         W1 + (size_t)(nc * 128 + n) * K1N + (kc + 1) * 64 + qlin * 8);
                }
                cp_commit();
            }
            const u32 curB = bBase + cur * BUFSZ;
            const u32 aBaseH = dynBase + cur * ABUF;
            const u32 aBaseL = aBaseH + 9216;
            #pragma unroll
            for (int ks = 0; ks < 4; ks++) {
                int kA = ks * 32;
                u32 ah[2][4], al[2][4];
                ldm_x4(ah[0], aBaseH + aOff[0] + kA); ldm_x4(ah[1], aBaseH + aOff[1] + kA);
                ldm_x4(al[0], aBaseL + aOff[0] + kA); ldm_x4(al[1], aBaseL + aOff[1] + kA);
                int kB = ks * 32;
                #pragma unroll
                for (int j = 0; j < 4; j++) {
                    u32 bh0, bh1;
                    ldm_x2(bh0, bh1, curB + j * (8 * SB * 2) + kB);
                    #pragma unroll
                    for (int i = 0; i < 2; i++) {
                        mma16816(acc1[i][j], ah[i], bh0, bh1);
                        mma16816(acc1[i][j], al[i], bh0, bh1);
                    }
                }
            }
            if (kc < 4) {
                u16* aDstH = (u16*)(dyn + (cur ^ 1) * ABUF);
                #pragma unroll
                for (int j = 0; j < 4; j++) {
                    int lin = j * 256 + tid;
                    int r = lin >> 4, kl = (lin & 15) * 4;
                    int k = (kc + 1) * 64 + kl;
                    int node = min(n0 + r, NNODE - 1);
                    float4 v = (k < 256) ? *(const float4*)(xb + (size_t)node * ND + k)
                                         : *(const float4*)(ab + (size_t)node * ED + (k - 256));
                    u16 h0 = hf(v.x), h1 = hf(v.y), h2 = hf(v.z), h3 = hf(v.w);
                    u16 l0 = hf(v.x - hf_f(h0)), l1 = hf(v.y - hf_f(h1));
                    u16 l2 = hf(v.z - hf_f(h2)), l3 = hf(v.w - hf_f(h3));
                    size_t o = (size_t)r * SAS + kl;
                    *(ull*)(aDstH + o)        = (ull)h0 | ((ull)h1 << 16) | ((ull)h2 << 32) | ((ull)h3 << 48);
                    *(ull*)(aDstH + 4608 + o) = (ull)l0 | ((ull)l1 << 16) | ((ull)l2 << 32) | ((ull)l3 << 48);
                }
                cp_wait0();
            }
            __syncthreads();
        }

        #pragma unroll
        for (int i = 0; i < 2; i++)
            #pragma unroll
            for (int j = 0; j < 4; j++) {
                int col = ngrp * 32 + j * 8 + 2 * t;
                int bc = nc * 128 + col;
                int r0 = m0 + i * 16 + g, r1 = r0 + 8;
                float v0 = silu_f(acc1[i][j][0] + s_b1[bc]);
                float v1 = silu_f(acc1[i][j][1] + s_b1[bc + 1]);
                float v2 = silu_f(acc1[i][j][2] + s_b1[bc]);
                float v3 = silu_f(acc1[i][j][3] + s_b1[bc + 1]);
                u16 h0 = hf(v0), h1 = hf(v1), h2 = hf(v2), h3 = hf(v3);
                *(u32*)(sHh + r0 * SH + col) = (u32)h0 | ((u32)h1 << 16);
                *(u32*)(sHh + r1 * SH + col) = (u32)h2 | ((u32)h3 << 16);
                u16 q0 = hf(v0 - hf_f(h0)), q1 = hf(v1 - hf_f(h1));
                u16 q2 = hf(v2 - hf_f(h2)), q3 = hf(v3 - hf_f(h3));
                *(u32*)(sHl + r0 * SH + col) = (u32)q0 | ((u32)q1 << 16);
                *(u32*)(sHl + r1 * SH + col) = (u32)q2 | ((u32)q3 << 16);
            }
        __syncthreads();

        for (int s = 0; s < 2; s++) {
            for (int i = tid; i < 2048; i += 256) {
                int n = i >> 3, q = i & 7;
                *(uint4*)(sW2 + n * SB + q * 8) =
                    *(const uint4*)(W2 + (size_t)n * HD + nc * 128 + s * 64 + q * 8);
            }
            __syncthreads();
            #pragma unroll
            for (int ks = 0; ks < 4; ks++) {
                int kH = (s * 64 + ks * 16) * 2;
                int kW = (ks * 16) * 2;
                u32 ah[2][4], al[2][4];
                ldm_x4(ah[0], hH + kH); ldm_x4(ah[1], hH + 16 * SH * 2 + kH);
                ldm_x4(al[0], hL + kH); ldm_x4(al[1], hL + 16 * SH * 2 + kH);
                #pragma unroll
                for (int j = 0; j < 8; j++) {
                    u32 bh0, bh1;
                    ldm_x2(bh0, bh1, wBase + j * (8 * SB * 2) + kW);
                    #pragma unroll
                    for (int i = 0; i < 2; i++) {
                        mma16816(acc2[i][j], ah[i], bh0, bh1);
                        mma16816(acc2[i][j], al[i], bh0, bh1);
                    }
                }
            }
            __syncthreads();
        }
    }

    #pragma unroll
    for (int i = 0; i < 2; i++)
        #pragma unroll
        for (int j = 0; j < 8; j++) {
            int col = ngrp * 64 + j * 8 + 2 * t;
            int r0 = m0 + i * 16 + g, r1 = r0 + 8;
            sm_p[r0 * 260 + col]     = acc2[i][j][0] + s_b2[col];
            sm_p[r0 * 260 + col + 1] = acc2[i][j][1] + s_b2[col + 1];
            sm_p[r1 * 260 + col]     = acc2[i][j][2] + s_b2[col];
            sm_p[r1 * 260 + col + 1] = acc2[i][j][3] + s_b2[col + 1];
        }
    __syncthreads();
    {
        int r = tid >> 2, sub = tid & 3;
        float s = 0.f, s2 = 0.f;
        #pragma unroll 8
        for (int cc = 0; cc < 64; cc++) {
            float v = sm_p[r * 260 + sub * 64 + cc];
            s += v; s2 += v * v;
        }
        s  += __shfl_xor_sync(0xffffffffu, s, 1);
        s  += __shfl_xor_sync(0xffffffffu, s, 2);
        s2 += __shfl_xor_sync(0xffffffffu, s2, 1);
        s2 += __shfl_xor_sync(0xffffffffu, s2, 2);
        if (sub == 0) {
            float mu = s * (1.0f / 256.0f);
            s_mu[r] = mu;
            s_rs[r] = rsqrtf(s2 * (1.0f / 256.0f) - mu * mu + 1e-5f);
        }
    }
    __syncthreads();
    {
        int c = tid;
        float gv = s_g[c], bv = s_bb[c];
        float* xo = x + (size_t)b * NNODE * ND;
        for (int rr = 0; rr < 64; rr++) {
            if (n0 + rr < NNODE) {
                float v = sm_p[rr * 260 + c];
                size_t o = (size_t)(n0 + rr) * ND + c;
                xo[o] = xo[o] + (v - s_mu[rr]) * s_rs[rr] * gv + bv;
            }
        }
    }
}

// ============================== LAUNCH ===============================
extern "C" void kernel_launch(void* const* d_in, const int* in_sizes, int n_in,
                              void* d_out, int out_size) {
    const float* nf  = (const float*)d_in[0];
    const float* ef  = (const float*)d_in[1];
    const float* We1 = (const float*)d_in[2];
    const float* be1 = (const float*)d_in[3];
    const float* We2 = (const float*)d_in[4];
    const float* be2 = (const float*)d_in[5];
    const float* geW = (const float*)d_in[6];
    const float* ble = (const float*)d_in[7];
    const float* Wn1 = (const float*)d_in[8];
    const float* bn1 = (const float*)d_in[9];
    const float* Wn2 = (const float*)d_in[10];
    const float* bn2 = (const float*)d_in[11];
    const float* gnW = (const float*)d_in[12];
    const float* bln = (const float*)d_in[13];
    const int*  eidx = (const int*)d_in[14];
    float* x = (float*)d_out;

    cudaFuncSetAttribute(precompute_p, cudaFuncAttributeMaxDynamicSharedMemorySize, PRE_DSMEM);
    cudaFuncSetAttribute(edge_kernel_mma, cudaFuncAttributeMaxDynamicSharedMemorySize, EDGE_DSMEM);
    cudaFuncSetAttribute(node_kernel_mma, cudaFuncAttributeMaxDynamicSharedMemorySize, NODE_DSMEM);

    prep_w1<<<2048, 256>>>(We1);
    prep_w2<<<512, 256>>>(We2);
    prep_wn1<<<1024, 256>>>(Wn1);
    prep_wn2<<<1024, 256>>>(Wn2);

    cudaMemcpyAsync(x, nf, sizeof(float) * (size_t)NB * NNODE * ND,
                    cudaMemcpyDeviceToDevice, 0);
    size_t ebytes = sizeof(float) * (size_t)NEDGE * ED;
    cudaMemcpyToSymbolAsync(g_e, ef, ebytes, 0, cudaMemcpyDeviceToDevice, 0);
    cudaMemcpyToSymbolAsync(g_e, ef, ebytes, ebytes, cudaMemcpyDeviceToDevice, 0);

    dim3 pg((NNODE + 63) / 64, NB);
    dim3 eg(NEDGE / 64, NB);
    dim3 ng((NNODE + 63) / 64, NB);
    for (int l = 0; l < NL; l++) {
        zero_agg_kernel<<<512, 256>>>();
        precompute_p<<<pg, 256, PRE_DSMEM>>>(x, l);
        edge_kernel_mma<<<eg, 256, EDGE_DSMEM>>>(x, eidx, be1, be2, geW, ble, l);
        node_kernel_mma<<<ng, 256, NODE_DSMEM>>>(x, bn1, bn2, gnW, bln, l);
    }
}

// round 16
// speedup vs baseline: 10.1393x; 1.0455x over previous
#include <cuda_runtime.h>
#include <cuda_fp16.h>
#include <cstdint>

#define NB 2
#define NNODE 40962
#define NEDGE 327680
#define ND 256
#define ED 64
#define HD 512
#define NL 16
#define K1E 576
#define K1N 320

typedef unsigned long long ull;
typedef unsigned int u32;
typedef unsigned short u16;

// ----------------------------- scratch ------------------------------
__device__ float g_e[(size_t)NB * NEDGE * ED];
__device__ float g_agg[(size_t)NB * NNODE * ED];
__device__ u16 g_psrc[(size_t)NB * NNODE * HD];   // fp16: x @ W1[64:320)
__device__ u16 g_pdst[(size_t)NB * NNODE * HD];   // fp16: x @ W1[320:576)
__device__ u16 gW1T[(size_t)NL * HD * K1E];
__device__ u16 gW2T[(size_t)NL * ED * HD];
__device__ u16 gWn1T[(size_t)NL * HD * K1N];
__device__ u16 gWn2T[(size_t)NL * ND * HD];

// --------------------------- helpers --------------------------------
__device__ __forceinline__ u16 hf(float v) {
    return __half_as_ushort(__float2half_rn(v));
}
__device__ __forceinline__ float hf_f(u16 h) {
    return __half2float(__ushort_as_half(h));
}
__device__ __forceinline__ float2 h2f(u32 v) {
    __half2 h = *reinterpret_cast<__half2*>(&v);
    return __half22float2(h);
}
__device__ __forceinline__ float silu_f(float v) {
    return __fdividef(v, 1.0f + __expf(-v));
}
__device__ __forceinline__ u32 smem_u32(const void* p) {
    u32 a; asm("{ .reg .u64 t; cvta.to.shared.u64 t, %1; cvt.u32.u64 %0, t; }"
               : "=r"(a) : "l"(p));
    return a;
}
__device__ __forceinline__ void mma16816(float* d, const u32* a, u32 b0, u32 b1) {
    asm volatile(
        "mma.sync.aligned.m16n8k16.row.col.f32.f16.f16.f32 "
        "{%0,%1,%2,%3}, {%4,%5,%6,%7}, {%8,%9}, {%0,%1,%2,%3};"
        : "+f"(d[0]), "+f"(d[1]), "+f"(d[2]), "+f"(d[3])
        : "r"(a[0]), "r"(a[1]), "r"(a[2]), "r"(a[3]), "r"(b0), "r"(b1));
}
__device__ __forceinline__ void ldm_x4(u32* r, u32 a) {
    asm volatile("ldmatrix.sync.aligned.m8n8.x4.shared.b16 {%0,%1,%2,%3}, [%4];"
        : "=r"(r[0]), "=r"(r[1]), "=r"(r[2]), "=r"(r[3]) : "r"(a));
}
__device__ __forceinline__ void ldm_x2(u32& r0, u32& r1, u32 a) {
    asm volatile("ldmatrix.sync.aligned.m8n8.x2.shared.b16 {%0,%1}, [%2];"
        : "=r"(r0), "=r"(r1) : "r"(a));
}
__device__ __forceinline__ void cp16(u32 sdst, const void* gsrc) {
    asm volatile("cp.async.cg.shared.global [%0], [%1], 16;"
                 :: "r"(sdst), "l"(gsrc) : "memory");
}
__device__ __forceinline__ void cp_commit() {
    asm volatile("cp.async.commit_group;" ::: "memory");
}
__device__ __forceinline__ void cp_wait0() {
    asm volatile("cp.async.wait_group 0;" ::: "memory");
}

// --------------------------- prep kernels ---------------------------
__global__ void prep_w1(const float* __restrict__ W) {
    size_t tot = (size_t)NL * K1E * HD;
    for (size_t i = (size_t)blockIdx.x * blockDim.x + threadIdx.x; i < tot;
         i += (size_t)gridDim.x * blockDim.x) {
        size_t l = i / ((size_t)K1E * HD);
        size_t rem = i - l * (size_t)K1E * HD;
        size_t k = rem / HD, n = rem - k * HD;
        gW1T[(l * HD + n) * K1E + k] = hf(W[i]);
    }
}
__global__ void prep_w2(const float* __restrict__ W) {
    size_t tot = (size_t)NL * HD * ED;
    for (size_t i = (size_t)blockIdx.x * blockDim.x + threadIdx.x; i < tot;
         i += (size_t)gridDim.x * blockDim.x) {
        size_t l = i / ((size_t)HD * ED);
        size_t rem = i - l * (size_t)HD * ED;
        size_t k = rem / ED, n = rem - k * ED;
        gW2T[(l * ED + n) * HD + k] = hf(W[i]);
    }
}
__global__ void prep_wn1(const float* __restrict__ W) {
    size_t tot = (size_t)NL * K1N * HD;
    for (size_t i = (size_t)blockIdx.x * blockDim.x + threadIdx.x; i < tot;
         i += (size_t)gridDim.x * blockDim.x) {
        size_t l = i / ((size_t)K1N * HD);
        size_t rem = i - l * (size_t)K1N * HD;
        size_t k = rem / HD, n = rem - k * HD;
        gWn1T[(l * HD + n) * K1N + k] = hf(W[i]);
    }
}
__global__ void prep_wn2(const float* __restrict__ W) {
    size_t tot = (size_t)NL * HD * ND;
    for (size_t i = (size_t)blockIdx.x * blockDim.x + threadIdx.x; i < tot;
         i += (size_t)gridDim.x * blockDim.x) {
        size_t l = i / ((size_t)HD * ND);
        size_t rem = i - l * (size_t)HD * ND;
        size_t k = rem / ND, n = rem - k * ND;
        gWn2T[(l * ND + n) * HD + k] = hf(W[i]);
    }
}

// strides (u16 units)
#define SAS 72    /* small A row stride (64k + 8 pad) */
#define SAP 264   /* precompute A row stride (256k + 8 pad) */
#define SB 72     /* B slab row stride */
#define SH 136    /* h / edge-W2 row stride */
#define ABUF 18432
#define BUFSZ 18432

// ===================== PRECOMPUTE KERNEL =============================
// P_src[node] = x[node] @ W1T[:, 64:320), P_dst = x @ W1T[:, 320:576)
// (fp16 output). Also zeroes this block's agg slice.
#define POFF_B 67584                   /* 2 * 64*SAP*2 */
#define PRE_DSMEM (POFF_B + 2 * BUFSZ) /* 104448 */

__global__ void __launch_bounds__(256, 2)
precompute_p(const float* __restrict__ x, int l)
{
    extern __shared__ char dyn[];

    const int tid = threadIdx.x;
    const int lane = tid & 31;
    const int w = tid >> 5;
    const int g = lane >> 2;
    const int t = lane & 3;
    const int mgrp = w & 1;
    const int ngrp = w >> 1;
    const int m0 = mgrp * 32;
    const int b = blockIdx.y;
    const int n0 = blockIdx.x * 64;

    const float* xb = x + (size_t)b * NNODE * ND;
    const u16* W1 = gW1T + (size_t)l * HD * K1E;

    // zero this block's agg slice (replaces zero_agg kernel)
    {
        float* ag = g_agg + (size_t)b * NNODE * ED;
        float4 z = make_float4(0.f, 0.f, 0.f, 0.f);
        for (int i = tid; i < 64 * 16; i += 256) {
            int r = i >> 4, q = i & 15;
            if (n0 + r < NNODE)
                ((float4*)(ag + (size_t)(n0 + r) * ED))[q] = z;
        }
    }

    // convert A resident: 64 x 256 fp32 -> fp16 hi/lo
    for (int j = 0; j < 16; j++) {
        int lin = j * 256 + tid;
        int r = lin >> 6, kl = (lin & 63) * 4;
        int node = min(n0 + r, NNODE - 1);
        float4 v = *(const float4*)(xb + (size_t)node * ND + kl);
        u16 h0 = hf(v.x), h1 = hf(v.y), h2 = hf(v.z), h3 = hf(v.w);
        u16 l0 = hf(v.x - hf_f(h0)), l1 = hf(v.y - hf_f(h1));
        u16 l2 = hf(v.z - hf_f(h2)), l3 = hf(v.w - hf_f(h3));
        size_t o = (size_t)r * SAP + kl;
        *(ull*)((u16*)dyn + o)         = (ull)h0 | ((ull)h1 << 16) | ((ull)h2 << 32) | ((ull)h3 << 48);
        *(ull*)((u16*)dyn + 16896 + o) = (ull)l0 | ((ull)l1 << 16) | ((ull)l2 << 32) | ((ull)l3 << 48);
    }
    __syncthreads();

    const u32 dynBase = smem_u32(dyn);
    u32 aOff[2];
    #pragma unroll
    for (int i = 0; i < 2; i++)
        aOff[i] = (u32)((m0 + i * 16 + (lane & 15)) * SAP * 2 + (lane >> 4) * 16);
    const u32 bBase = dynBase + POFF_B
                    + (ngrp * 32 + (lane & 7)) * SB * 2 + ((lane >> 3) & 1) * 16;
    const int nlin = tid >> 3, qlin = tid & 7;

    for (int mat = 0; mat < 2; mat++) {
        u16* P = (mat ? g_pdst : g_psrc) + (size_t)b * NNODE * HD;
        const int kb = 64 + mat * 256;

        for (int nc = 0; nc < 4; nc++) {
            float acc[2][4][4];
            #pragma unroll
            for (int i = 0; i < 2; i++)
                #pragma unroll
                for (int j = 0; j < 4; j++)
                    #pragma unroll
                    for (int q = 0; q < 4; q++) acc[i][j][q] = 0.0f;

            #pragma unroll
            for (int j = 0; j < 4; j++) {
                int n = j * 32 + nlin;
                cp16(dynBase + POFF_B + (n * SB + qlin * 8) * 2,
                     W1 + (size_t)(nc * 128 + n) * K1E + kb + qlin * 8);
            }
            cp_commit(); cp_wait0();
            __syncthreads();

            for (int kc = 0; kc < 4; kc++) {
                int cur = kc & 1;
                if (kc < 3) {
                    u32 dst = dynBase + POFF_B + (cur ^ 1) * BUFSZ;
                    #pragma unroll
                    for (int j = 0; j < 4; j++) {
                        int n = j * 32 + nlin;
                        cp16(dst + (n * SB + qlin * 8) * 2,
                             W1 + (size_t)(nc * 128 + n) * K1E + kb + (kc + 1) * 64 + qlin * 8);
                    }
                    cp_commit();
                }
                const u32 curB = bBase + cur * BUFSZ;
                #pragma unroll
                for (int ks = 0; ks < 4; ks++) {
                    int kA = (kc * 64 + ks * 16) * 2;
                    u32 ah[2][4], al[2][4];
                    ldm_x4(ah[0], dynBase + aOff[0] + kA);
                    ldm_x4(ah[1], dynBase + aOff[1] + kA);
                    ldm_x4(al[0], dynBase + 33792 + aOff[0] + kA);
                    ldm_x4(al[1], dynBase + 33792 + aOff[1] + kA);
                    int kB = ks * 32;
                    #pragma unroll
                    for (int j = 0; j < 4; j++) {
                        u32 bh0, bh1;
                        ldm_x2(bh0, bh1, curB + j * (8 * SB * 2) + kB);
                        #pragma unroll
                        for (int i = 0; i < 2; i++) {
                            mma16816(acc[i][j], ah[i], bh0, bh1);
                            mma16816(acc[i][j], al[i], bh0, bh1);
                        }
                    }
                }
                if (kc < 3) cp_wait0();
                __syncthreads();
            }

            // write P chunk as fp16 pairs
            #pragma unroll
            for (int i = 0; i < 2; i++)
                #pragma unroll
                for (int j = 0; j < 4; j++) {
                    int c = nc * 128 + ngrp * 32 + j * 8 + 2 * t;
                    int r0 = m0 + i * 16 + g, r1 = r0 + 8;
                    if (n0 + r0 < NNODE)
                        *(u32*)(P + (size_t)(n0 + r0) * HD + c) =
                            (u32)hf(acc[i][j][0]) | ((u32)hf(acc[i][j][1]) << 16);
                    if (n0 + r1 < NNODE)
                        *(u32*)(P + (size_t)(n0 + r1) * HD + c) =
                            (u32)hf(acc[i][j][2]) | ((u32)hf(acc[i][j][3]) << 16);
                }
        }
    }
}

// ===================== EDGE KERNEL (factored GEMM1) ==================
#define EOFF_B 18432
#define EOFF_W2 53248
#define EDGE_DSMEM 70656

__global__ void __launch_bounds__(256, 2)
edge_kernel_mma(const float* __restrict__ x, const int* __restrict__ eidx,
                const float* __restrict__ be1, const float* __restrict__ be2,
                const float* __restrict__ geW, const float* __restrict__ bleW, int l)
{
    extern __shared__ char dyn[];
    u16* sB  = (u16*)(dyn + EOFF_B);
    u16* sHh = (u16*)(dyn + EOFF_B);
    u16* sHl = (u16*)(dyn + 35840);
    u16* sW2 = (u16*)(dyn + EOFF_W2);
    float* sm_p = (float*)(dyn + EOFF_W2);

    __shared__ int s_src[64], s_dst[64];
    __shared__ float s_b1[512], s_b2[64], s_g[64], s_bb[64];
    __shared__ float s_mu[64], s_rs[64];

    const int tid = threadIdx.x;
    const int lane = tid & 31;
    const int w = tid >> 5;
    const int g = lane >> 2;
    const int t = lane & 3;
    const int mgrp = w & 1;
    const int ngrp = w >> 1;
    const int m0 = mgrp * 32;
    const int b = blockIdx.y;
    const int e0 = blockIdx.x * 64;

    if (tid < 64) {
        s_src[tid] = eidx[e0 + tid];
        s_dst[tid] = eidx[NEDGE + e0 + tid];
    }
    for (int i = tid; i < 512; i += 256) s_b1[i] = be1[l * HD + i];
    if (tid < 64) {
        s_b2[tid] = be2[l * ED + tid];
        s_g[tid]  = geW[l * ED + tid];
        s_bb[tid] = bleW[l * ED + tid];
    }

    const float* eb = g_e + (size_t)b * NEDGE * ED;
    const u16* W1 = gW1T + (size_t)l * HD * K1E;
    const u16* W2 = gW2T + (size_t)l * ED * HD;
    const u16* Ps = g_psrc + (size_t)b * NNODE * HD;
    const u16* Pd = g_pdst + (size_t)b * NNODE * HD;

    #pragma unroll
    for (int j = 0; j < 4; j++) {
        int lin = j * 256 + tid;
        int r = lin >> 4, kl = (lin & 15) * 4;
        float4 v = *(const float4*)(eb + (size_t)(e0 + r) * ED + kl);
        u16 h0 = hf(v.x), h1 = hf(v.y), h2 = hf(v.z), h3 = hf(v.w);
        u16 l0 = hf(v.x - hf_f(h0)), l1 = hf(v.y - hf_f(h1));
        u16 l2 = hf(v.z - hf_f(h2)), l3 = hf(v.w - hf_f(h3));
        size_t o = (size_t)r * SAS + kl;
        *(ull*)((u16*)dyn + o)        = (ull)h0 | ((ull)h1 << 16) | ((ull)h2 << 32) | ((ull)h3 << 48);
        *(ull*)((u16*)dyn + 4608 + o) = (ull)l0 | ((ull)l1 << 16) | ((ull)l2 << 32) | ((ull)l3 << 48);
    }

    const u32 dynBase = smem_u32(dyn);
    u32 aOff[2];
    #pragma unroll
    for (int i = 0; i < 2; i++)
        aOff[i] = (u32)((m0 + i * 16 + (lane & 15)) * SAS * 2 + (lane >> 4) * 16);
    const u32 bBase = dynBase + EOFF_B
                    + (ngrp * 32 + (lane & 7)) * SB * 2 + ((lane >> 3) & 1) * 16;
    const u32 hH = dynBase + EOFF_B + (m0 + (lane & 15)) * SH * 2 + (lane >> 4) * 16;
    const u32 hL = hH + 17408;
    const u32 wBase = dynBase + EOFF_W2
                    + (ngrp * 16 + (lane & 7)) * SH * 2 + ((lane >> 3) & 1) * 16;

    float acc2[2][2][4];
    #pragma unroll
    for (int i = 0; i < 2; i++)
        #pragma unroll
        for (int j = 0; j < 2; j++)
            #pragma unroll
            for (int q = 0; q < 4; q++) acc2[i][j][q] = 0.0f;

    for (int nc = 0; nc < 4; nc++) {
        #pragma unroll
        for (int j = 0; j < 4; j++) {
            int lin = j * 256 + tid;
            int n = lin >> 3, q = lin & 7;
            *(uint4*)(sB + n * SB + q * 8) =
                *(const uint4*)(W1 + (size_t)(nc * 128 + n) * K1E + q * 8);
        }
        #pragma unroll
        for (int j = 0; j < 4; j++) {
            int lin = j * 256 + tid;
            int n = lin >> 4, q = lin & 15;
            *(uint4*)(sW2 + n * SH + q * 8) =
                *(const uint4*)(W2 + (size_t)n * HD + nc * 128 + q * 8);
        }
        __syncthreads();

        float acc1[2][4][4];
        #pragma unroll
        for (int i = 0; i < 2; i++)
            #pragma unroll
            for (int j = 0; j < 4; j++)
                #pragma unroll
                for (int q = 0; q < 4; q++) acc1[i][j][q] = 0.0f;

        #pragma unroll
        for (int ks = 0; ks < 4; ks++) {
            int kA = ks * 32;
            u32 ah[2][4], al[2][4];
            ldm_x4(ah[0], dynBase + aOff[0] + kA);
            ldm_x4(ah[1], dynBase + aOff[1] + kA);
            ldm_x4(al[0], dynBase + 9216 + aOff[0] + kA);
            ldm_x4(al[1], dynBase + 9216 + aOff[1] + kA);
            #pragma unroll
            for (int j = 0; j < 4; j++) {
                u32 bh0, bh1;
                ldm_x2(bh0, bh1, bBase + j * (8 * SB * 2) + ks * 32);
                #pragma unroll
                for (int i = 0; i < 2; i++) {
                    mma16816(acc1[i][j], ah[i], bh0, bh1);
                    mma16816(acc1[i][j], al[i], bh0, bh1);
                }
            }
        }

        // add gathered P_src + P_dst (fp16 pairs)
        #pragma unroll
        for (int i = 0; i < 2; i++)
            #pragma unroll
            for (int j = 0; j < 4; j++) {
                int c = nc * 128 + ngrp * 32 + j * 8 + 2 * t;
                int r0 = m0 + i * 16 + g, r1 = r0 + 8;
                float2 p0 = h2f(*(const u32*)(Ps + (size_t)s_src[r0] * HD + c));
                float2 q0 = h2f(*(const u32*)(Pd + (size_t)s_dst[r0] * HD + c));
                acc1[i][j][0] += p0.x + q0.x;
                acc1[i][j][1] += p0.y + q0.y;
                float2 p1 = h2f(*(const u32*)(Ps + (size_t)s_src[r1] * HD + c));
                float2 q1 = h2f(*(const u32*)(Pd + (size_t)s_dst[r1] * HD + c));
                acc1[i][j][2] += p1.x + q1.x;
                acc1[i][j][3] += p1.y + q1.y;
            }
        __syncthreads();

        // silu + bias -> H (fp16 hi/lo)
        #pragma unroll
        for (int i = 0; i < 2; i++)
            #pragma unroll
            for (int j = 0; j < 4; j++) {
                int col = ngrp * 32 + j * 8 + 2 * t;
                int bc = nc * 128 + col;
                int r0 = m0 + i * 16 + g, r1 = r0 + 8;
                float v0 = silu_f(acc1[i][j][0] + s_b1[bc]);
                float v1 = silu_f(acc1[i][j][1] + s_b1[bc + 1]);
                float v2 = silu_f(acc1[i][j][2] + s_b1[bc]);
                float v3 = silu_f(acc1[i][j][3] + s_b1[bc + 1]);
                u16 h0 = hf(v0), h1 = hf(v1), h2 = hf(v2), h3 = hf(v3);
                *(u32*)(sHh + r0 * SH + col) = (u32)h0 | ((u32)h1 << 16);
                *(u32*)(sHh + r1 * SH + col) = (u32)h2 | ((u32)h3 << 16);
                u16 q0 = hf(v0 - hf_f(h0)), q1 = hf(v1 - hf_f(h1));
                u16 q2 = hf(v2 - hf_f(h2)), q3 = hf(v3 - hf_f(h3));
                *(u32*)(sHl + r0 * SH + col) = (u32)q0 | ((u32)q1 << 16);
                *(u32*)(sHl + r1 * SH + col) = (u32)q2 | ((u32)q3 << 16);
            }
        __syncthreads();

        // GEMM2: acc2 += (Hh + Hl) @ W2
        #pragma unroll
        for (int ks = 0; ks < 8; ks++) {
            int k0 = (ks * 16) * 2;
            u32 ah[2][4], al[2][4];
            ldm_x4(ah[0], hH + k0); ldm_x4(ah[1], hH + 16 * SH * 2 + k0);
            ldm_x4(al[0], hL + k0); ldm_x4(al[1], hL + 16 * SH * 2 + k0);
            #pragma unroll
            for (int j = 0; j < 2; j++) {
                u32 bh0, bh1;
                ldm_x2(bh0, bh1, wBase + j * (8 * SH * 2) + k0);
                #pragma unroll
                for (int i = 0; i < 2; i++) {
                    mma16816(acc2[i][j], ah[i], bh0, bh1);
                    mma16816(acc2[i][j], al[i], bh0, bh1);
                }
            }
        }
        __syncthreads();
    }

    // epilogue
    #pragma unroll
    for (int i = 0; i < 2; i++)
        #pragma unroll
        for (int j = 0; j < 2; j++) {
            int col = ngrp * 16 + j * 8 + 2 * t;
            int r0 = m0 + i * 16 + g, r1 = r0 + 8;
            sm_p[r0 * 68 + col]     = acc2[i][j][0] + s_b2[col];
            sm_p[r0 * 68 + col + 1] = acc2[i][j][1] + s_b2[col + 1];
            sm_p[r1 * 68 + col]     = acc2[i][j][2] + s_b2[col];
            sm_p[r1 * 68 + col + 1] = acc2[i][j][3] + s_b2[col + 1];
        }
    __syncthreads();
    {
        int r = tid >> 2, sub = tid & 3;
        float s = 0.f, s2 = 0.f;
        #pragma unroll
        for (int cc = 0; cc < 16; cc++) {
            float v = sm_p[r * 68 + sub * 16 + cc];
            s += v; s2 += v * v;
        }
        s  += __shfl_xor_sync(0xffffffffu, s, 1);
        s  += __shfl_xor_sync(0xffffffffu, s, 2);
        s2 += __shfl_xor_sync(0xffffffffu, s2, 1);
        s2 += __shfl_xor_sync(0xffffffffu, s2, 2);
        if (sub == 0) {
            float mu = s * (1.0f / 64.0f);
            s_mu[r] = mu;
            s_rs[r] = rsqrtf(s2 * (1.0f / 64.0f) - mu * mu + 1e-5f);
        }
    }
    __syncthreads();
    {
        int c = tid & 63, grp = tid >> 6;
        float gv = s_g[c], bv = s_bb[c];
        float* eo = g_e + (size_t)b * NEDGE * ED;
        float* ag = g_agg + (size_t)b * NNODE * ED;
        #pragma unroll 4
        for (int rr = 0; rr < 16; rr++) {
            int r = grp * 16 + rr;
            float p = sm_p[r * 68 + c];
            float en = eo[(size_t)(e0 + r) * ED + c]
                     + (p - s_mu[r]) * s_rs[r] * gv + bv;
            eo[(size_t)(e0 + r) * ED + c] = en;
            atomicAdd(ag + (size_t)s_dst[r] * ED + c, en);
        }
    }
}

// ===================== NODE KERNEL (validated R14) ===================
#define NOFF_B (2 * ABUF)
#define NODE_DSMEM (NOFF_B + 2 * BUFSZ)

__global__ void __launch_bounds__(256, 2)
node_kernel_mma(float* __restrict__ x,
                const float* __restrict__ bn1, const float* __restrict__ bn2,
                const float* __restrict__ gnW, const float* __restrict__ blnW, int l)
{
    extern __shared__ char dyn[];
    u16* sHh = (u16*)(dyn);
    u16* sHl = sHh + 64 * SH;
    u16* sW2 = (u16*)(dyn + NOFF_B);
    float* sm_p = (float*)(dyn);

    __shared__ float s_b1[512], s_b2[256], s_g[256], s_bb[256];
    __shared__ float s_mu[64], s_rs[64];

    const int tid = threadIdx.x;
    const int lane = tid & 31;
    const int w = tid >> 5;
    const int g = lane >> 2;
    const int t = lane & 3;
    const int mgrp = w & 1;
    const int ngrp = w >> 1;
    const int m0 = mgrp * 32;
    const int b = blockIdx.y;
    const int n0 = blockIdx.x * 64;

    for (int i = tid; i < 512; i += 256) s_b1[i] = bn1[l * HD + i];
    if (tid < 256) {
        s_b2[tid] = bn2[l * ND + tid];
        s_g[tid]  = gnW[l * ND + tid];
        s_bb[tid] = blnW[l * ND + tid];
    }
    __syncthreads();

    const float* xb = x + (size_t)b * NNODE * ND;
    const float* ab = g_agg + (size_t)b * NNODE * ED;

    const u16* W1 = gWn1T + (size_t)l * HD * K1N;
    const u16* W2 = gWn2T + (size_t)l * ND * HD;

    u32 aOff[2];
    #pragma unroll
    for (int i = 0; i < 2; i++)
        aOff[i] = (u32)((m0 + i * 16 + (lane & 15)) * SAS * 2 + (lane >> 4) * 16);
    const u32 dynBase = smem_u32(dyn);
    const u32 bBase = dynBase + NOFF_B
                    + (ngrp * 32 + (lane & 7)) * SB * 2 + ((lane >> 3) & 1) * 16;
    const u32 hH = dynBase + (m0 + (lane & 15)) * SH * 2 + (lane >> 4) * 16;
    const u32 hL = hH + 17408;
    const u32 wBase = dynBase + NOFF_B
                    + (ngrp * 64 + (lane & 7)) * SB * 2 + ((lane >> 3) & 1) * 16;

    const int nlin = tid >> 3, qlin = tid & 7;

    float acc2[2][8][4];
    #pragma unroll
    for (int i = 0; i < 2; i++)
        #pragma unroll
        for (int j = 0; j < 8; j++)
            #pragma unroll
            for (int q = 0; q < 4; q++) acc2[i][j][q] = 0.0f;

    for (int nc = 0; nc < 4; nc++) {
        float acc1[2][4][4];
        #pragma unroll
        for (int i = 0; i < 2; i++)
            #pragma unroll
            for (int j = 0; j < 4; j++)
                #pragma unroll
                for (int q = 0; q < 4; q++) acc1[i][j][q] = 0.0f;

        #pragma unroll
        for (int j = 0; j < 4; j++) {
            int n = j * 32 + nlin;
            cp16(dynBase + NOFF_B + (n * SB + qlin * 8) * 2,
                 W1 + (size_t)(nc * 128 + n) * K1N + qlin * 8);
        }
        cp_commit();
        #pragma unroll
        for (int j = 0; j < 4; j++) {
            int lin = j * 256 + tid;
            int r = lin >> 4, kl = (lin & 15) * 4;
            int node = min(n0 + r, NNODE - 1);
            float4 v = (kl < 256) ? *(const float4*)(xb + (size_t)node * ND + kl)
                                  : *(const float4*)(ab + (size_t)node * ED + (kl - 256));
            u16 h0 = hf(v.x), h1 = hf(v.y), h2 = hf(v.z), h3 = hf(v.w);
            u16 l0 = hf(v.x - hf_f(h0)), l1 = hf(v.y - hf_f(h1));
            u16 l2 = hf(v.z - hf_f(h2)), l3 = hf(v.w - hf_f(h3));
            size_t o = (size_t)r * SAS + kl;
            *(ull*)((u16*)dyn + o)        = (ull)h0 | ((ull)h1 << 16) | ((ull)h2 << 32) | ((ull)h3 << 48);
            *(ull*)((u16*)dyn + 4608 + o) = (ull)l0 | ((ull)l1 << 16) | ((ull)l2 << 32) | ((ull)l3 << 48);
        }
        cp_wait0();
        __syncthreads();

        for (int kc = 0; kc < 5; kc++) {
            int cur = kc & 1;
            if (kc < 4) {
                u32 dst = dynBase + NOFF_B + (cur ^ 1) * BUFSZ;
                #pragma unroll
                for (int j = 0; j < 4; j++) {
                    int n = j * 32 + nlin;
                    cp16(dst + (n * SB + qlin * 8) * 2,
                         W1 + (size_t)(nc * 128 + n) * K1N + (kc + 1) * 64 + qlin * 8);
                }
                cp_commit();
            }
            const u32 curB = bBase + cur * BUFSZ;
            const u32 aBaseH = dynBase + cur * ABUF;
            const u32 aBaseL = aBaseH + 9216;
            #pragma unroll
            for (int ks = 0; ks < 4; ks++) {
                int kA = ks * 32;
                u32 ah[2][4], al[2][4];
                ldm_x4(ah[0], aBaseH + aOff[0] + kA); ldm_x4(ah[1], aBaseH + aOff[1] + kA);
                ldm_x4(al[0], aBaseL + aOff[0] + kA); ldm_x4(al[1], aBaseL + aOff[1] + kA);
                int kB = ks * 32;
                #pragma unroll
                for (int j = 0; j < 4; j++) {
                    u32 bh0, bh1;
                    ldm_x2(bh0, bh1, curB + j * (8 * SB * 2) + kB);
                    #pragma unroll
                    for (int i = 0; i < 2; i++) {
                        mma16816(acc1[i][j], ah[i], bh0, bh1);
                        mma16816(acc1[i][j], al[i], bh0, bh1);
                    }
                }
            }
            if (kc < 4) {
                u16* aDstH = (u16*)(dyn + (cur ^ 1) * ABUF);
                #pragma unroll
                for (int j = 0; j < 4; j++) {
                    int lin = j * 256 + tid;
                    int r = lin >> 4, kl = (lin & 15) * 4;
                    int k = (kc + 1) * 64 + kl;
                    int node = min(n0 + r, NNODE - 1);
                    float4 v = (k < 256) ? *(const float4*)(xb + (size_t)node * ND + k)
                                         : *(const float4*)(ab + (size_t)node * ED + (k - 256));
                    u16 h0 = hf(v.x), h1 = hf(v.y), h2 = hf(v.z), h3 = hf(v.w);
                    u16 l0 = hf(v.x - hf_f(h0)), l1 = hf(v.y - hf_f(h1));
                    u16 l2 = hf(v.z - hf_f(h2)), l3 = hf(v.w - hf_f(h3));
                    size_t o = (size_t)r * SAS + kl;
                    *(ull*)(aDstH + o)        = (ull)h0 | ((ull)h1 << 16) | ((ull)h2 << 32) | ((ull)h3 << 48);
                    *(ull*)(aDstH + 4608 + o) = (ull)l0 | ((ull)l1 << 16) | ((ull)l2 << 32) | ((ull)l3 << 48);
                }
                cp_wait0();
            }
            __syncthreads();
        }

        #pragma unroll
        for (int i = 0; i < 2; i++)
            #pragma unroll
            for (int j = 0; j < 4; j++) {
                int col = ngrp * 32 + j * 8 + 2 * t;
                int bc = nc * 128 + col;
                int r0 = m0 + i * 16 + g, r1 = r0 + 8;
                float v0 = silu_f(acc1[i][j][0] + s_b1[bc]);
                float v1 = silu_f(acc1[i][j][1] + s_b1[bc + 1]);
                float v2 = silu_f(acc1[i][j][2] + s_b1[bc]);
                float v3 = silu_f(acc1[i][j][3] + s_b1[bc + 1]);
                u16 h0 = hf(v0), h1 = hf(v1), h2 = hf(v2), h3 = hf(v3);
                *(u32*)(sHh + r0 * SH + col) = (u32)h0 | ((u32)h1 << 16);
                *(u32*)(sHh + r1 * SH + col) = (u32)h2 | ((u32)h3 << 16);
                u16 q0 = hf(v0 - hf_f(h0)), q1 = hf(v1 - hf_f(h1));
                u16 q2 = hf(v2 - hf_f(h2)), q3 = hf(v3 - hf_f(h3));
                *(u32*)(sHl + r0 * SH + col) = (u32)q0 | ((u32)q1 << 16);
                *(u32*)(sHl + r1 * SH + col) = (u32)q2 | ((u32)q3 << 16);
            }
        __syncthreads();

        for (int s = 0; s < 2; s++) {
            for (int i = tid; i < 2048; i += 256) {
                int n = i >> 3, q = i & 7;
                *(uint4*)(sW2 + n * SB + q * 8) =
                    *(const uint4*)(W2 + (size_t)n * HD + nc * 128 + s * 64 + q * 8);
            }
            __syncthreads();
            #pragma unroll
            for (int ks = 0; ks < 4; ks++) {
                int kH = (s * 64 + ks * 16) * 2;
                int kW = (ks * 16) * 2;
                u32 ah[2][4], al[2][4];
                ldm_x4(ah[0], hH + kH); ldm_x4(ah[1], hH + 16 * SH * 2 + kH);
                ldm_x4(al[0], hL + kH); ldm_x4(al[1], hL + 16 * SH * 2 + kH);
                #pragma unroll
                for (int j = 0; j < 8; j++) {
                    u32 bh0, bh1;
                    ldm_x2(bh0, bh1, wBase + j * (8 * SB * 2) + kW);
                    #pragma unroll
                    for (int i = 0; i < 2; i++) {
                        mma16816(acc2[i][j], ah[i], bh0, bh1);
                        mma16816(acc2[i][j], al[i], bh0, bh1);
                    }
                }
            }
            __syncthreads();
        }
    }

    #pragma unroll
    for (int i = 0; i < 2; i++)
        #pragma unroll
        for (int j = 0; j < 8; j++) {
            int col = ngrp * 64 + j * 8 + 2 * t;
            int r0 = m0 + i * 16 + g, r1 = r0 + 8;
            sm_p[r0 * 260 + col]     = acc2[i][j][0] + s_b2[col];
            sm_p[r0 * 260 + col + 1] = acc2[i][j][1] + s_b2[col + 1];
            sm_p[r1 * 260 + col]     = acc2[i][j][2] + s_b2[col];
            sm_p[r1 * 260 + col + 1] = acc2[i][j][3] + s_b2[col + 1];
        }
    __syncthreads();
    {
        int r = tid >> 2, sub = tid & 3;
        float s = 0.f, s2 = 0.f;
        #pragma unroll 8
        for (int cc = 0; cc < 64; cc++) {
            float v = sm_p[r * 260 + sub * 64 + cc];
            s += v; s2 += v * v;
        }
        s  += __shfl_xor_sync(0xffffffffu, s, 1);
        s  += __shfl_xor_sync(0xffffffffu, s, 2);
        s2 += __shfl_xor_sync(0xffffffffu, s2, 1);
        s2 += __shfl_xor_sync(0xffffffffu, s2, 2);
        if (sub == 0) {
            float mu = s * (1.0f / 256.0f);
            s_mu[r] = mu;
            s_rs[r] = rsqrtf(s2 * (1.0f / 256.0f) - mu * mu + 1e-5f);
        }
    }
    __syncthreads();
    {
        int c = tid;
        float gv = s_g[c], bv = s_bb[c];
        float* xo = x + (size_t)b * NNODE * ND;
        for (int rr = 0; rr < 64; rr++) {
            if (n0 + rr < NNODE) {
                float v = sm_p[rr * 260 + c];
                size_t o = (size_t)(n0 + rr) * ND + c;
                xo[o] = xo[o] + (v - s_mu[rr]) * s_rs[rr] * gv + bv;
            }
        }
    }
}

// ============================== LAUNCH ===============================
extern "C" void kernel_launch(void* const* d_in, const int* in_sizes, int n_in,
                              void* d_out, int out_size) {
    const float* nf  = (const float*)d_in[0];
    const float* ef  = (const float*)d_in[1];
    const float* We1 = (const float*)d_in[2];
    const float* be1 = (const float*)d_in[3];
    const float* We2 = (const float*)d_in[4];
    const float* be2 = (const float*)d_in[5];
    const float* geW = (const float*)d_in[6];
    const float* ble = (const float*)d_in[7];
    const float* Wn1 = (const float*)d_in[8];
    const float* bn1 = (const float*)d_in[9];
    const float* Wn2 = (const float*)d_in[10];
    const float* bn2 = (const float*)d_in[11];
    const float* gnW = (const float*)d_in[12];
    const float* bln = (const float*)d_in[13];
    const int*  eidx = (const int*)d_in[14];
    float* x = (float*)d_out;

    cudaFuncSetAttribute(precompute_p, cudaFuncAttributeMaxDynamicSharedMemorySize, PRE_DSMEM);
    cudaFuncSetAttribute(edge_kernel_mma, cudaFuncAttributeMaxDynamicSharedMemorySize, EDGE_DSMEM);
    cudaFuncSetAttribute(node_kernel_mma, cudaFuncAttributeMaxDynamicSharedMemorySize, NODE_DSMEM);

    prep_w1<<<2048, 256>>>(We1);
    prep_w2<<<512, 256>>>(We2);
    prep_wn1<<<1024, 256>>>(Wn1);
    prep_wn2<<<1024, 256>>>(Wn2);

    cudaMemcpyAsync(x, nf, sizeof(float) * (size_t)NB * NNODE * ND,
                    cudaMemcpyDeviceToDevice, 0);
    size_t ebytes = sizeof(float) * (size_t)NEDGE * ED;
    cudaMemcpyToSymbolAsync(g_e, ef, ebytes, 0, cudaMemcpyDeviceToDevice, 0);
    cudaMemcpyToSymbolAsync(g_e, ef, ebytes, ebytes, cudaMemcpyDeviceToDevice, 0);

    dim3 pg((NNODE + 63) / 64, NB);
    dim3 eg(NEDGE / 64, NB);
    dim3 ng((NNODE + 63) / 64, NB);
    for (int l = 0; l < NL; l++) {
        precompute_p<<<pg, 256, PRE_DSMEM>>>(x, l);
        edge_kernel_mma<<<eg, 256, EDGE_DSMEM>>>(x, eidx, be1, be2, geW, ble, l);
        node_kernel_mma<<<ng, 256, NODE_DSMEM>>>(x, bn1, bn2, gnW, bln, l);
    }
}

// round 17
// speedup vs baseline: 11.4900x; 1.1332x over previous
#include <cuda_runtime.h>
#include <cuda_fp16.h>
#include <cstdint>

#define NB 2
#define NNODE 40962
#define NEDGE 327680
#define ND 256
#define ED 64
#define HD 512
#define NL 16
#define K1E 576
#define K1N 320

typedef unsigned long long ull;
typedef unsigned int u32;
typedef unsigned short u16;

// ----------------------------- scratch ------------------------------
__device__ float g_e[(size_t)NB * NEDGE * ED];
__device__ float g_agg[(size_t)NB * NNODE * ED];
__device__ u16 g_psrc[(size_t)NB * NNODE * HD];   // fp16: x @ W1[64:320)
__device__ u16 g_pdst[(size_t)NB * NNODE * HD];   // fp16: x @ W1[320:576)
__device__ u16 gW1T[(size_t)NL * HD * K1E];
__device__ u16 gW2T[(size_t)NL * ED * HD];
__device__ u16 gWn1T[(size_t)NL * HD * K1N];
__device__ u16 gWn2T[(size_t)NL * ND * HD];

// --------------------------- helpers --------------------------------
__device__ __forceinline__ u16 hf(float v) {
    return __half_as_ushort(__float2half_rn(v));
}
__device__ __forceinline__ float hf_f(u16 h) {
    return __half2float(__ushort_as_half(h));
}
__device__ __forceinline__ float2 h2f(u32 v) {
    __half2 h = *reinterpret_cast<__half2*>(&v);
    return __half22float2(h);
}
__device__ __forceinline__ float silu_f(float v) {
    return __fdividef(v, 1.0f + __expf(-v));
}
__device__ __forceinline__ u32 smem_u32(const void* p) {
    u32 a; asm("{ .reg .u64 t; cvta.to.shared.u64 t, %1; cvt.u32.u64 %0, t; }"
               : "=r"(a) : "l"(p));
    return a;
}
__device__ __forceinline__ void mma16816(float* d, const u32* a, u32 b0, u32 b1) {
    asm volatile(
        "mma.sync.aligned.m16n8k16.row.col.f32.f16.f16.f32 "
        "{%0,%1,%2,%3}, {%4,%5,%6,%7}, {%8,%9}, {%0,%1,%2,%3};"
        : "+f"(d[0]), "+f"(d[1]), "+f"(d[2]), "+f"(d[3])
        : "r"(a[0]), "r"(a[1]), "r"(a[2]), "r"(a[3]), "r"(b0), "r"(b1));
}
__device__ __forceinline__ void ldm_x4(u32* r, u32 a) {
    asm volatile("ldmatrix.sync.aligned.m8n8.x4.shared.b16 {%0,%1,%2,%3}, [%4];"
        : "=r"(r[0]), "=r"(r[1]), "=r"(r[2]), "=r"(r[3]) : "r"(a));
}
__device__ __forceinline__ void ldm_x2(u32& r0, u32& r1, u32 a) {
    asm volatile("ldmatrix.sync.aligned.m8n8.x2.shared.b16 {%0,%1}, [%2];"
        : "=r"(r0), "=r"(r1) : "r"(a));
}
__device__ __forceinline__ void cp16(u32 sdst, const void* gsrc) {
    asm volatile("cp.async.cg.shared.global [%0], [%1], 16;"
                 :: "r"(sdst), "l"(gsrc) : "memory");
}
__device__ __forceinline__ void cp_commit() {
    asm volatile("cp.async.commit_group;" ::: "memory");
}
__device__ __forceinline__ void cp_wait0() {
    asm volatile("cp.async.wait_group 0;" ::: "memory");
}

// --------------------------- prep kernel (merged) --------------------
__global__ void prep_all(const float* __restrict__ We1, const float* __restrict__ We2,
                         const float* __restrict__ Wn1, const float* __restrict__ Wn2)
{
    const size_t stride = (size_t)gridDim.x * blockDim.x;
    const size_t t0 = (size_t)blockIdx.x * blockDim.x + threadIdx.x;
    {
        size_t tot = (size_t)NL * K1E * HD;
        for (size_t i = t0; i < tot; i += stride) {
            size_t l = i / ((size_t)K1E * HD);
            size_t rem = i - l * (size_t)K1E * HD;
            size_t k = rem / HD, n = rem - k * HD;
            gW1T[(l * HD + n) * K1E + k] = hf(We1[i]);
        }
    }
    {
        size_t tot = (size_t)NL * HD * ED;
        for (size_t i = t0; i < tot; i += stride) {
            size_t l = i / ((size_t)HD * ED);
            size_t rem = i - l * (size_t)HD * ED;
            size_t k = rem / ED, n = rem - k * ED;
            gW2T[(l * ED + n) * HD + k] = hf(We2[i]);
        }
    }
    {
        size_t tot = (size_t)NL * K1N * HD;
        for (size_t i = t0; i < tot; i += stride) {
            size_t l = i / ((size_t)K1N * HD);
            size_t rem = i - l * (size_t)K1N * HD;
            size_t k = rem / HD, n = rem - k * HD;
            gWn1T[(l * HD + n) * K1N + k] = hf(Wn1[i]);
        }
    }
    {
        size_t tot = (size_t)NL * HD * ND;
        for (size_t i = t0; i < tot; i += stride) {
            size_t l = i / ((size_t)HD * ND);
            size_t rem = i - l * (size_t)HD * ND;
            size_t k = rem / ND, n = rem - k * ND;
            gWn2T[(l * ND + n) * HD + k] = hf(Wn2[i]);
        }
    }
}

// strides (u16 units)
#define SAS 72    /* small A row stride (64k + 8 pad) */
#define SAP 264   /* precompute A row stride (256k + 8 pad) */
#define SB 72     /* B slab row stride */
#define SH 136    /* h / edge-W2 row stride */
#define SP 136    /* staged-P row stride (128 cols + 8 pad) */
#define ABUF 18432
#define BUFSZ 18432

// ===================== PRECOMPUTE KERNEL =============================
#define POFF_B 67584                   /* 2 * 64*SAP*2 */
#define PRE_DSMEM (POFF_B + 2 * BUFSZ) /* 104448 */

__global__ void __launch_bounds__(256, 2)
precompute_p(const float* __restrict__ x, int l)
{
    extern __shared__ char dyn[];

    const int tid = threadIdx.x;
    const int lane = tid & 31;
    const int w = tid >> 5;
    const int g = lane >> 2;
    const int t = lane & 3;
    const int mgrp = w & 1;
    const int ngrp = w >> 1;
    const int m0 = mgrp * 32;
    const int b = blockIdx.y;
    const int n0 = blockIdx.x * 64;

    const float* xb = x + (size_t)b * NNODE * ND;
    const u16* W1 = gW1T + (size_t)l * HD * K1E;

    // zero this block's agg slice
    {
        float* ag = g_agg + (size_t)b * NNODE * ED;
        float4 z = make_float4(0.f, 0.f, 0.f, 0.f);
        for (int i = tid; i < 64 * 16; i += 256) {
            int r = i >> 4, q = i & 15;
            if (n0 + r < NNODE)
                ((float4*)(ag + (size_t)(n0 + r) * ED))[q] = z;
        }
    }

    // convert A resident: 64 x 256 fp32 -> fp16 hi/lo
    for (int j = 0; j < 16; j++) {
        int lin = j * 256 + tid;
        int r = lin >> 6, kl = (lin & 63) * 4;
        int node = min(n0 + r, NNODE - 1);
        float4 v = *(const float4*)(xb + (size_t)node * ND + kl);
        u16 h0 = hf(v.x), h1 = hf(v.y), h2 = hf(v.z), h3 = hf(v.w);
        u16 l0 = hf(v.x - hf_f(h0)), l1 = hf(v.y - hf_f(h1));
        u16 l2 = hf(v.z - hf_f(h2)), l3 = hf(v.w - hf_f(h3));
        size_t o = (size_t)r * SAP + kl;
        *(ull*)((u16*)dyn + o)         = (ull)h0 | ((ull)h1 << 16) | ((ull)h2 << 32) | ((ull)h3 << 48);
        *(ull*)((u16*)dyn + 16896 + o) = (ull)l0 | ((ull)l1 << 16) | ((ull)l2 << 32) | ((ull)l3 << 48);
    }
    __syncthreads();

    const u32 dynBase = smem_u32(dyn);
    u32 aOff[2];
    #pragma unroll
    for (int i = 0; i < 2; i++)
        aOff[i] = (u32)((m0 + i * 16 + (lane & 15)) * SAP * 2 + (lane >> 4) * 16);
    const u32 bBase = dynBase + POFF_B
                    + (ngrp * 32 + (lane & 7)) * SB * 2 + ((lane >> 3) & 1) * 16;
    const int nlin = tid >> 3, qlin = tid & 7;

    for (int mat = 0; mat < 2; mat++) {
        u16* P = (mat ? g_pdst : g_psrc) + (size_t)b * NNODE * HD;
        const int kb = 64 + mat * 256;

        for (int nc = 0; nc < 4; nc++) {
            float acc[2][4][4];
            #pragma unroll
            for (int i = 0; i < 2; i++)
                #pragma unroll
                for (int j = 0; j < 4; j++)
                    #pragma unroll
                    for (int q = 0; q < 4; q++) acc[i][j][q] = 0.0f;

            #pragma unroll
            for (int j = 0; j < 4; j++) {
                int n = j * 32 + nlin;
                cp16(dynBase + POFF_B + (n * SB + qlin * 8) * 2,
                     W1 + (size_t)(nc * 128 + n) * K1E + kb + qlin * 8);
            }
            cp_commit(); cp_wait0();
            __syncthreads();

            for (int kc = 0; kc < 4; kc++) {
                int cur = kc & 1;
                if (kc < 3) {
                    u32 dst = dynBase + POFF_B + (cur ^ 1) * BUFSZ;
                    #pragma unroll
                    for (int j = 0; j < 4; j++) {
                        int n = j * 32 + nlin;
                        cp16(dst + (n * SB + qlin * 8) * 2,
                             W1 + (size_t)(nc * 128 + n) * K1E + kb + (kc + 1) * 64 + qlin * 8);
                    }
                    cp_commit();
                }
                const u32 curB = bBase + cur * BUFSZ;
                #pragma unroll
                for (int ks = 0; ks < 4; ks++) {
                    int kA = (kc * 64 + ks * 16) * 2;
                    u32 ah[2][4], al[2][4];
                    ldm_x4(ah[0], dynBase + aOff[0] + kA);
                    ldm_x4(ah[1], dynBase + aOff[1] + kA);
                    ldm_x4(al[0], dynBase + 33792 + aOff[0] + kA);
                    ldm_x4(al[1], dynBase + 33792 + aOff[1] + kA);
                    int kB = ks * 32;
                    #pragma unroll
                    for (int j = 0; j < 4; j++) {
                        u32 bh0, bh1;
                        ldm_x2(bh0, bh1, curB + j * (8 * SB * 2) + kB);
                        #pragma unroll
                        for (int i = 0; i < 2; i++) {
                            mma16816(acc[i][j], ah[i], bh0, bh1);
                            mma16816(acc[i][j], al[i], bh0, bh1);
                        }
                    }
                }
                if (kc < 3) cp_wait0();
                __syncthreads();
            }

            #pragma unroll
            for (int i = 0; i < 2; i++)
                #pragma unroll
                for (int j = 0; j < 4; j++) {
                    int c = nc * 128 + ngrp * 32 + j * 8 + 2 * t;
                    int r0 = m0 + i * 16 + g, r1 = r0 + 8;
                    if (n0 + r0 < NNODE)
                        *(u32*)(P + (size_t)(n0 + r0) * HD + c) =
                            (u32)hf(acc[i][j][0]) | ((u32)hf(acc[i][j][1]) << 16);
                    if (n0 + r1 < NNODE)
                        *(u32*)(P + (size_t)(n0 + r1) * HD + c) =
                            (u32)hf(acc[i][j][2]) | ((u32)hf(acc[i][j][3]) << 16);
                }
        }
    }
}

// ===================== EDGE KERNEL (factored + staged P) =============
#define EOFF_B 18432
#define EOFF_W2 53248
#define EOFF_P 70656
#define EDGE_DSMEM (EOFF_P + 34816)   /* 105472 */

__global__ void __launch_bounds__(256, 2)
edge_kernel_mma(const int* __restrict__ eidx,
                const float* __restrict__ be1, const float* __restrict__ be2,
                const float* __restrict__ geW, const float* __restrict__ bleW, int l)
{
    extern __shared__ char dyn[];
    u16* sB  = (u16*)(dyn + EOFF_B);
    u16* sHh = (u16*)(dyn + EOFF_B);
    u16* sHl = (u16*)(dyn + 35840);
    u16* sW2 = (u16*)(dyn + EOFF_W2);
    u16* sP  = (u16*)(dyn + EOFF_P);       // [128 rows][SP] (src 0..63, dst 64..127)
    float* sm_p = (float*)(dyn + EOFF_W2);

    __shared__ int s_src[64], s_dst[64];
    __shared__ float s_b1[512], s_b2[64], s_g[64], s_bb[64];
    __shared__ float s_mu[64], s_rs[64];

    const int tid = threadIdx.x;
    const int lane = tid & 31;
    const int w = tid >> 5;
    const int g = lane >> 2;
    const int t = lane & 3;
    const int mgrp = w & 1;
    const int ngrp = w >> 1;
    const int m0 = mgrp * 32;
    const int b = blockIdx.y;
    const int e0 = blockIdx.x * 64;

    if (tid < 64) {
        s_src[tid] = eidx[e0 + tid];
        s_dst[tid] = eidx[NEDGE + e0 + tid];
    }
    for (int i = tid; i < 512; i += 256) s_b1[i] = be1[l * HD + i];
    if (tid < 64) {
        s_b2[tid] = be2[l * ED + tid];
        s_g[tid]  = geW[l * ED + tid];
        s_bb[tid] = bleW[l * ED + tid];
    }

    const float* eb = g_e + (size_t)b * NEDGE * ED;
    const u16* W1 = gW1T + (size_t)l * HD * K1E;
    const u16* W2 = gW2T + (size_t)l * ED * HD;
    const u16* Ps = g_psrc + (size_t)b * NNODE * HD;
    const u16* Pd = g_pdst + (size_t)b * NNODE * HD;

    // convert e tile (64 x 64) -> A hi/lo resident at dyn
    #pragma unroll
    for (int j = 0; j < 4; j++) {
        int lin = j * 256 + tid;
        int r = lin >> 4, kl = (lin & 15) * 4;
        float4 v = *(const float4*)(eb + (size_t)(e0 + r) * ED + kl);
        u16 h0 = hf(v.x), h1 = hf(v.y), h2 = hf(v.z), h3 = hf(v.w);
        u16 l0 = hf(v.x - hf_f(h0)), l1 = hf(v.y - hf_f(h1));
        u16 l2 = hf(v.z - hf_f(h2)), l3 = hf(v.w - hf_f(h3));
        size_t o = (size_t)r * SAS + kl;
        *(ull*)((u16*)dyn + o)        = (ull)h0 | ((ull)h1 << 16) | ((ull)h2 << 32) | ((ull)h3 << 48);
        *(ull*)((u16*)dyn + 4608 + o) = (ull)l0 | ((ull)l1 << 16) | ((ull)l2 << 32) | ((ull)l3 << 48);
    }
    __syncthreads();   // s_src/s_dst visible to all (needed by cp.async staging)

    const u32 dynBase = smem_u32(dyn);
    u32 aOff[2];
    #pragma unroll
    for (int i = 0; i < 2; i++)
        aOff[i] = (u32)((m0 + i * 16 + (lane & 15)) * SAS * 2 + (lane >> 4) * 16);
    const u32 bBase = dynBase + EOFF_B
                    + (ngrp * 32 + (lane & 7)) * SB * 2 + ((lane >> 3) & 1) * 16;
    const u32 hH = dynBase + EOFF_B + (m0 + (lane & 15)) * SH * 2 + (lane >> 4) * 16;
    const u32 hL = hH + 17408;
    const u32 wBase = dynBase + EOFF_W2
                    + (ngrp * 16 + (lane & 7)) * SH * 2 + ((lane >> 3) & 1) * 16;

    float acc2[2][2][4];
    #pragma unroll
    for (int i = 0; i < 2; i++)
        #pragma unroll
        for (int j = 0; j < 2; j++)
            #pragma unroll
            for (int q = 0; q < 4; q++) acc2[i][j][q] = 0.0f;

    for (int nc = 0; nc < 4; nc++) {
        // stage P tiles via cp.async (latency hidden under B loads + GEMM1)
        #pragma unroll
        for (int j = 0; j < 4; j++) {
            int lin = j * 256 + tid;
            int r = lin >> 4, q = lin & 15;
            cp16(dynBase + EOFF_P + (r * SP + q * 8) * 2,
                 Ps + (size_t)s_src[r] * HD + nc * 128 + q * 8);
        }
        #pragma unroll
        for (int j = 0; j < 4; j++) {
            int lin = j * 256 + tid;
            int r = lin >> 4, q = lin & 15;
            cp16(dynBase + EOFF_P + ((64 + r) * SP + q * 8) * 2,
                 Pd + (size_t)s_dst[r] * HD + nc * 128 + q * 8);
        }
        cp_commit();

        // B slab [128n][64k] + W2 chunk [64n][128k]
        #pragma unroll
        for (int j = 0; j < 4; j++) {
            int lin = j * 256 + tid;
            int n = lin >> 3, q = lin & 7;
            *(uint4*)(sB + n * SB + q * 8) =
                *(const uint4*)(W1 + (size_t)(nc * 128 + n) * K1E + q * 8);
        }
        #pragma unroll
        for (int j = 0; j < 4; j++) {
            int lin = j * 256 + tid;
            int n = lin >> 4, q = lin & 15;
            *(uint4*)(sW2 + n * SH + q * 8) =
                *(const uint4*)(W2 + (size_t)n * HD + nc * 128 + q * 8);
        }
        __syncthreads();

        float acc1[2][4][4];
        #pragma unroll
        for (int i = 0; i < 2; i++)
            #pragma unroll
            for (int j = 0; j < 4; j++)
                #pragma unroll
                for (int q = 0; q < 4; q++) acc1[i][j][q] = 0.0f;

        // GEMM1: e @ W1[0:64)
        #pragma unroll
        for (int ks = 0; ks < 4; ks++) {
            int kA = ks * 32;
            u32 ah[2][4], al[2][4];
            ldm_x4(ah[0], dynBase + aOff[0] + kA);
            ldm_x4(ah[1], dynBase + aOff[1] + kA);
            ldm_x4(al[0], dynBase + 9216 + aOff[0] + kA);
            ldm_x4(al[1], dynBase + 9216 + aOff[1] + kA);
            #pragma unroll
            for (int j = 0; j < 4; j++) {
                u32 bh0, bh1;
                ldm_x2(bh0, bh1, bBase + j * (8 * SB * 2) + ks * 32);
                #pragma unroll
                for (int i = 0; i < 2; i++) {
                    mma16816(acc1[i][j], ah[i], bh0, bh1);
                    mma16816(acc1[i][j], al[i], bh0, bh1);
                }
            }
        }
        cp_wait0();
        __syncthreads();   // B dead, staged P visible

        // add staged P_src + P_dst (LDS, conflict-free) + silu + H store
        #pragma unroll
        for (int i = 0; i < 2; i++)
            #pragma unroll
            for (int j = 0; j < 4; j++) {
                int c2 = ngrp * 32 + j * 8 + 2 * t;
                int bc = nc * 128 + c2;
                int r0 = m0 + i * 16 + g, r1 = r0 + 8;
                float2 p0 = h2f(*(const u32*)(sP + r0 * SP + c2));
                float2 q0 = h2f(*(const u32*)(sP + (64 + r0) * SP + c2));
                float2 p1 = h2f(*(const u32*)(sP + r1 * SP + c2));
                float2 q1 = h2f(*(const u32*)(sP + (64 + r1) * SP + c2));
                float v0 = silu_f(acc1[i][j][0] + p0.x + q0.x + s_b1[bc]);
                float v1 = silu_f(acc1[i][j][1] + p0.y + q0.y + s_b1[bc + 1]);
                float v2 = silu_f(acc1[i][j][2] + p1.x + q1.x + s_b1[bc]);
                float v3 = silu_f(acc1[i][j][3] + p1.y + q1.y + s_b1[bc + 1]);
                u16 h0 = hf(v0), h1 = hf(v1), h2 = hf(v2), h3 = hf(v3);
                *(u32*)(sHh + r0 * SH + c2) = (u32)h0 | ((u32)h1 << 16);
                *(u32*)(sHh + r1 * SH + c2) = (u32)h2 | ((u32)h3 << 16);
                u16 q0b = hf(v0 - hf_f(h0)), q1b = hf(v1 - hf_f(h1));
                u16 q2b = hf(v2 - hf_f(h2)), q3b = hf(v3 - hf_f(h3));
                *(u32*)(sHl + r0 * SH + c2) = (u32)q0b | ((u32)q1b << 16);
                *(u32*)(sHl + r1 * SH + c2) = (u32)q2b | ((u32)q3b << 16);
            }
        __syncthreads();

        // GEMM2: acc2 += (Hh + Hl) @ W2
        #pragma unroll
        for (int ks = 0; ks < 8; ks++) {
            int k0 = (ks * 16) * 2;
            u32 ah[2][4], al[2][4];
            ldm_x4(ah[0], hH + k0); ldm_x4(ah[1], hH + 16 * SH * 2 + k0);
            ldm_x4(al[0], hL + k0); ldm_x4(al[1], hL + 16 * SH * 2 + k0);
            #pragma unroll
            for (int j = 0; j < 2; j++) {
                u32 bh0, bh1;
                ldm_x2(bh0, bh1, wBase + j * (8 * SH * 2) + k0);
                #pragma unroll
                for (int i = 0; i < 2; i++) {
                    mma16816(acc2[i][j], ah[i], bh0, bh1);
                    mma16816(acc2[i][j], al[i], bh0, bh1);
                }
            }
        }
        __syncthreads();
    }

    // epilogue
    #pragma unroll
    for (int i = 0; i < 2; i++)
        #pragma unroll
        for (int j = 0; j < 2; j++) {
            int col = ngrp * 16 + j * 8 + 2 * t;
            int r0 = m0 + i * 16 + g, r1 = r0 + 8;
            sm_p[r0 * 68 + col]     = acc2[i][j][0] + s_b2[col];
            sm_p[r0 * 68 + col + 1] = acc2[i][j][1] + s_b2[col + 1];
            sm_p[r1 * 68 + col]     = acc2[i][j][2] + s_b2[col];
            sm_p[r1 * 68 + col + 1] = acc2[i][j][3] + s_b2[col + 1];
        }
    __syncthreads();
    {
        int r = tid >> 2, sub = tid & 3;
        float s = 0.f, s2 = 0.f;
        #pragma unroll
        for (int cc = 0; cc < 16; cc++) {
            float v = sm_p[r * 68 + sub * 16 + cc];
            s += v; s2 += v * v;
        }
        s  += __shfl_xor_sync(0xffffffffu, s, 1);
        s  += __shfl_xor_sync(0xffffffffu, s, 2);
        s2 += __shfl_xor_sync(0xffffffffu, s2, 1);
        s2 += __shfl_xor_sync(0xffffffffu, s2, 2);
        if (sub == 0) {
            float mu = s * (1.0f / 64.0f);
            s_mu[r] = mu;
            s_rs[r] = rsqrtf(s2 * (1.0f / 64.0f) - mu * mu + 1e-5f);
        }
    }
    __syncthreads();
    {
        int c = tid & 63, grp = tid >> 6;
        float gv = s_g[c], bv = s_bb[c];
        float* eo = g_e + (size_t)b * NEDGE * ED;
        float* ag = g_agg + (size_t)b * NNODE * ED;
        #pragma unroll 4
        for (int rr = 0; rr < 16; rr++) {
            int r = grp * 16 + rr;
            float p = sm_p[r * 68 + c];
            float en = eo[(size_t)(e0 + r) * ED + c]
                     + (p - s_mu[r]) * s_rs[r] * gv + bv;
            eo[(size_t)(e0 + r) * ED + c] = en;
            atomicAdd(ag + (size_t)s_dst[r] * ED + c, en);
        }
    }
}

// ===================== NODE KERNEL (validated R14) ===================
#define NOFF_B (2 * ABUF)
#define NODE_DSMEM (NOFF_B + 2 * BUFSZ)

__global__ void __launch_bounds__(256, 2)
node_kernel_mma(float* __restrict__ x,
                const float* __restrict__ bn1, const float* __restrict__ bn2,
                const float* __restrict__ gnW, const float* __restrict__ blnW, int l)
{
    extern __shared__ char dyn[];
    u16* sHh = (u16*)(dyn);
    u16* sHl = sHh + 64 * SH;
    u16* sW2 = (u16*)(dyn + NOFF_B);
    float* sm_p = (float*)(dyn);

    __shared__ float s_b1[512], s_b2[256], s_g[256], s_bb[256];
    __shared__ float s_mu[64], s_rs[64];

    const int tid = threadIdx.x;
    const int lane = tid & 31;
    const int w = tid >> 5;
    const int g = lane >> 2;
    const int t = lane & 3;
    const int mgrp = w & 1;
    const int ngrp = w >> 1;
    const int m0 = mgrp * 32;
    const int b = blockIdx.y;
    const int n0 = blockIdx.x * 64;

    for (int i = tid; i < 512; i += 256) s_b1[i] = bn1[l * HD + i];
    if (tid < 256) {
        s_b2[tid] = bn2[l * ND + tid];
        s_g[tid]  = gnW[l * ND + tid];
        s_bb[tid] = blnW[l * ND + tid];
    }
    __syncthreads();

    const float* xb = x + (size_t)b * NNODE * ND;
    const float* ab = g_agg + (size_t)b * NNODE * ED;

    const u16* W1 = gWn1T + (size_t)l * HD * K1N;
    const u16* W2 = gWn2T + (size_t)l * ND * HD;

    u32 aOff[2];
    #pragma unroll
    for (int i = 0; i < 2; i++)
        aOff[i] = (u32)((m0 + i * 16 + (lane & 15)) * SAS * 2 + (lane >> 4) * 16);
    const u32 dynBase = smem_u32(dyn);
    const u32 bBase = dynBase + NOFF_B
                    + (ngrp * 32 + (lane & 7)) * SB * 2 + ((lane >> 3) & 1) * 16;
    const u32 hH = dynBase + (m0 + (lane & 15)) * SH * 2 + (lane >> 4) * 16;
    const u32 hL = hH + 17408;
    const u32 wBase = dynBase + NOFF_B
                    + (ngrp * 64 + (lane & 7)) * SB * 2 + ((lane >> 3) & 1) * 16;

    const int nlin = tid >> 3, qlin = tid & 7;

    float acc2[2][8][4];
    #pragma unroll
    for (int i = 0; i < 2; i++)
        #pragma unroll
        for (int j = 0; j < 8; j++)
            #pragma unroll
            for (int q = 0; q < 4; q++) acc2[i][j][q] = 0.0f;

    for (int nc = 0; nc < 4; nc++) {
        float acc1[2][4][4];
        #pragma unroll
        for (int i = 0; i < 2; i++)
            #pragma unroll
            for (int j = 0; j < 4; j++)
                #pragma unroll
                for (int q = 0; q < 4; q++) acc1[i][j][q] = 0.0f;

        #pragma unroll
        for (int j = 0; j < 4; j++) {
            int n = j * 32 + nlin;
            cp16(dynBase + NOFF_B + (n * SB + qlin * 8) * 2,
                 W1 + (size_t)(nc * 128 + n) * K1N + qlin * 8);
        }
        cp_commit();
        #pragma unroll
        for (int j = 0; j < 4; j++) {
            int lin = j * 256 + tid;
            int r = lin >> 4, kl = (lin & 15) * 4;
            int node = min(n0 + r, NNODE - 1);
            float4 v = (kl < 256) ? *(const float4*)(xb + (size_t)node * ND + kl)
                                  : *(const float4*)(ab + (size_t)node * ED + (kl - 256));
            u16 h0 = hf(v.x), h1 = hf(v.y), h2 = hf(v.z), h3 = hf(v.w);
            u16 l0 = hf(v.x - hf_f(h0)), l1 = hf(v.y - hf_f(h1));
            u16 l2 = hf(v.z - hf_f(h2)), l3 = hf(v.w - hf_f(h3));
            size_t o = (size_t)r * SAS + kl;
            *(ull*)((u16*)dyn + o)        = (ull)h0 | ((ull)h1 << 16) | ((ull)h2 << 32) | ((ull)h3 << 48);
            *(ull*)((u16*)dyn + 4608 + o) = (ull)l0 | ((ull)l1 << 16) | ((ull)l2 << 32) | ((ull)l3 << 48);
        }
        cp_wait0();
        __syncthreads();

        for (int kc = 0; kc < 5; kc++) {
            int cur = kc & 1;
            if (kc < 4) {
                u32 dst = dynBase + NOFF_B + (cur ^ 1) * BUFSZ;
                #pragma unroll
                for (int j = 0; j < 4; j++) {
                    int n = j * 32 + nlin;
                    cp16(dst + (n * SB + qlin * 8) * 2,
                         W1 + (size_t)(nc * 128 + n) * K1N + (kc + 1) * 64 + qlin * 8);
                }
                cp_commit();
            }
            const u32 curB = bBase + cur * BUFSZ;
            const u32 aBaseH = dynBase + cur * ABUF;
            const u32 aBaseL = aBaseH + 9216;
            #pragma unroll
            for (int ks = 0; ks < 4; ks++) {
                int kA = ks * 32;
                u32 ah[2][4], al[2][4];
                ldm_x4(ah[0], aBaseH + aOff[0] + kA); ldm_x4(ah[1], aBaseH + aOff[1] + kA);
                ldm_x4(al[0], aBaseL + aOff[0] + kA); ldm_x4(al[1], aBaseL + aOff[1] + kA);
                int kB = ks * 32;
                #pragma unroll
                for (int j = 0; j < 4; j++) {
                    u32 bh0, bh1;
                    ldm_x2(bh0, bh1, curB + j * (8 * SB * 2) + kB);
                    #pragma unroll
                    for (int i = 0; i < 2; i++) {
                        mma16816(acc1[i][j], ah[i], bh0, bh1);
                        mma16816(acc1[i][j], al[i], bh0, bh1);
                    }
                }
            }
            if (kc < 4) {
                u16* aDstH = (u16*)(dyn + (cur ^ 1) * ABUF);
                #pragma unroll
                for (int j = 0; j < 4; j++) {
                    int lin = j * 256 + tid;
                    int r = lin >> 4, kl = (lin & 15) * 4;
                    int k = (kc + 1) * 64 + kl;
                    int node = min(n0 + r, NNODE - 1);
                    float4 v = (k < 256) ? *(const float4*)(xb + (size_t)node * ND + k)
                                         : *(const float4*)(ab + (size_t)node * ED + (k - 256));
                    u16 h0 = hf(v.x), h1 = hf(v.y), h2 = hf(v.z), h3 = hf(v.w);
                    u16 l0 = hf(v.x - hf_f(h0)), l1 = hf(v.y - hf_f(h1));
                    u16 l2 = hf(v.z - hf_f(h2)), l3 = hf(v.w - hf_f(h3));
                    size_t o = (size_t)r * SAS + kl;
                    *(ull*)(aDstH + o)        = (ull)h0 | ((ull)h1 << 16) | ((ull)h2 << 32) | ((ull)h3 << 48);
                    *(ull*)(aDstH + 4608 + o) = (ull)l0 | ((ull)l1 << 16) | ((ull)l2 << 32) | ((ull)l3 << 48);
                }
                cp_wait0();
            }
            __syncthreads();
        }

        #pragma unroll
        for (int i = 0; i < 2; i++)
            #pragma unroll
            for (int j = 0; j < 4; j++) {
                int col = ngrp * 32 + j * 8 + 2 * t;
                int bc = nc * 128 + col;
                int r0 = m0 + i * 16 + g, r1 = r0 + 8;
                float v0 = silu_f(acc1[i][j][0] + s_b1[bc]);
                float v1 = silu_f(acc1[i][j][1] + s_b1[bc + 1]);
                float v2 = silu_f(acc1[i][j][2] + s_b1[bc]);
                float v3 = silu_f(acc1[i][j][3] + s_b1[bc + 1]);
                u16 h0 = hf(v0), h1 = hf(v1), h2 = hf(v2), h3 = hf(v3);
                *(u32*)(sHh + r0 * SH + col) = (u32)h0 | ((u32)h1 << 16);
                *(u32*)(sHh + r1 * SH + col) = (u32)h2 | ((u32)h3 << 16);
                u16 q0 = hf(v0 - hf_f(h0)), q1 = hf(v1 - hf_f(h1));
                u16 q2 = hf(v2 - hf_f(h2)), q3 = hf(v3 - hf_f(h3));
                *(u32*)(sHl + r0 * SH + col) = (u32)q0 | ((u32)q1 << 16);
                *(u32*)(sHl + r1 * SH + col) = (u32)q2 | ((u32)q3 << 16);
            }
        __syncthreads();

        for (int s = 0; s < 2; s++) {
            for (int i = tid; i < 2048; i += 256) {
                int n = i >> 3, q = i & 7;
                *(uint4*)(sW2 + n * SB + q * 8) =
                    *(const uint4*)(W2 + (size_t)n * HD + nc * 128 + s * 64 + q * 8);
            }
            __syncthreads();
            #pragma unroll
            for (int ks = 0; ks < 4; ks++) {
                int kH = (s * 64 + ks * 16) * 2;
                int kW = (ks * 16) * 2;
                u32 ah[2][4], al[2][4];
                ldm_x4(ah[0], hH + kH); ldm_x4(ah[1], hH + 16 * SH * 2 + kH);
                ldm_x4(al[0], hL + kH); ldm_x4(al[1], hL + 16 * SH * 2 + kH);
                #pragma unroll
                for (int j = 0; j < 8; j++) {
                    u32 bh0, bh1;
                    ldm_x2(bh0, bh1, wBase + j * (8 * SB * 2) + kW);
                    #pragma unroll
                    for (int i = 0; i < 2; i++) {
                        mma16816(acc2[i][j], ah[i], bh0, bh1);
                        mma16816(acc2[i][j], al[i], bh0, bh1);
                    }
                }
            }
            __syncthreads();
        }
    }

    #pragma unroll
    for (int i = 0; i < 2; i++)
        #pragma unroll
        for (int j = 0; j < 8; j++) {
            int col = ngrp * 64 + j * 8 + 2 * t;
            int r0 = m0 + i * 16 + g, r1 = r0 + 8;
            sm_p[r0 * 260 + col]     = acc2[i][j][0] + s_b2[col];
            sm_p[r0 * 260 + col + 1] = acc2[i][j][1] + s_b2[col + 1];
            sm_p[r1 * 260 + col]     = acc2[i][j][2] + s_b2[col];
            sm_p[r1 * 260 + col + 1] = acc2[i][j][3] + s_b2[col + 1];
        }
    __syncthreads();
    {
        int r = tid >> 2, sub = tid & 3;
        float s = 0.f, s2 = 0.f;
        #pragma unroll 8
        for (int cc = 0; cc < 64; cc++) {
            float v = sm_p[r * 260 + sub * 64 + cc];
            s += v; s2 += v * v;
        }
        s  += __shfl_xor_sync(0xffffffffu, s, 1);
        s  += __shfl_xor_sync(0xffffffffu, s, 2);
        s2 += __shfl_xor_sync(0xffffffffu, s2, 1);
        s2 += __shfl_xor_sync(0xffffffffu, s2, 2);
        if (sub == 0) {
            float mu = s * (1.0f / 256.0f);
            s_mu[r] = mu;
            s_rs[r] = rsqrtf(s2 * (1.0f / 256.0f) - mu * mu + 1e-5f);
        }
    }
    __syncthreads();
    {
        int c = tid;
        float gv = s_g[c], bv = s_bb[c];
        float* xo = x + (size_t)b * NNODE * ND;
        for (int rr = 0; rr < 64; rr++) {
            if (n0 + rr < NNODE) {
                float v = sm_p[rr * 260 + c];
                size_t o = (size_t)(n0 + rr) * ND + c;
                xo[o] = xo[o] + (v - s_mu[rr]) * s_rs[rr] * gv + bv;
            }
        }
    }
}

// ============================== LAUNCH ===============================
extern "C" void kernel_launch(void* const* d_in, const int* in_sizes, int n_in,
                              void* d_out, int out_size) {
    const float* nf  = (const float*)d_in[0];
    const float* ef  = (const float*)d_in[1];
    const float* We1 = (const float*)d_in[2];
    const float* be1 = (const float*)d_in[3];
    const float* We2 = (const float*)d_in[4];
    const float* be2 = (const float*)d_in[5];
    const float* geW = (const float*)d_in[6];
    const float* ble = (const float*)d_in[7];
    const float* Wn1 = (const float*)d_in[8];
    const float* bn1 = (const float*)d_in[9];
    const float* Wn2 = (const float*)d_in[10];
    const float* bn2 = (const float*)d_in[11];
    const float* gnW = (const float*)d_in[12];
    const float* bln = (const float*)d_in[13];
    const int*  eidx = (const int*)d_in[14];
    float* x = (float*)d_out;

    cudaFuncSetAttribute(precompute_p, cudaFuncAttributeMaxDynamicSharedMemorySize, PRE_DSMEM);
    cudaFuncSetAttribute(edge_kernel_mma, cudaFuncAttributeMaxDynamicSharedMemorySize, EDGE_DSMEM);
    cudaFuncSetAttribute(node_kernel_mma, cudaFuncAttributeMaxDynamicSharedMemorySize, NODE_DSMEM);

    prep_all<<<2048, 256>>>(We1, We2, Wn1, Wn2);

    cudaMemcpyAsync(x, nf, sizeof(float) * (size_t)NB * NNODE * ND,
                    cudaMemcpyDeviceToDevice, 0);
    size_t ebytes = sizeof(float) * (size_t)NEDGE * ED;
    cudaMemcpyToSymbolAsync(g_e, ef, ebytes, 0, cudaMemcpyDeviceToDevice, 0);
    cudaMemcpyToSymbolAsync(g_e, ef, ebytes, ebytes, cudaMemcpyDeviceToDevice, 0);

    dim3 pg((NNODE + 63) / 64, NB);
    dim3 eg(NEDGE / 64, NB);
    dim3 ng((NNODE + 63) / 64, NB);
    for (int l = 0; l < NL; l++) {
        precompute_p<<<pg, 256, PRE_DSMEM>>>(x, l);
        edge_kernel_mma<<<eg, 256, EDGE_DSMEM>>>(eidx, be1, be2, geW, ble, l);
        node_kernel_mma<<<ng, 256, NODE_DSMEM>>>(x, bn1, bn2, gnW, bln, l);
    }
}